// round 1
// baseline (speedup 1.0000x reference)
#include <cuda_runtime.h>
#include <math.h>

#define S_LEN 16384
#define HID 1280
#define NH 16
#define HD 80
#define NC 16
#define CH 1024
#define QKV_STRIDE (3 * HID)   // 3840

// Scratch (no cudaMalloc allowed)
__device__ float g_qkv[(size_t)S_LEN * 3 * HID];   // [S, 3, NH, HD]
__device__ float g_attn[(size_t)S_LEN * HID];      // [S, NH*HD]

// ---------------------------------------------------------------------------
// C[M,N] = A[M,K] @ B[N,K]^T + bias[N]   (classic 128x128x8 SGEMM, 8x8 microtile)
// Requires M%128==0, N%128==0, K%8==0 (true for all our shapes).
// ---------------------------------------------------------------------------
__global__ __launch_bounds__(256, 2)
void sgemm_abt(const float* __restrict__ A, const float* __restrict__ B,
               const float* __restrict__ bias, float* __restrict__ C,
               int M, int N, int K)
{
    __shared__ float As[8][128];
    __shared__ float Bs[8][128];

    const int tid  = threadIdx.x;
    const int bm   = blockIdx.y * 128;
    const int bn   = blockIdx.x * 128;
    const int lrow = tid >> 1;          // 0..127
    const int lcol = (tid & 1) * 4;     // 0 or 4
    const int tx   = tid & 15;
    const int ty   = tid >> 4;

    const float* Ap = A + (size_t)(bm + lrow) * K + lcol;
    const float* Bp = B + (size_t)(bn + lrow) * K + lcol;

    float acc[8][8];
#pragma unroll
    for (int i = 0; i < 8; i++)
#pragma unroll
        for (int j = 0; j < 8; j++) acc[i][j] = 0.f;

    for (int k0 = 0; k0 < K; k0 += 8) {
        float4 av = *(const float4*)(Ap + k0);
        float4 bv = *(const float4*)(Bp + k0);
        __syncthreads();   // protect previous iteration's reads
        As[lcol + 0][lrow] = av.x;
        As[lcol + 1][lrow] = av.y;
        As[lcol + 2][lrow] = av.z;
        As[lcol + 3][lrow] = av.w;
        Bs[lcol + 0][lrow] = bv.x;
        Bs[lcol + 1][lrow] = bv.y;
        Bs[lcol + 2][lrow] = bv.z;
        Bs[lcol + 3][lrow] = bv.w;
        __syncthreads();
#pragma unroll
        for (int kk = 0; kk < 8; kk++) {
            float a[8], b[8];
#pragma unroll
            for (int i = 0; i < 8; i++) a[i] = As[kk][ty * 8 + i];
#pragma unroll
            for (int j = 0; j < 8; j++) b[j] = Bs[kk][tx * 8 + j];
#pragma unroll
            for (int i = 0; i < 8; i++)
#pragma unroll
                for (int j = 0; j < 8; j++) acc[i][j] += a[i] * b[j];
        }
    }

#pragma unroll
    for (int i = 0; i < 8; i++) {
        const int row = bm + ty * 8 + i;
#pragma unroll
        for (int j = 0; j < 8; j++) {
            const int col = bn + tx * 8 + j;
            C[(size_t)row * N + col] = acc[i][j] + bias[col];
        }
    }
}

// ---------------------------------------------------------------------------
// RoPE in-place on q and k halves of g_qkv.
// out[d]    = x[d]   * cos[d]    - x[d+40] * sin[d]       (d < 40)
// out[d+40] = x[d+40]* cos[d+40] + x[d]    * sin[d+40]
// ---------------------------------------------------------------------------
__global__ void rope_kernel(const float* __restrict__ cosb,
                            const float* __restrict__ sinb)
{
    int idx = blockIdx.x * blockDim.x + threadIdx.x;
    if (idx >= S_LEN * NH * (HD / 2)) return;
    const int d = idx % 40;
    const int h = (idx / 40) % NH;
    const int t = idx / (40 * NH);

    const float c0 = cosb[t * HD + d];
    const float c1 = cosb[t * HD + d + 40];
    const float s0 = sinb[t * HD + d];
    const float s1 = sinb[t * HD + d + 40];

    float* q = g_qkv + (size_t)t * QKV_STRIDE + h * HD;
    float* k = q + HID;

    const float q0 = q[d], q1 = q[d + 40];
    q[d]      = q0 * c0 - q1 * s0;
    q[d + 40] = q1 * c1 + q0 * s1;
    const float k0 = k[d], k1 = k[d + 40];
    k[d]      = k0 * c0 - k1 * s0;
    k[d + 40] = k1 * c1 + k0 * s1;
}

// ---------------------------------------------------------------------------
// Flash attention per (chunk, head): BM=64 q rows per block, BN=64 key tiles,
// full 1024-key loop with online softmax. fp32 throughout.
// grid = (CH/BM, NC*NH), block = 256 (16x16), dynamic smem = 79616 B.
// ---------------------------------------------------------------------------
#define BM 64
#define BN 64
#define QS_STRIDE 81   // pad 80 -> 81 to avoid same-bank column strides
#define SS_STRIDE 65

#define SMEM_Q  0
#define SMEM_K  (BM * QS_STRIDE)            // 5184
#define SMEM_V  (2 * BM * QS_STRIDE)        // 10368
#define SMEM_S  (3 * BM * QS_STRIDE)        // 15552
#define SMEM_M  (SMEM_S + BM * SS_STRIDE)   // 19712
#define SMEM_L  (SMEM_M + BM)
#define SMEM_AL (SMEM_L + BM)
#define SMEM_FLOATS (SMEM_AL + BM)          // 19904
#define ATTN_SMEM_BYTES (SMEM_FLOATS * 4)   // 79616

__global__ __launch_bounds__(256)
void attn_kernel()
{
    extern __shared__ float sm[];
    float* Qs = sm + SMEM_Q;
    float* Ks = sm + SMEM_K;
    float* Vs = sm + SMEM_V;
    float* Ss = sm + SMEM_S;
    float* rm = sm + SMEM_M;
    float* rl = sm + SMEM_L;
    float* ra = sm + SMEM_AL;

    const int tid = threadIdx.x;
    const int tx = tid & 15, ty = tid >> 4;
    const int nc = blockIdx.y / NH;
    const int h  = blockIdx.y % NH;
    const int t0 = nc * CH + blockIdx.x * BM;
    const float scale = 0.11180339887498949f;   // 1/sqrt(80)

    // Load Q tile [64, 80]
    for (int i = tid; i < BM * HD; i += 256) {
        const int r = i / HD, d = i % HD;
        Qs[r * QS_STRIDE + d] =
            g_qkv[(size_t)(t0 + r) * QKV_STRIDE + h * HD + d];
    }
    if (tid < BM) { rm[tid] = -1e30f; rl[tid] = 0.f; }

    float o[4][5];
#pragma unroll
    for (int i = 0; i < 4; i++)
#pragma unroll
        for (int c = 0; c < 5; c++) o[i][c] = 0.f;

    for (int kt = 0; kt < CH; kt += BN) {
        __syncthreads();   // protect prior-iter Ss/Vs reads, Q-store visibility
        for (int i = tid; i < BN * HD; i += 256) {
            const int r = i / HD, d = i % HD;
            const size_t base =
                (size_t)(nc * CH + kt + r) * QKV_STRIDE + h * HD + d;
            Ks[r * QS_STRIDE + d] = g_qkv[base + HID];
            Vs[r * QS_STRIDE + d] = g_qkv[base + 2 * HID];
        }
        __syncthreads();

        // scores: s[4][4] = Q(4 rows) . K(4 rows)
        float s[4][4];
#pragma unroll
        for (int i = 0; i < 4; i++)
#pragma unroll
            for (int j = 0; j < 4; j++) s[i][j] = 0.f;
#pragma unroll 10
        for (int d = 0; d < HD; d++) {
            float a[4], b[4];
#pragma unroll
            for (int i = 0; i < 4; i++) a[i] = Qs[(ty * 4 + i) * QS_STRIDE + d];
#pragma unroll
            for (int j = 0; j < 4; j++) b[j] = Ks[(tx * 4 + j) * QS_STRIDE + d];
#pragma unroll
            for (int i = 0; i < 4; i++)
#pragma unroll
                for (int j = 0; j < 4; j++) s[i][j] += a[i] * b[j];
        }
#pragma unroll
        for (int i = 0; i < 4; i++)
#pragma unroll
            for (int j = 0; j < 4; j++)
                Ss[(ty * 4 + i) * SS_STRIDE + tx * 4 + j] = s[i][j] * scale;
        __syncthreads();

        // per-row online softmax update
        if (tid < BM) {
            float* row = Ss + tid * SS_STRIDE;
            const float mold = rm[tid];
            float mt = mold;
#pragma unroll 8
            for (int j = 0; j < BN; j++) mt = fmaxf(mt, row[j]);
            const float alpha = __expf(mold - mt);
            float sum = 0.f;
#pragma unroll 8
            for (int j = 0; j < BN; j++) {
                const float p = __expf(row[j] - mt);
                row[j] = p;
                sum += p;
            }
            rm[tid] = mt;
            rl[tid] = rl[tid] * alpha + sum;
            ra[tid] = alpha;
        }
        __syncthreads();

        // rescale accumulators + O += P @ V
        float al[4];
#pragma unroll
        for (int i = 0; i < 4; i++) al[i] = ra[ty * 4 + i];
#pragma unroll
        for (int i = 0; i < 4; i++)
#pragma unroll
            for (int c = 0; c < 5; c++) o[i][c] *= al[i];
#pragma unroll 8
        for (int j = 0; j < BN; j++) {
            float p[4], v[5];
#pragma unroll
            for (int i = 0; i < 4; i++) p[i] = Ss[(ty * 4 + i) * SS_STRIDE + j];
#pragma unroll
            for (int c = 0; c < 5; c++) v[c] = Vs[j * QS_STRIDE + c * 16 + tx];
#pragma unroll
            for (int i = 0; i < 4; i++)
#pragma unroll
                for (int c = 0; c < 5; c++) o[i][c] += p[i] * v[c];
        }
    }

    float inv[4];
#pragma unroll
    for (int i = 0; i < 4; i++) inv[i] = 1.f / rl[ty * 4 + i];
#pragma unroll
    for (int i = 0; i < 4; i++)
#pragma unroll
        for (int c = 0; c < 5; c++)
            g_attn[(size_t)(t0 + ty * 4 + i) * HID + h * HD + c * 16 + tx] =
                o[i][c] * inv[i];
}

// ---------------------------------------------------------------------------
extern "C" void kernel_launch(void* const* d_in, const int* in_sizes, int n_in,
                              void* d_out, int out_size)
{
    const float* x      = (const float*)d_in[0];
    // d_in[1] = cu_seqlens (uniform chunks, encoded in constants)
    const float* cosb   = (const float*)d_in[2];
    const float* sinb   = (const float*)d_in[3];
    const float* w_qkv  = (const float*)d_in[4];
    const float* b_qkv  = (const float*)d_in[5];
    const float* w_proj = (const float*)d_in[6];
    const float* b_proj = (const float*)d_in[7];
    float* out = (float*)d_out;

    float *qkv_ptr, *attn_ptr;
    cudaGetSymbolAddress((void**)&qkv_ptr, g_qkv);
    cudaGetSymbolAddress((void**)&attn_ptr, g_attn);

    cudaFuncSetAttribute(attn_kernel,
                         cudaFuncAttributeMaxDynamicSharedMemorySize,
                         ATTN_SMEM_BYTES);

    // 1) qkv = x @ w_qkv^T + b_qkv
    sgemm_abt<<<dim3(3 * HID / 128, S_LEN / 128), 256>>>(
        x, w_qkv, b_qkv, qkv_ptr, S_LEN, 3 * HID, HID);

    // 2) RoPE on q, k (in place)
    rope_kernel<<<(S_LEN * NH * (HD / 2) + 255) / 256, 256>>>(cosb, sinb);

    // 3) chunked attention
    attn_kernel<<<dim3(CH / BM, NC * NH), 256, ATTN_SMEM_BYTES>>>();

    // 4) out = attn @ w_proj^T + b_proj
    sgemm_abt<<<dim3(HID / 128, S_LEN / 128), 256>>>(
        attn_ptr, w_proj, b_proj, out, S_LEN, HID, HID);
}

// round 3
// speedup vs baseline: 1.5847x; 1.5847x over previous
#include <cuda_runtime.h>
#include <cuda_bf16.h>
#include <cstdint>
#include <math.h>

#define S_LEN 16384
#define HID 1280
#define NH 16
#define HD 80
#define NC 16
#define CH 1024
#define QKV_STRIDE (3 * HID)   // 3840

// ---------------------------------------------------------------------------
// Scratch (no cudaMalloc allowed)
// ---------------------------------------------------------------------------
__device__ float g_qkv[(size_t)S_LEN * 3 * HID];   // [S, 3, NH, HD] fp32
__device__ float g_attn[(size_t)S_LEN * HID];      // [S, NH*HD]    fp32

__device__ __align__(256) __nv_bfloat16 g_xhi[(size_t)S_LEN * HID];
__device__ __align__(256) __nv_bfloat16 g_xlo[(size_t)S_LEN * HID];
__device__ __align__(256) __nv_bfloat16 g_wqhi[(size_t)3 * HID * HID];
__device__ __align__(256) __nv_bfloat16 g_wqlo[(size_t)3 * HID * HID];
__device__ __align__(256) __nv_bfloat16 g_wphi[(size_t)HID * HID];
__device__ __align__(256) __nv_bfloat16 g_wplo[(size_t)HID * HID];
__device__ __align__(256) __nv_bfloat16 g_ahi[(size_t)S_LEN * HID];
__device__ __align__(256) __nv_bfloat16 g_alo[(size_t)S_LEN * HID];

// ---------------------------------------------------------------------------
// helpers (sm_80-era instructions only — harness compiles for plain sm_103)
// ---------------------------------------------------------------------------
__device__ __forceinline__ uint32_t smem_u32(const void* p) {
    uint32_t a;
    asm("{ .reg .u64 t; cvta.to.shared.u64 t, %1; cvt.u32.u64 %0, t; }"
        : "=r"(a) : "l"(p));
    return a;
}

__device__ __forceinline__ void cpa16(uint32_t dst, const void* src) {
    asm volatile("cp.async.cg.shared.global [%0], [%1], 16;\n"
                 :: "r"(dst), "l"(src));
}
__device__ __forceinline__ void cpa_commit() {
    asm volatile("cp.async.commit_group;\n" ::: "memory");
}
template <int N>
__device__ __forceinline__ void cpa_wait() {
    asm volatile("cp.async.wait_group %0;\n" :: "n"(N) : "memory");
}

__device__ __forceinline__ void ldm_x4(uint32_t* r, uint32_t addr) {
    asm volatile("ldmatrix.sync.aligned.m8n8.x4.shared.b16 {%0,%1,%2,%3}, [%4];"
                 : "=r"(r[0]), "=r"(r[1]), "=r"(r[2]), "=r"(r[3])
                 : "r"(addr));
}

__device__ __forceinline__ void mma16816(float* d, const uint32_t* a,
                                         const uint32_t* b) {
    asm volatile(
        "mma.sync.aligned.m16n8k16.row.col.f32.bf16.bf16.f32 "
        "{%0,%1,%2,%3}, {%4,%5,%6,%7}, {%8,%9}, {%0,%1,%2,%3};"
        : "+f"(d[0]), "+f"(d[1]), "+f"(d[2]), "+f"(d[3])
        : "r"(a[0]), "r"(a[1]), "r"(a[2]), "r"(a[3]), "r"(b[0]), "r"(b[1]));
}

// ---------------------------------------------------------------------------
// fp32 -> (hi, lo) bf16 split conversion  (n must be a multiple of 4)
// ---------------------------------------------------------------------------
__global__ void cvt_hilo(const float* __restrict__ src,
                         __nv_bfloat16* __restrict__ hi,
                         __nv_bfloat16* __restrict__ lo, int n)
{
    int i = (blockIdx.x * blockDim.x + threadIdx.x) * 4;
    if (i >= n) return;
    float4 v = *(const float4*)(src + i);
    float f[4] = {v.x, v.y, v.z, v.w};
    __nv_bfloat16 h[4], l[4];
#pragma unroll
    for (int j = 0; j < 4; j++) {
        h[j] = __float2bfloat16(f[j]);
        l[j] = __float2bfloat16(f[j] - __bfloat162float(h[j]));
    }
    *(__nv_bfloat162*)(hi + i)     = __nv_bfloat162(h[0], h[1]);
    *(__nv_bfloat162*)(hi + i + 2) = __nv_bfloat162(h[2], h[3]);
    *(__nv_bfloat162*)(lo + i)     = __nv_bfloat162(l[0], l[1]);
    *(__nv_bfloat162*)(lo + i + 2) = __nv_bfloat162(l[2], l[3]);
}

// ---------------------------------------------------------------------------
// HMMA GEMM: C[M,N] = split(A)[M,K] @ split(B)[N,K]^T + bias[N]
// bf16 hi/lo 3-term split, fp32 accumulate.
// Block 128x128, K-chunk 32, 8 warps (4M x 2N), warp tile 32x64.
// smem rows padded to 40 bf16 (80B) -> conflict-free ldmatrix.
// ---------------------------------------------------------------------------
#define GBM 128
#define GBN 128
#define GBK 32
#define ROWB 80                       // bytes per smem row (40 bf16)
#define MAT_BYTES (128 * ROWB)        // 10240
#define SM_AHI 0
#define SM_ALO (1 * MAT_BYTES)
#define SM_BHI (2 * MAT_BYTES)
#define SM_BLO (3 * MAT_BYTES)
#define STG_BYTES (4 * MAT_BYTES)     // 40960
#define GEMM_SMEM (2 * STG_BYTES)     // 81920

__global__ __launch_bounds__(256, 1)
void gemm_mma(const __nv_bfloat16* __restrict__ Ahi,
              const __nv_bfloat16* __restrict__ Alo,
              const __nv_bfloat16* __restrict__ Bhi,
              const __nv_bfloat16* __restrict__ Blo,
              const float* __restrict__ bias, float* __restrict__ C,
              int M, int N, int K)
{
    extern __shared__ char dsm[];
    const uint32_t sbase = smem_u32(dsm);

    const int tid  = threadIdx.x;
    const int lane = tid & 31;
    const int wid  = tid >> 5;
    const int wm   = wid & 3;        // 0..3  (M)
    const int wn   = wid >> 2;       // 0..1  (N)
    const int bm   = blockIdx.y * GBM;
    const int bn   = blockIdx.x * GBN;
    const int NK   = K / GBK;

    float acc[2][8][4];
#pragma unroll
    for (int i = 0; i < 2; i++)
#pragma unroll
        for (int j = 0; j < 8; j++)
#pragma unroll
            for (int c = 0; c < 4; c++) acc[i][j][c] = 0.f;

    // per-stage loader: 512 16B chunks per matrix, 2 per thread
    auto load_stage = [&](int k0, int s) {
        const uint32_t sb = sbase + s * STG_BYTES;
#pragma unroll
        for (int i = 0; i < 2; i++) {
            const int c   = tid + i * 256;
            const int row = c >> 2, j = c & 3;
            const uint32_t off = (uint32_t)(row * ROWB + j * 16);
            const size_t ga = (size_t)(bm + row) * K + k0 + j * 8;
            const size_t gb = (size_t)(bn + row) * K + k0 + j * 8;
            cpa16(sb + SM_AHI + off, Ahi + ga);
            cpa16(sb + SM_ALO + off, Alo + ga);
            cpa16(sb + SM_BHI + off, Bhi + gb);
            cpa16(sb + SM_BLO + off, Blo + gb);
        }
        cpa_commit();
    };

    load_stage(0, 0);

    // precomputed ldmatrix lane addressing (within-tile offsets)
    const int a_row = (lane & 15);
    const int a_kof = (lane >> 4) << 3;
    const int b_nof = (lane & 7) + ((lane >> 4) << 3);
    const int b_kof = ((lane >> 3) & 1) << 3;

    for (int k = 0; k < NK; k++) {
        if (k > 0) __syncthreads();             // finish reads of buf (k+1)&1
        if (k + 1 < NK) {
            load_stage((k + 1) * GBK, (k + 1) & 1);
            cpa_wait<1>();
        } else {
            cpa_wait<0>();
        }
        __syncthreads();                        // stage k visible to all

        const uint32_t sb = sbase + (k & 1) * STG_BYTES;
#pragma unroll
        for (int kk = 0; kk < GBK; kk += 16) {
            uint32_t a_hi[2][4], a_lo[2][4];
#pragma unroll
            for (int mf = 0; mf < 2; mf++) {
                const uint32_t ad = sb + SM_AHI +
                    (wm * 32 + mf * 16 + a_row) * ROWB + (kk + a_kof) * 2;
                ldm_x4(a_hi[mf], ad);
                ldm_x4(a_lo[mf], ad + MAT_BYTES);
            }
            uint32_t b_hi[4][4], b_lo[4][4];
#pragma unroll
            for (int j = 0; j < 4; j++) {
                const uint32_t bd = sb + SM_BHI +
                    (wn * 64 + j * 16 + b_nof) * ROWB + (kk + b_kof) * 2;
                ldm_x4(b_hi[j], bd);
                ldm_x4(b_lo[j], bd + MAT_BYTES);
            }
#pragma unroll
            for (int mf = 0; mf < 2; mf++)
#pragma unroll
                for (int j = 0; j < 4; j++) {
                    mma16816(acc[mf][2 * j + 0], a_hi[mf], &b_hi[j][0]);
                    mma16816(acc[mf][2 * j + 1], a_hi[mf], &b_hi[j][2]);
                    mma16816(acc[mf][2 * j + 0], a_hi[mf], &b_lo[j][0]);
                    mma16816(acc[mf][2 * j + 1], a_hi[mf], &b_lo[j][2]);
                    mma16816(acc[mf][2 * j + 0], a_lo[mf], &b_hi[j][0]);
                    mma16816(acc[mf][2 * j + 1], a_lo[mf], &b_hi[j][2]);
                }
        }
    }

    // epilogue: acc -> gmem (+bias)
#pragma unroll
    for (int mf = 0; mf < 2; mf++) {
        const int r0 = bm + wm * 32 + mf * 16 + (lane >> 2);
#pragma unroll
        for (int nf = 0; nf < 8; nf++) {
            const int c0 = bn + wn * 64 + nf * 8 + (lane & 3) * 2;
            const float b0 = bias[c0], b1 = bias[c0 + 1];
            float2 v0 = {acc[mf][nf][0] + b0, acc[mf][nf][1] + b1};
            float2 v1 = {acc[mf][nf][2] + b0, acc[mf][nf][3] + b1};
            *(float2*)(C + (size_t)r0 * N + c0) = v0;
            *(float2*)(C + (size_t)(r0 + 8) * N + c0) = v1;
        }
    }
}

// ---------------------------------------------------------------------------
// RoPE in-place on q and k halves of g_qkv (fp32).
// ---------------------------------------------------------------------------
__global__ void rope_kernel(const float* __restrict__ cosb,
                            const float* __restrict__ sinb)
{
    int idx = blockIdx.x * blockDim.x + threadIdx.x;
    if (idx >= S_LEN * NH * (HD / 2)) return;
    const int d = idx % 40;
    const int h = (idx / 40) % NH;
    const int t = idx / (40 * NH);

    const float c0 = cosb[t * HD + d];
    const float c1 = cosb[t * HD + d + 40];
    const float s0 = sinb[t * HD + d];
    const float s1 = sinb[t * HD + d + 40];

    float* q = g_qkv + (size_t)t * QKV_STRIDE + h * HD;
    float* k = q + HID;

    const float q0 = q[d], q1 = q[d + 40];
    q[d]      = q0 * c0 - q1 * s0;
    q[d + 40] = q1 * c1 + q0 * s1;
    const float k0 = k[d], k1 = k[d + 40];
    k[d]      = k0 * c0 - k1 * s0;
    k[d + 40] = k1 * c1 + k0 * s1;
}

// ---------------------------------------------------------------------------
// Flash attention per (chunk, head): fp32 SIMT (unchanged)
// ---------------------------------------------------------------------------
#define BM 64
#define BN 64
#define QS_STRIDE 81
#define SS_STRIDE 65

#define SMEM_Q  0
#define SMEM_K  (BM * QS_STRIDE)
#define SMEM_V  (2 * BM * QS_STRIDE)
#define SMEM_S  (3 * BM * QS_STRIDE)
#define SMEM_M  (SMEM_S + BM * SS_STRIDE)
#define SMEM_L  (SMEM_M + BM)
#define SMEM_AL (SMEM_L + BM)
#define SMEM_FLOATS (SMEM_AL + BM)
#define ATTN_SMEM_BYTES (SMEM_FLOATS * 4)

__global__ __launch_bounds__(256)
void attn_kernel()
{
    extern __shared__ float sm[];
    float* Qs = sm + SMEM_Q;
    float* Ks = sm + SMEM_K;
    float* Vs = sm + SMEM_V;
    float* Ss = sm + SMEM_S;
    float* rm = sm + SMEM_M;
    float* rl = sm + SMEM_L;
    float* ra = sm + SMEM_AL;

    const int tid = threadIdx.x;
    const int tx = tid & 15, ty = tid >> 4;
    const int nc = blockIdx.y / NH;
    const int h  = blockIdx.y % NH;
    const int t0 = nc * CH + blockIdx.x * BM;
    const float scale = 0.11180339887498949f;

    for (int i = tid; i < BM * HD; i += 256) {
        const int r = i / HD, d = i % HD;
        Qs[r * QS_STRIDE + d] =
            g_qkv[(size_t)(t0 + r) * QKV_STRIDE + h * HD + d];
    }
    if (tid < BM) { rm[tid] = -1e30f; rl[tid] = 0.f; }

    float o[4][5];
#pragma unroll
    for (int i = 0; i < 4; i++)
#pragma unroll
        for (int c = 0; c < 5; c++) o[i][c] = 0.f;

    for (int kt = 0; kt < CH; kt += BN) {
        __syncthreads();
        for (int i = tid; i < BN * HD; i += 256) {
            const int r = i / HD, d = i % HD;
            const size_t base =
                (size_t)(nc * CH + kt + r) * QKV_STRIDE + h * HD + d;
            Ks[r * QS_STRIDE + d] = g_qkv[base + HID];
            Vs[r * QS_STRIDE + d] = g_qkv[base + 2 * HID];
        }
        __syncthreads();

        float s[4][4];
#pragma unroll
        for (int i = 0; i < 4; i++)
#pragma unroll
            for (int j = 0; j < 4; j++) s[i][j] = 0.f;
#pragma unroll 10
        for (int d = 0; d < HD; d++) {
            float a[4], b[4];
#pragma unroll
            for (int i = 0; i < 4; i++) a[i] = Qs[(ty * 4 + i) * QS_STRIDE + d];
#pragma unroll
            for (int j = 0; j < 4; j++) b[j] = Ks[(tx * 4 + j) * QS_STRIDE + d];
#pragma unroll
            for (int i = 0; i < 4; i++)
#pragma unroll
                for (int j = 0; j < 4; j++) s[i][j] += a[i] * b[j];
        }
#pragma unroll
        for (int i = 0; i < 4; i++)
#pragma unroll
            for (int j = 0; j < 4; j++)
                Ss[(ty * 4 + i) * SS_STRIDE + tx * 4 + j] = s[i][j] * scale;
        __syncthreads();

        if (tid < BM) {
            float* row = Ss + tid * SS_STRIDE;
            const float mold = rm[tid];
            float mt = mold;
#pragma unroll 8
            for (int j = 0; j < BN; j++) mt = fmaxf(mt, row[j]);
            const float alpha = __expf(mold - mt);
            float sum = 0.f;
#pragma unroll 8
            for (int j = 0; j < BN; j++) {
                const float p = __expf(row[j] - mt);
                row[j] = p;
                sum += p;
            }
            rm[tid] = mt;
            rl[tid] = rl[tid] * alpha + sum;
            ra[tid] = alpha;
        }
        __syncthreads();

        float al[4];
#pragma unroll
        for (int i = 0; i < 4; i++) al[i] = ra[ty * 4 + i];
#pragma unroll
        for (int i = 0; i < 4; i++)
#pragma unroll
            for (int c = 0; c < 5; c++) o[i][c] *= al[i];
#pragma unroll 8
        for (int j = 0; j < BN; j++) {
            float p[4], v[5];
#pragma unroll
            for (int i = 0; i < 4; i++) p[i] = Ss[(ty * 4 + i) * SS_STRIDE + j];
#pragma unroll
            for (int c = 0; c < 5; c++) v[c] = Vs[j * QS_STRIDE + c * 16 + tx];
#pragma unroll
            for (int i = 0; i < 4; i++)
#pragma unroll
                for (int c = 0; c < 5; c++) o[i][c] += p[i] * v[c];
        }
    }

    float inv[4];
#pragma unroll
    for (int i = 0; i < 4; i++) inv[i] = 1.f / rl[ty * 4 + i];
#pragma unroll
    for (int i = 0; i < 4; i++)
#pragma unroll
        for (int c = 0; c < 5; c++)
            g_attn[(size_t)(t0 + ty * 4 + i) * HID + h * HD + c * 16 + tx] =
                o[i][c] * inv[i];
}

// ---------------------------------------------------------------------------
extern "C" void kernel_launch(void* const* d_in, const int* in_sizes, int n_in,
                              void* d_out, int out_size)
{
    const float* x      = (const float*)d_in[0];
    const float* cosb   = (const float*)d_in[2];
    const float* sinb   = (const float*)d_in[3];
    const float* w_qkv  = (const float*)d_in[4];
    const float* b_qkv  = (const float*)d_in[5];
    const float* w_proj = (const float*)d_in[6];
    const float* b_proj = (const float*)d_in[7];
    float* out = (float*)d_out;

    float *qkv_p, *attn_p;
    __nv_bfloat16 *xhi, *xlo, *wqhi, *wqlo, *wphi, *wplo, *ahi, *alo;
    cudaGetSymbolAddress((void**)&qkv_p, g_qkv);
    cudaGetSymbolAddress((void**)&attn_p, g_attn);
    cudaGetSymbolAddress((void**)&xhi, g_xhi);
    cudaGetSymbolAddress((void**)&xlo, g_xlo);
    cudaGetSymbolAddress((void**)&wqhi, g_wqhi);
    cudaGetSymbolAddress((void**)&wqlo, g_wqlo);
    cudaGetSymbolAddress((void**)&wphi, g_wphi);
    cudaGetSymbolAddress((void**)&wplo, g_wplo);
    cudaGetSymbolAddress((void**)&ahi, g_ahi);
    cudaGetSymbolAddress((void**)&alo, g_alo);

    cudaFuncSetAttribute(attn_kernel,
                         cudaFuncAttributeMaxDynamicSharedMemorySize,
                         ATTN_SMEM_BYTES);
    cudaFuncSetAttribute(gemm_mma,
                         cudaFuncAttributeMaxDynamicSharedMemorySize,
                         GEMM_SMEM);

    const int n_x = S_LEN * HID;
    const int n_wq = 3 * HID * HID;
    const int n_wp = HID * HID;

    // 1) split conversions
    cvt_hilo<<<(n_x / 4 + 255) / 256, 256>>>(x, xhi, xlo, n_x);
    cvt_hilo<<<(n_wq / 4 + 255) / 256, 256>>>(w_qkv, wqhi, wqlo, n_wq);
    cvt_hilo<<<(n_wp / 4 + 255) / 256, 256>>>(w_proj, wphi, wplo, n_wp);

    // 2) qkv = x @ w_qkv^T + b_qkv   (HMMA split)
    gemm_mma<<<dim3(3 * HID / GBN, S_LEN / GBM), 256, GEMM_SMEM>>>(
        xhi, xlo, wqhi, wqlo, b_qkv, qkv_p, S_LEN, 3 * HID, HID);

    // 3) RoPE (fp32, in place)
    rope_kernel<<<(S_LEN * NH * (HD / 2) + 255) / 256, 256>>>(cosb, sinb);

    // 4) chunked attention (fp32 SIMT)
    attn_kernel<<<dim3(CH / BM, NC * NH), 256, ATTN_SMEM_BYTES>>>();

    // 5) split attn output, proj GEMM (HMMA split)
    cvt_hilo<<<(n_x / 4 + 255) / 256, 256>>>(attn_p, ahi, alo, n_x);
    gemm_mma<<<dim3(HID / GBN, S_LEN / GBM), 256, GEMM_SMEM>>>(
        ahi, alo, wphi, wplo, b_proj, out, S_LEN, HID, HID);
}

// round 4
// speedup vs baseline: 3.3281x; 2.1002x over previous
#include <cuda_runtime.h>
#include <cuda_bf16.h>
#include <cstdint>
#include <math.h>

#define S_LEN 16384
#define HID 1280
#define NH 16
#define HD 80
#define NC 16
#define CH 1024
#define QKV_STRIDE (3 * HID)   // 3840

// ---------------------------------------------------------------------------
// Scratch (no cudaMalloc allowed)
// ---------------------------------------------------------------------------
__device__ float g_qkv[(size_t)S_LEN * 3 * HID];   // [S, 3, NH, HD] fp32

__device__ __align__(256) __nv_bfloat16 g_xhi[(size_t)S_LEN * HID];
__device__ __align__(256) __nv_bfloat16 g_xlo[(size_t)S_LEN * HID];
__device__ __align__(256) __nv_bfloat16 g_wqhi[(size_t)3 * HID * HID];
__device__ __align__(256) __nv_bfloat16 g_wqlo[(size_t)3 * HID * HID];
__device__ __align__(256) __nv_bfloat16 g_wphi[(size_t)HID * HID];
__device__ __align__(256) __nv_bfloat16 g_wplo[(size_t)HID * HID];
// attention inputs, [S, NH, HD] bf16 hi/lo
__device__ __align__(256) __nv_bfloat16 g_qhi[(size_t)S_LEN * HID];
__device__ __align__(256) __nv_bfloat16 g_qlo[(size_t)S_LEN * HID];
__device__ __align__(256) __nv_bfloat16 g_khi[(size_t)S_LEN * HID];
__device__ __align__(256) __nv_bfloat16 g_klo[(size_t)S_LEN * HID];
__device__ __align__(256) __nv_bfloat16 g_vhi[(size_t)S_LEN * HID];
__device__ __align__(256) __nv_bfloat16 g_vlo[(size_t)S_LEN * HID];
// attention output (= proj GEMM input), hi/lo
__device__ __align__(256) __nv_bfloat16 g_ahi[(size_t)S_LEN * HID];
__device__ __align__(256) __nv_bfloat16 g_alo[(size_t)S_LEN * HID];

// ---------------------------------------------------------------------------
// helpers (sm_80-era instructions only — harness compiles for plain sm_103)
// ---------------------------------------------------------------------------
__device__ __forceinline__ uint32_t smem_u32(const void* p) {
    uint32_t a;
    asm("{ .reg .u64 t; cvta.to.shared.u64 t, %1; cvt.u32.u64 %0, t; }"
        : "=r"(a) : "l"(p));
    return a;
}

__device__ __forceinline__ void cpa16(uint32_t dst, const void* src) {
    asm volatile("cp.async.cg.shared.global [%0], [%1], 16;\n"
                 :: "r"(dst), "l"(src));
}
__device__ __forceinline__ void cpa_commit() {
    asm volatile("cp.async.commit_group;\n" ::: "memory");
}
template <int N>
__device__ __forceinline__ void cpa_wait() {
    asm volatile("cp.async.wait_group %0;\n" :: "n"(N) : "memory");
}

__device__ __forceinline__ void ldm_x4(uint32_t* r, uint32_t addr) {
    asm volatile("ldmatrix.sync.aligned.m8n8.x4.shared.b16 {%0,%1,%2,%3}, [%4];"
                 : "=r"(r[0]), "=r"(r[1]), "=r"(r[2]), "=r"(r[3])
                 : "r"(addr));
}
__device__ __forceinline__ void ldm_x4_t(uint32_t* r, uint32_t addr) {
    asm volatile(
        "ldmatrix.sync.aligned.m8n8.x4.trans.shared.b16 {%0,%1,%2,%3}, [%4];"
        : "=r"(r[0]), "=r"(r[1]), "=r"(r[2]), "=r"(r[3])
        : "r"(addr));
}

__device__ __forceinline__ void mma16816(float* d, const uint32_t* a,
                                         const uint32_t* b) {
    asm volatile(
        "mma.sync.aligned.m16n8k16.row.col.f32.bf16.bf16.f32 "
        "{%0,%1,%2,%3}, {%4,%5,%6,%7}, {%8,%9}, {%0,%1,%2,%3};"
        : "+f"(d[0]), "+f"(d[1]), "+f"(d[2]), "+f"(d[3])
        : "r"(a[0]), "r"(a[1]), "r"(a[2]), "r"(a[3]), "r"(b[0]), "r"(b[1]));
}

// pack two fp32 into bf16x2: low half = lo, high half = hi
__device__ __forceinline__ uint32_t pack_bf16(float lo, float hi) {
    uint32_t d;
    asm("cvt.rn.bf16x2.f32 %0, %1, %2;" : "=r"(d) : "f"(hi), "f"(lo));
    return d;
}

__device__ __forceinline__ void split_hilo(float f, __nv_bfloat16& h,
                                           __nv_bfloat16& l) {
    h = __float2bfloat16(f);
    l = __float2bfloat16(f - __bfloat162float(h));
}

// ---------------------------------------------------------------------------
// fp32 -> (hi, lo) bf16 split conversion  (n must be a multiple of 4)
// ---------------------------------------------------------------------------
__global__ void cvt_hilo(const float* __restrict__ src,
                         __nv_bfloat16* __restrict__ hi,
                         __nv_bfloat16* __restrict__ lo, int n)
{
    int i = (blockIdx.x * blockDim.x + threadIdx.x) * 4;
    if (i >= n) return;
    float4 v = *(const float4*)(src + i);
    float f[4] = {v.x, v.y, v.z, v.w};
    __nv_bfloat16 h[4], l[4];
#pragma unroll
    for (int j = 0; j < 4; j++) split_hilo(f[j], h[j], l[j]);
    *(__nv_bfloat162*)(hi + i)     = __nv_bfloat162(h[0], h[1]);
    *(__nv_bfloat162*)(hi + i + 2) = __nv_bfloat162(h[2], h[3]);
    *(__nv_bfloat162*)(lo + i)     = __nv_bfloat162(l[0], l[1]);
    *(__nv_bfloat162*)(lo + i + 2) = __nv_bfloat162(l[2], l[3]);
}

// ---------------------------------------------------------------------------
// HMMA GEMM: C[M,N] = split(A)[M,K] @ split(B)[N,K]^T + bias[N]
// Block 128x128, K-chunk 32, 8 warps (4M x 2N), warp tile 32x64.
// B-fragment loads inside j-loop -> fits 128 regs -> 2 CTAs/SM.
// ---------------------------------------------------------------------------
#define GBM 128
#define GBN 128
#define GBK 32
#define ROWB 80
#define MAT_BYTES (128 * ROWB)
#define SM_AHI 0
#define SM_ALO (1 * MAT_BYTES)
#define SM_BHI (2 * MAT_BYTES)
#define SM_BLO (3 * MAT_BYTES)
#define STG_BYTES (4 * MAT_BYTES)     // 40960
#define GEMM_SMEM (2 * STG_BYTES)     // 81920

__global__ __launch_bounds__(256, 2)
void gemm_mma(const __nv_bfloat16* __restrict__ Ahi,
              const __nv_bfloat16* __restrict__ Alo,
              const __nv_bfloat16* __restrict__ Bhi,
              const __nv_bfloat16* __restrict__ Blo,
              const float* __restrict__ bias, float* __restrict__ C,
              int M, int N, int K)
{
    extern __shared__ char dsm[];
    const uint32_t sbase = smem_u32(dsm);

    const int tid  = threadIdx.x;
    const int lane = tid & 31;
    const int wid  = tid >> 5;
    const int wm   = wid & 3;
    const int wn   = wid >> 2;
    const int bm   = blockIdx.y * GBM;
    const int bn   = blockIdx.x * GBN;
    const int NK   = K / GBK;

    float acc[2][8][4];
#pragma unroll
    for (int i = 0; i < 2; i++)
#pragma unroll
        for (int j = 0; j < 8; j++)
#pragma unroll
            for (int c = 0; c < 4; c++) acc[i][j][c] = 0.f;

    auto load_stage = [&](int k0, int s) {
        const uint32_t sb = sbase + s * STG_BYTES;
#pragma unroll
        for (int i = 0; i < 2; i++) {
            const int c   = tid + i * 256;
            const int row = c >> 2, j = c & 3;
            const uint32_t off = (uint32_t)(row * ROWB + j * 16);
            const size_t ga = (size_t)(bm + row) * K + k0 + j * 8;
            const size_t gb = (size_t)(bn + row) * K + k0 + j * 8;
            cpa16(sb + SM_AHI + off, Ahi + ga);
            cpa16(sb + SM_ALO + off, Alo + ga);
            cpa16(sb + SM_BHI + off, Bhi + gb);
            cpa16(sb + SM_BLO + off, Blo + gb);
        }
        cpa_commit();
    };

    load_stage(0, 0);

    const int a_row = (lane & 15);
    const int a_kof = (lane >> 4) << 3;
    const int b_nof = (lane & 7) + ((lane >> 4) << 3);
    const int b_kof = ((lane >> 3) & 1) << 3;

    for (int k = 0; k < NK; k++) {
        if (k > 0) __syncthreads();
        if (k + 1 < NK) {
            load_stage((k + 1) * GBK, (k + 1) & 1);
            cpa_wait<1>();
        } else {
            cpa_wait<0>();
        }
        __syncthreads();

        const uint32_t sb = sbase + (k & 1) * STG_BYTES;
#pragma unroll
        for (int kk = 0; kk < GBK; kk += 16) {
            uint32_t a_hi[2][4], a_lo[2][4];
#pragma unroll
            for (int mf = 0; mf < 2; mf++) {
                const uint32_t ad = sb + SM_AHI +
                    (wm * 32 + mf * 16 + a_row) * ROWB + (kk + a_kof) * 2;
                ldm_x4(a_hi[mf], ad);
                ldm_x4(a_lo[mf], ad + MAT_BYTES);
            }
#pragma unroll
            for (int j = 0; j < 4; j++) {
                uint32_t b_hi[4], b_lo[4];
                const uint32_t bd = sb + SM_BHI +
                    (wn * 64 + j * 16 + b_nof) * ROWB + (kk + b_kof) * 2;
                ldm_x4(b_hi, bd);
                ldm_x4(b_lo, bd + MAT_BYTES);
#pragma unroll
                for (int mf = 0; mf < 2; mf++) {
                    mma16816(acc[mf][2 * j + 0], a_hi[mf], &b_hi[0]);
                    mma16816(acc[mf][2 * j + 1], a_hi[mf], &b_hi[2]);
                    mma16816(acc[mf][2 * j + 0], a_hi[mf], &b_lo[0]);
                    mma16816(acc[mf][2 * j + 1], a_hi[mf], &b_lo[2]);
                    mma16816(acc[mf][2 * j + 0], a_lo[mf], &b_hi[0]);
                    mma16816(acc[mf][2 * j + 1], a_lo[mf], &b_hi[2]);
                }
            }
        }
    }

#pragma unroll
    for (int mf = 0; mf < 2; mf++) {
        const int r0 = bm + wm * 32 + mf * 16 + (lane >> 2);
#pragma unroll
        for (int nf = 0; nf < 8; nf++) {
            const int c0 = bn + wn * 64 + nf * 8 + (lane & 3) * 2;
            const float b0 = bias[c0], b1 = bias[c0 + 1];
            float2 v0 = {acc[mf][nf][0] + b0, acc[mf][nf][1] + b1};
            float2 v1 = {acc[mf][nf][2] + b0, acc[mf][nf][3] + b1};
            *(float2*)(C + (size_t)r0 * N + c0) = v0;
            *(float2*)(C + (size_t)(r0 + 8) * N + c0) = v1;
        }
    }
}

// ---------------------------------------------------------------------------
// RoPE + hi/lo bf16 conversion of q, k, v: g_qkv fp32 -> 6 bf16 arrays.
// One thread per (t, h, d<40): handles d and d+40 of q, k, v.
// ---------------------------------------------------------------------------
__global__ void rope_cvt(const float* __restrict__ cosb,
                         const float* __restrict__ sinb)
{
    int idx = blockIdx.x * blockDim.x + threadIdx.x;
    if (idx >= S_LEN * NH * 40) return;
    const int d = idx % 40;
    const int h = (idx / 40) % NH;
    const int t = idx / (40 * NH);

    const float c0 = cosb[t * HD + d];
    const float c1 = cosb[t * HD + d + 40];
    const float s0 = sinb[t * HD + d];
    const float s1 = sinb[t * HD + d + 40];

    const size_t base = (size_t)t * QKV_STRIDE + h * HD;
    const float q0 = g_qkv[base + d],            q1 = g_qkv[base + d + 40];
    const float k0 = g_qkv[base + HID + d],      k1 = g_qkv[base + HID + d + 40];
    const float v0 = g_qkv[base + 2 * HID + d],  v1 = g_qkv[base + 2 * HID + d + 40];

    const float qr0 = q0 * c0 - q1 * s0;
    const float qr1 = q1 * c1 + q0 * s1;
    const float kr0 = k0 * c0 - k1 * s0;
    const float kr1 = k1 * c1 + k0 * s1;

    const size_t o = (size_t)t * HID + h * HD + d;
    __nv_bfloat16 hh, ll;
    split_hilo(qr0, hh, ll); g_qhi[o] = hh;      g_qlo[o] = ll;
    split_hilo(qr1, hh, ll); g_qhi[o + 40] = hh; g_qlo[o + 40] = ll;
    split_hilo(kr0, hh, ll); g_khi[o] = hh;      g_klo[o] = ll;
    split_hilo(kr1, hh, ll); g_khi[o + 40] = hh; g_klo[o + 40] = ll;
    split_hilo(v0, hh, ll);  g_vhi[o] = hh;      g_vlo[o] = ll;
    split_hilo(v1, hh, ll);  g_vhi[o + 40] = hh; g_vlo[o + 40] = ll;
}

// ---------------------------------------------------------------------------
// HMMA flash attention. CTA = (chunk, head, 128 q rows); 8 warps x 16 rows.
// KV in 64-key double-buffered stages; S + softmax state in registers.
// hi/lo split (3-term) for QK^T and PV.
// smem row stride 176 B -> conflict-free ldmatrix (48i mod 128 distinct banks).
// ---------------------------------------------------------------------------
#define ARB 176                         // bytes per smem row
#define AQ_BYTES (128 * ARB)            // 22528
#define AKV_BYTES (64 * ARB)            // 11264
#define A_STG (4 * AKV_BYTES)           // K hi/lo + V hi/lo = 45056
#define ATTN_SMEM (2 * AQ_BYTES + 2 * A_STG)   // 135168
#define AK_HI 0
#define AK_LO (1 * AKV_BYTES)
#define AV_HI (2 * AKV_BYTES)
#define AV_LO (3 * AKV_BYTES)

__global__ __launch_bounds__(256, 1)
void attn_mma()
{
    extern __shared__ char dsm[];
    const uint32_t sbase = smem_u32(dsm);
    const uint32_t SQH = sbase;
    const uint32_t SQL = sbase + AQ_BYTES;
    const uint32_t SKV0 = sbase + 2 * AQ_BYTES;

    const int tid  = threadIdx.x;
    const int lane = tid & 31;
    const int wid  = tid >> 5;
    const int nc = blockIdx.y >> 4;
    const int h  = blockIdx.y & 15;
    const int t0 = nc * CH + blockIdx.x * 128;
    const float kscale = 0.11180339887498949f * 1.4426950408889634f; // /sqrt(80)*log2(e)

    // ldmatrix lane addressing
    const int a_row = (lane & 15);
    const int a_kof = (lane >> 4) << 3;
    const int b_nof = (lane & 7) + ((lane >> 4) << 3);
    const int b_kof = ((lane >> 3) & 1) << 3;
    const int v_row = (lane & 15);                 // key row for trans load
    const int v_cof = (lane >> 4) << 3;            // hd col offset

    // load Q (128 rows x 10 chunks x hi/lo)
    for (int i = tid; i < 1280; i += 256) {
        const int r = i / 10, c = i % 10;
        const uint32_t off = (uint32_t)(r * ARB + c * 16);
        const size_t src = (size_t)(t0 + r) * HID + h * HD + c * 8;
        cpa16(SQH + off, g_qhi + src);
        cpa16(SQL + off, g_qlo + src);
    }
    auto load_kv = [&](int kb, int s) {
        const uint32_t sb = SKV0 + s * A_STG;
        for (int i = tid; i < 640; i += 256) {
            const int r = i / 10, c = i % 10;
            const uint32_t off = (uint32_t)(r * ARB + c * 16);
            const size_t src = (size_t)(nc * CH + kb * 64 + r) * HID + h * HD + c * 8;
            cpa16(sb + AK_HI + off, g_khi + src);
            cpa16(sb + AK_LO + off, g_klo + src);
            cpa16(sb + AV_HI + off, g_vhi + src);
            cpa16(sb + AV_LO + off, g_vlo + src);
        }
        cpa_commit();
    };
    load_kv(0, 0);
    cpa_commit();   // flush Q+stage0 as one tracked group boundary

    float o[10][4];
#pragma unroll
    for (int n = 0; n < 10; n++)
#pragma unroll
        for (int c = 0; c < 4; c++) o[n][c] = 0.f;
    float m0 = -1e30f, m1 = -1e30f, l0 = 0.f, l1 = 0.f;

    for (int kb = 0; kb < 16; kb++) {
        if (kb > 0) __syncthreads();
        if (kb + 1 < 16) {
            load_kv(kb + 1, (kb + 1) & 1);
            cpa_wait<1>();
        } else {
            cpa_wait<0>();
        }
        __syncthreads();

        const uint32_t sb = SKV0 + (kb & 1) * A_STG;

        // ---- S = Q K^T (3-term split), 64 cols, k=80 ----
        float s[8][4];
#pragma unroll
        for (int j = 0; j < 8; j++)
#pragma unroll
            for (int c = 0; c < 4; c++) s[j][c] = 0.f;

#pragma unroll
        for (int kt = 0; kt < 5; kt++) {
            uint32_t ah[4], al[4];
            const uint32_t ad = SQH + (wid * 16 + a_row) * ARB +
                                (kt * 16 + a_kof) * 2;
            ldm_x4(ah, ad);
            ldm_x4(al, ad + (SQL - SQH));
#pragma unroll
            for (int g = 0; g < 4; g++) {
                uint32_t bh[4], bl[4];
                const uint32_t bd = sb + AK_HI + (g * 16 + b_nof) * ARB +
                                    (kt * 16 + b_kof) * 2;
                ldm_x4(bh, bd);
                ldm_x4(bl, bd + AKV_BYTES);
                mma16816(s[2 * g + 0], ah, &bh[0]);
                mma16816(s[2 * g + 1], ah, &bh[2]);
                mma16816(s[2 * g + 0], ah, &bl[0]);
                mma16816(s[2 * g + 1], ah, &bl[2]);
                mma16816(s[2 * g + 0], al, &bh[0]);
                mma16816(s[2 * g + 1], al, &bh[2]);
            }
        }

        // ---- online softmax (rows r = lane>>2 and r+8 within warp tile) ----
        float mb0 = -1e30f, mb1 = -1e30f;
#pragma unroll
        for (int j = 0; j < 8; j++) {
            mb0 = fmaxf(mb0, fmaxf(s[j][0], s[j][1]));
            mb1 = fmaxf(mb1, fmaxf(s[j][2], s[j][3]));
        }
        mb0 = fmaxf(mb0, __shfl_xor_sync(0xffffffffu, mb0, 1));
        mb0 = fmaxf(mb0, __shfl_xor_sync(0xffffffffu, mb0, 2));
        mb1 = fmaxf(mb1, __shfl_xor_sync(0xffffffffu, mb1, 1));
        mb1 = fmaxf(mb1, __shfl_xor_sync(0xffffffffu, mb1, 2));

        const float mn0 = fmaxf(m0, mb0), mn1 = fmaxf(m1, mb1);
        const float alpha0 = exp2f((m0 - mn0) * kscale);
        const float alpha1 = exp2f((m1 - mn1) * kscale);
        m0 = mn0; m1 = mn1;

        float sum0 = 0.f, sum1 = 0.f;
#pragma unroll
        for (int j = 0; j < 8; j++) {
            s[j][0] = exp2f((s[j][0] - m0) * kscale); sum0 += s[j][0];
            s[j][1] = exp2f((s[j][1] - m0) * kscale); sum0 += s[j][1];
            s[j][2] = exp2f((s[j][2] - m1) * kscale); sum1 += s[j][2];
            s[j][3] = exp2f((s[j][3] - m1) * kscale); sum1 += s[j][3];
        }
        sum0 += __shfl_xor_sync(0xffffffffu, sum0, 1);
        sum0 += __shfl_xor_sync(0xffffffffu, sum0, 2);
        sum1 += __shfl_xor_sync(0xffffffffu, sum1, 1);
        sum1 += __shfl_xor_sync(0xffffffffu, sum1, 2);
        l0 = l0 * alpha0 + sum0;
        l1 = l1 * alpha1 + sum1;

#pragma unroll
        for (int n = 0; n < 10; n++) {
            o[n][0] *= alpha0; o[n][1] *= alpha0;
            o[n][2] *= alpha1; o[n][3] *= alpha1;
        }

        // ---- O += P V (3-term split); k = 64 keys, n = 80 hd ----
#pragma unroll
        for (int t = 0; t < 4; t++) {
            uint32_t ph[4], pl[4];
            const float* f0 = s[2 * t];
            const float* f1 = s[2 * t + 1];
            ph[0] = pack_bf16(f0[0], f0[1]);
            ph[1] = pack_bf16(f0[2], f0[3]);
            ph[2] = pack_bf16(f1[0], f1[1]);
            ph[3] = pack_bf16(f1[2], f1[3]);
#pragma unroll
            for (int q = 0; q < 4; q++) {
                const float* f = (q < 2) ? f0 : f1;
                const int b = (q & 1) * 2;
                const float lx = f[b]     - __uint_as_float(ph[q] << 16);
                const float ly = f[b + 1] - __uint_as_float(ph[q] & 0xFFFF0000u);
                pl[q] = pack_bf16(lx, ly);
            }
#pragma unroll
            for (int v = 0; v < 5; v++) {
                uint32_t vh[4], vl[4];
                const uint32_t vd = sb + AV_HI + (t * 16 + v_row) * ARB +
                                    (v * 16 + v_cof) * 2;
                ldm_x4_t(vh, vd);
                ldm_x4_t(vl, vd + AKV_BYTES);
                mma16816(o[2 * v + 0], ph, &vh[0]);
                mma16816(o[2 * v + 1], ph, &vh[2]);
                mma16816(o[2 * v + 0], ph, &vl[0]);
                mma16816(o[2 * v + 1], ph, &vl[2]);
                mma16816(o[2 * v + 0], pl, &vh[0]);
                mma16816(o[2 * v + 1], pl, &vh[2]);
            }
        }
    }

    // ---- epilogue: o/l -> hi/lo bf16 -> g_ahi/g_alo ----
    const float li0 = 1.f / l0, li1 = 1.f / l1;
    const int r0 = t0 + wid * 16 + (lane >> 2);
    const size_t colb = h * HD + 2 * (lane & 3);
#pragma unroll
    for (int n = 0; n < 10; n++) {
        const float f00 = o[n][0] * li0, f01 = o[n][1] * li0;
        const float f10 = o[n][2] * li1, f11 = o[n][3] * li1;
        __nv_bfloat16 h00, l00, h01, l01, h10, l10, h11, l11;
        split_hilo(f00, h00, l00); split_hilo(f01, h01, l01);
        split_hilo(f10, h10, l10); split_hilo(f11, h11, l11);
        const size_t p0 = (size_t)r0 * HID + colb + n * 8;
        const size_t p1 = (size_t)(r0 + 8) * HID + colb + n * 8;
        *(__nv_bfloat162*)(g_ahi + p0) = __nv_bfloat162(h00, h01);
        *(__nv_bfloat162*)(g_alo + p0) = __nv_bfloat162(l00, l01);
        *(__nv_bfloat162*)(g_ahi + p1) = __nv_bfloat162(h10, h11);
        *(__nv_bfloat162*)(g_alo + p1) = __nv_bfloat162(l10, l11);
    }
}

// ---------------------------------------------------------------------------
extern "C" void kernel_launch(void* const* d_in, const int* in_sizes, int n_in,
                              void* d_out, int out_size)
{
    const float* x      = (const float*)d_in[0];
    const float* cosb   = (const float*)d_in[2];
    const float* sinb   = (const float*)d_in[3];
    const float* w_qkv  = (const float*)d_in[4];
    const float* b_qkv  = (const float*)d_in[5];
    const float* w_proj = (const float*)d_in[6];
    const float* b_proj = (const float*)d_in[7];
    float* out = (float*)d_out;

    float* qkv_p;
    __nv_bfloat16 *xhi, *xlo, *wqhi, *wqlo, *wphi, *wplo, *ahi, *alo;
    cudaGetSymbolAddress((void**)&qkv_p, g_qkv);
    cudaGetSymbolAddress((void**)&xhi, g_xhi);
    cudaGetSymbolAddress((void**)&xlo, g_xlo);
    cudaGetSymbolAddress((void**)&wqhi, g_wqhi);
    cudaGetSymbolAddress((void**)&wqlo, g_wqlo);
    cudaGetSymbolAddress((void**)&wphi, g_wphi);
    cudaGetSymbolAddress((void**)&wplo, g_wplo);
    cudaGetSymbolAddress((void**)&ahi, g_ahi);
    cudaGetSymbolAddress((void**)&alo, g_alo);

    cudaFuncSetAttribute(gemm_mma,
                         cudaFuncAttributeMaxDynamicSharedMemorySize, GEMM_SMEM);
    cudaFuncSetAttribute(attn_mma,
                         cudaFuncAttributeMaxDynamicSharedMemorySize, ATTN_SMEM);

    const int n_x = S_LEN * HID;
    const int n_wq = 3 * HID * HID;
    const int n_wp = HID * HID;

    cvt_hilo<<<(n_x / 4 + 255) / 256, 256>>>(x, xhi, xlo, n_x);
    cvt_hilo<<<(n_wq / 4 + 255) / 256, 256>>>(w_qkv, wqhi, wqlo, n_wq);
    cvt_hilo<<<(n_wp / 4 + 255) / 256, 256>>>(w_proj, wphi, wplo, n_wp);

    gemm_mma<<<dim3(3 * HID / GBN, S_LEN / GBM), 256, GEMM_SMEM>>>(
        xhi, xlo, wqhi, wqlo, b_qkv, qkv_p, S_LEN, 3 * HID, HID);

    rope_cvt<<<(S_LEN * NH * 40 + 255) / 256, 256>>>(cosb, sinb);

    attn_mma<<<dim3(8, NC * NH), 256, ATTN_SMEM>>>();

    gemm_mma<<<dim3(HID / GBN, S_LEN / GBM), 256, GEMM_SMEM>>>(
        ahi, alo, wphi, wplo, b_proj, out, S_LEN, HID, HID);
}

// round 5
// speedup vs baseline: 3.3849x; 1.0171x over previous
#include <cuda_runtime.h>
#include <cuda_bf16.h>
#include <cstdint>
#include <math.h>

#define S_LEN 16384
#define HID 1280
#define NH 16
#define HD 80
#define NC 16
#define CH 1024
#define QKV_STRIDE (3 * HID)   // 3840

// ---------------------------------------------------------------------------
// Scratch (no cudaMalloc allowed)
// ---------------------------------------------------------------------------
__device__ float g_qkv[(size_t)S_LEN * 3 * HID];   // [S, 3, NH, HD] fp32

__device__ __align__(256) __nv_bfloat16 g_xhi[(size_t)S_LEN * HID];
__device__ __align__(256) __nv_bfloat16 g_xlo[(size_t)S_LEN * HID];
__device__ __align__(256) __nv_bfloat16 g_wqhi[(size_t)3 * HID * HID];
__device__ __align__(256) __nv_bfloat16 g_wqlo[(size_t)3 * HID * HID];
__device__ __align__(256) __nv_bfloat16 g_wphi[(size_t)HID * HID];
__device__ __align__(256) __nv_bfloat16 g_wplo[(size_t)HID * HID];
// attention inputs, [S, NH, HD] bf16 hi/lo (q pre-scaled by 1/sqrt(80)*log2e)
__device__ __align__(256) __nv_bfloat16 g_qhi[(size_t)S_LEN * HID];
__device__ __align__(256) __nv_bfloat16 g_qlo[(size_t)S_LEN * HID];
__device__ __align__(256) __nv_bfloat16 g_khi[(size_t)S_LEN * HID];
__device__ __align__(256) __nv_bfloat16 g_klo[(size_t)S_LEN * HID];
__device__ __align__(256) __nv_bfloat16 g_vhi[(size_t)S_LEN * HID];
__device__ __align__(256) __nv_bfloat16 g_vlo[(size_t)S_LEN * HID];
// attention output (= proj GEMM input), hi/lo
__device__ __align__(256) __nv_bfloat16 g_ahi[(size_t)S_LEN * HID];
__device__ __align__(256) __nv_bfloat16 g_alo[(size_t)S_LEN * HID];

// ---------------------------------------------------------------------------
// helpers (sm_80-era instructions only — harness compiles for plain sm_103)
// ---------------------------------------------------------------------------
__device__ __forceinline__ uint32_t smem_u32(const void* p) {
    uint32_t a;
    asm("{ .reg .u64 t; cvta.to.shared.u64 t, %1; cvt.u32.u64 %0, t; }"
        : "=r"(a) : "l"(p));
    return a;
}

__device__ __forceinline__ void cpa16(uint32_t dst, const void* src) {
    asm volatile("cp.async.cg.shared.global [%0], [%1], 16;\n"
                 :: "r"(dst), "l"(src));
}
__device__ __forceinline__ void cpa_commit() {
    asm volatile("cp.async.commit_group;\n" ::: "memory");
}
template <int N>
__device__ __forceinline__ void cpa_wait() {
    asm volatile("cp.async.wait_group %0;\n" :: "n"(N) : "memory");
}

__device__ __forceinline__ void ldm_x4(uint32_t* r, uint32_t addr) {
    asm volatile("ldmatrix.sync.aligned.m8n8.x4.shared.b16 {%0,%1,%2,%3}, [%4];"
                 : "=r"(r[0]), "=r"(r[1]), "=r"(r[2]), "=r"(r[3])
                 : "r"(addr));
}
__device__ __forceinline__ void ldm_x4_t(uint32_t* r, uint32_t addr) {
    asm volatile(
        "ldmatrix.sync.aligned.m8n8.x4.trans.shared.b16 {%0,%1,%2,%3}, [%4];"
        : "=r"(r[0]), "=r"(r[1]), "=r"(r[2]), "=r"(r[3])
        : "r"(addr));
}

__device__ __forceinline__ void mma16816(float* d, const uint32_t* a,
                                         const uint32_t* b) {
    asm volatile(
        "mma.sync.aligned.m16n8k16.row.col.f32.bf16.bf16.f32 "
        "{%0,%1,%2,%3}, {%4,%5,%6,%7}, {%8,%9}, {%0,%1,%2,%3};"
        : "+f"(d[0]), "+f"(d[1]), "+f"(d[2]), "+f"(d[3])
        : "r"(a[0]), "r"(a[1]), "r"(a[2]), "r"(a[3]), "r"(b[0]), "r"(b[1]));
}

// pack two fp32 into bf16x2: low half = lo, high half = hi
__device__ __forceinline__ uint32_t pack_bf16(float lo, float hi) {
    uint32_t d;
    asm("cvt.rn.bf16x2.f32 %0, %1, %2;" : "=r"(d) : "f"(hi), "f"(lo));
    return d;
}

__device__ __forceinline__ void split_hilo(float f, __nv_bfloat16& h,
                                           __nv_bfloat16& l) {
    h = __float2bfloat16(f);
    l = __float2bfloat16(f - __bfloat162float(h));
}

// ---------------------------------------------------------------------------
// fp32 -> (hi, lo) bf16 split conversion  (n must be a multiple of 4)
// ---------------------------------------------------------------------------
__global__ void cvt_hilo(const float* __restrict__ src,
                         __nv_bfloat16* __restrict__ hi,
                         __nv_bfloat16* __restrict__ lo, int n)
{
    int i = (blockIdx.x * blockDim.x + threadIdx.x) * 4;
    if (i >= n) return;
    float4 v = *(const float4*)(src + i);
    float f[4] = {v.x, v.y, v.z, v.w};
    __nv_bfloat16 h[4], l[4];
#pragma unroll
    for (int j = 0; j < 4; j++) split_hilo(f[j], h[j], l[j]);
    *(__nv_bfloat162*)(hi + i)     = __nv_bfloat162(h[0], h[1]);
    *(__nv_bfloat162*)(hi + i + 2) = __nv_bfloat162(h[2], h[3]);
    *(__nv_bfloat162*)(lo + i)     = __nv_bfloat162(l[0], l[1]);
    *(__nv_bfloat162*)(lo + i + 2) = __nv_bfloat162(l[2], l[3]);
}

// ---------------------------------------------------------------------------
// HMMA GEMM: C[M,N] = split(A)[M,K] @ split(B)[N,K]^T + bias[N]
// Block 128x128, K-chunk 32, 8 warps (4M x 2N), warp tile 32x64.
// Single __syncthreads per K-iter; prefetch issued post-barrier.
// ---------------------------------------------------------------------------
#define GBM 128
#define GBN 128
#define GBK 32
#define ROWB 80
#define MAT_BYTES (128 * ROWB)
#define SM_AHI 0
#define SM_ALO (1 * MAT_BYTES)
#define SM_BHI (2 * MAT_BYTES)
#define SM_BLO (3 * MAT_BYTES)
#define STG_BYTES (4 * MAT_BYTES)     // 40960
#define GEMM_SMEM (2 * STG_BYTES)     // 81920

__global__ __launch_bounds__(256, 2)
void gemm_mma(const __nv_bfloat16* __restrict__ Ahi,
              const __nv_bfloat16* __restrict__ Alo,
              const __nv_bfloat16* __restrict__ Bhi,
              const __nv_bfloat16* __restrict__ Blo,
              const float* __restrict__ bias, float* __restrict__ C,
              int M, int N, int K)
{
    extern __shared__ char dsm[];
    const uint32_t sbase = smem_u32(dsm);

    const int tid  = threadIdx.x;
    const int lane = tid & 31;
    const int wid  = tid >> 5;
    const int wm   = wid & 3;
    const int wn   = wid >> 2;
    const int bm   = blockIdx.y * GBM;
    const int bn   = blockIdx.x * GBN;
    const int NK   = K / GBK;

    float acc[2][8][4];
#pragma unroll
    for (int i = 0; i < 2; i++)
#pragma unroll
        for (int j = 0; j < 8; j++)
#pragma unroll
            for (int c = 0; c < 4; c++) acc[i][j][c] = 0.f;

    auto load_stage = [&](int k0, int s) {
        const uint32_t sb = sbase + s * STG_BYTES;
#pragma unroll
        for (int i = 0; i < 2; i++) {
            const int c   = tid + i * 256;
            const int row = c >> 2, j = c & 3;
            const uint32_t off = (uint32_t)(row * ROWB + j * 16);
            const size_t ga = (size_t)(bm + row) * K + k0 + j * 8;
            const size_t gb = (size_t)(bn + row) * K + k0 + j * 8;
            cpa16(sb + SM_AHI + off, Ahi + ga);
            cpa16(sb + SM_ALO + off, Alo + ga);
            cpa16(sb + SM_BHI + off, Bhi + gb);
            cpa16(sb + SM_BLO + off, Blo + gb);
        }
        cpa_commit();
    };

    load_stage(0, 0);

    const int a_row = (lane & 15);
    const int a_kof = (lane >> 4) << 3;
    const int b_nof = (lane & 7) + ((lane >> 4) << 3);
    const int b_kof = ((lane >> 3) & 1) << 3;

    for (int k = 0; k < NK; k++) {
        cpa_wait<0>();                          // stage k landed
        __syncthreads();                        // visibility + WAR barrier
        if (k + 1 < NK) load_stage((k + 1) * GBK, (k + 1) & 1);

        const uint32_t sb = sbase + (k & 1) * STG_BYTES;
#pragma unroll
        for (int kk = 0; kk < GBK; kk += 16) {
            uint32_t a_hi[2][4], a_lo[2][4];
#pragma unroll
            for (int mf = 0; mf < 2; mf++) {
                const uint32_t ad = sb + SM_AHI +
                    (wm * 32 + mf * 16 + a_row) * ROWB + (kk + a_kof) * 2;
                ldm_x4(a_hi[mf], ad);
                ldm_x4(a_lo[mf], ad + MAT_BYTES);
            }
#pragma unroll
            for (int j = 0; j < 4; j++) {
                uint32_t b_hi[4], b_lo[4];
                const uint32_t bd = sb + SM_BHI +
                    (wn * 64 + j * 16 + b_nof) * ROWB + (kk + b_kof) * 2;
                ldm_x4(b_hi, bd);
                ldm_x4(b_lo, bd + MAT_BYTES);
#pragma unroll
                for (int mf = 0; mf < 2; mf++) {
                    mma16816(acc[mf][2 * j + 0], a_hi[mf], &b_hi[0]);
                    mma16816(acc[mf][2 * j + 1], a_hi[mf], &b_hi[2]);
                    mma16816(acc[mf][2 * j + 0], a_hi[mf], &b_lo[0]);
                    mma16816(acc[mf][2 * j + 1], a_hi[mf], &b_lo[2]);
                    mma16816(acc[mf][2 * j + 0], a_lo[mf], &b_hi[0]);
                    mma16816(acc[mf][2 * j + 1], a_lo[mf], &b_hi[2]);
                }
            }
        }
    }

#pragma unroll
    for (int mf = 0; mf < 2; mf++) {
        const int r0 = bm + wm * 32 + mf * 16 + (lane >> 2);
#pragma unroll
        for (int nf = 0; nf < 8; nf++) {
            const int c0 = bn + wn * 64 + nf * 8 + (lane & 3) * 2;
            const float b0 = bias[c0], b1 = bias[c0 + 1];
            float2 v0 = {acc[mf][nf][0] + b0, acc[mf][nf][1] + b1};
            float2 v1 = {acc[mf][nf][2] + b0, acc[mf][nf][3] + b1};
            *(float2*)(C + (size_t)r0 * N + c0) = v0;
            *(float2*)(C + (size_t)(r0 + 8) * N + c0) = v1;
        }
    }
}

// ---------------------------------------------------------------------------
// RoPE + hi/lo bf16 conversion of q, k, v.  q pre-scaled by 1/sqrt(80)*log2e
// so the attention kernel's logits are already in log2 domain.
// ---------------------------------------------------------------------------
#define QSCALE 0.16130856f   // 0.11180339887 * 1.44269504089

__global__ void rope_cvt(const float* __restrict__ cosb,
                         const float* __restrict__ sinb)
{
    int idx = blockIdx.x * blockDim.x + threadIdx.x;
    if (idx >= S_LEN * NH * 40) return;
    const int d = idx % 40;
    const int h = (idx / 40) % NH;
    const int t = idx / (40 * NH);

    const float c0 = cosb[t * HD + d];
    const float c1 = cosb[t * HD + d + 40];
    const float s0 = sinb[t * HD + d];
    const float s1 = sinb[t * HD + d + 40];

    const size_t base = (size_t)t * QKV_STRIDE + h * HD;
    const float q0 = g_qkv[base + d],            q1 = g_qkv[base + d + 40];
    const float k0 = g_qkv[base + HID + d],      k1 = g_qkv[base + HID + d + 40];
    const float v0 = g_qkv[base + 2 * HID + d],  v1 = g_qkv[base + 2 * HID + d + 40];

    const float qr0 = (q0 * c0 - q1 * s0) * QSCALE;
    const float qr1 = (q1 * c1 + q0 * s1) * QSCALE;
    const float kr0 = k0 * c0 - k1 * s0;
    const float kr1 = k1 * c1 + k0 * s1;

    const size_t o = (size_t)t * HID + h * HD + d;
    __nv_bfloat16 hh, ll;
    split_hilo(qr0, hh, ll); g_qhi[o] = hh;      g_qlo[o] = ll;
    split_hilo(qr1, hh, ll); g_qhi[o + 40] = hh; g_qlo[o + 40] = ll;
    split_hilo(kr0, hh, ll); g_khi[o] = hh;      g_klo[o] = ll;
    split_hilo(kr1, hh, ll); g_khi[o + 40] = hh; g_klo[o + 40] = ll;
    split_hilo(v0, hh, ll);  g_vhi[o] = hh;      g_vlo[o] = ll;
    split_hilo(v1, hh, ll);  g_vhi[o + 40] = hh; g_vlo[o + 40] = ll;
}

// ---------------------------------------------------------------------------
// HMMA flash attention. CTA = (chunk, head, 128 q rows); 8 warps x 16 rows.
// 3-stage cp.async KV pipeline, single sync per iter, S + state in regs.
// ---------------------------------------------------------------------------
#define ARB 176                         // bytes per smem row
#define AQ_BYTES (128 * ARB)            // 22528
#define AKV_BYTES (64 * ARB)            // 11264
#define A_STG (4 * AKV_BYTES)           // 45056
#define ATTN_SMEM (2 * AQ_BYTES + 3 * A_STG)   // 180224
#define AK_HI 0
#define AK_LO (1 * AKV_BYTES)
#define AV_HI (2 * AKV_BYTES)
#define AV_LO (3 * AKV_BYTES)

__global__ __launch_bounds__(256, 1)
void attn_mma()
{
    extern __shared__ char dsm[];
    const uint32_t sbase = smem_u32(dsm);
    const uint32_t SQH = sbase;
    const uint32_t SQL = sbase + AQ_BYTES;
    const uint32_t SKV0 = sbase + 2 * AQ_BYTES;

    const int tid  = threadIdx.x;
    const int lane = tid & 31;
    const int wid  = tid >> 5;
    const int nc = blockIdx.y >> 4;
    const int h  = blockIdx.y & 15;
    const int t0 = nc * CH + blockIdx.x * 128;

    const int a_row = (lane & 15);
    const int a_kof = (lane >> 4) << 3;
    const int b_nof = (lane & 7) + ((lane >> 4) << 3);
    const int b_kof = ((lane >> 3) & 1) << 3;
    const int v_row = (lane & 15);
    const int v_cof = (lane >> 4) << 3;

    // Q loads (uncommitted; folded into group 0 with KV stage 0)
    for (int i = tid; i < 1280; i += 256) {
        const int r = i / 10, c = i % 10;
        const uint32_t off = (uint32_t)(r * ARB + c * 16);
        const size_t src = (size_t)(t0 + r) * HID + h * HD + c * 8;
        cpa16(SQH + off, g_qhi + src);
        cpa16(SQL + off, g_qlo + src);
    }
    auto load_kv = [&](int kb, int s) {
        const uint32_t sb = SKV0 + s * A_STG;
        for (int i = tid; i < 640; i += 256) {
            const int r = i / 10, c = i % 10;
            const uint32_t off = (uint32_t)(r * ARB + c * 16);
            const size_t src = (size_t)(nc * CH + kb * 64 + r) * HID + h * HD + c * 8;
            cpa16(sb + AK_HI + off, g_khi + src);
            cpa16(sb + AK_LO + off, g_klo + src);
            cpa16(sb + AV_HI + off, g_vhi + src);
            cpa16(sb + AV_LO + off, g_vlo + src);
        }
        cpa_commit();
    };
    load_kv(0, 0);       // group 0 (Q + KV0)
    load_kv(1, 1);       // group 1

    float o[10][4];
#pragma unroll
    for (int n = 0; n < 10; n++)
#pragma unroll
        for (int c = 0; c < 4; c++) o[n][c] = 0.f;
    float m0 = -1e30f, m1 = -1e30f, l0 = 0.f, l1 = 0.f;

    for (int kb = 0; kb < 16; kb++) {
        if (kb < 14) cpa_wait<1>(); else cpa_wait<0>();
        __syncthreads();
        if (kb + 2 < 16) load_kv(kb + 2, (kb + 2) % 3);

        const uint32_t sb = SKV0 + (kb % 3) * A_STG;

        // ---- S = Q K^T (3-term split), 64 cols, k=80; log2-domain logits ----
        float s[8][4];
#pragma unroll
        for (int j = 0; j < 8; j++)
#pragma unroll
            for (int c = 0; c < 4; c++) s[j][c] = 0.f;

#pragma unroll
        for (int kt = 0; kt < 5; kt++) {
            uint32_t ah[4], al[4];
            const uint32_t ad = SQH + (wid * 16 + a_row) * ARB +
                                (kt * 16 + a_kof) * 2;
            ldm_x4(ah, ad);
            ldm_x4(al, ad + (SQL - SQH));
#pragma unroll
            for (int g = 0; g < 4; g++) {
                uint32_t bh[4], bl[4];
                const uint32_t bd = sb + AK_HI + (g * 16 + b_nof) * ARB +
                                    (kt * 16 + b_kof) * 2;
                ldm_x4(bh, bd);
                ldm_x4(bl, bd + AKV_BYTES);
                mma16816(s[2 * g + 0], ah, &bh[0]);
                mma16816(s[2 * g + 1], ah, &bh[2]);
                mma16816(s[2 * g + 0], ah, &bl[0]);
                mma16816(s[2 * g + 1], ah, &bl[2]);
                mma16816(s[2 * g + 0], al, &bh[0]);
                mma16816(s[2 * g + 1], al, &bh[2]);
            }
        }

        // ---- online softmax (log2 domain) ----
        float mb0 = -1e30f, mb1 = -1e30f;
#pragma unroll
        for (int j = 0; j < 8; j++) {
            mb0 = fmaxf(mb0, fmaxf(s[j][0], s[j][1]));
            mb1 = fmaxf(mb1, fmaxf(s[j][2], s[j][3]));
        }
        mb0 = fmaxf(mb0, __shfl_xor_sync(0xffffffffu, mb0, 1));
        mb0 = fmaxf(mb0, __shfl_xor_sync(0xffffffffu, mb0, 2));
        mb1 = fmaxf(mb1, __shfl_xor_sync(0xffffffffu, mb1, 1));
        mb1 = fmaxf(mb1, __shfl_xor_sync(0xffffffffu, mb1, 2));

        const float mn0 = fmaxf(m0, mb0), mn1 = fmaxf(m1, mb1);
        const float alpha0 = exp2f(m0 - mn0);
        const float alpha1 = exp2f(m1 - mn1);
        m0 = mn0; m1 = mn1;

        float sum0 = 0.f, sum1 = 0.f;
#pragma unroll
        for (int j = 0; j < 8; j++) {
            s[j][0] = exp2f(s[j][0] - m0); sum0 += s[j][0];
            s[j][1] = exp2f(s[j][1] - m0); sum0 += s[j][1];
            s[j][2] = exp2f(s[j][2] - m1); sum1 += s[j][2];
            s[j][3] = exp2f(s[j][3] - m1); sum1 += s[j][3];
        }
        sum0 += __shfl_xor_sync(0xffffffffu, sum0, 1);
        sum0 += __shfl_xor_sync(0xffffffffu, sum0, 2);
        sum1 += __shfl_xor_sync(0xffffffffu, sum1, 1);
        sum1 += __shfl_xor_sync(0xffffffffu, sum1, 2);
        l0 = l0 * alpha0 + sum0;
        l1 = l1 * alpha1 + sum1;

#pragma unroll
        for (int n = 0; n < 10; n++) {
            o[n][0] *= alpha0; o[n][1] *= alpha0;
            o[n][2] *= alpha1; o[n][3] *= alpha1;
        }

        // ---- O += P V (3-term split); k = 64 keys, n = 80 hd ----
#pragma unroll
        for (int t = 0; t < 4; t++) {
            uint32_t ph[4], pl[4];
            const float* f0 = s[2 * t];
            const float* f1 = s[2 * t + 1];
            ph[0] = pack_bf16(f0[0], f0[1]);
            ph[1] = pack_bf16(f0[2], f0[3]);
            ph[2] = pack_bf16(f1[0], f1[1]);
            ph[3] = pack_bf16(f1[2], f1[3]);
#pragma unroll
            for (int q = 0; q < 4; q++) {
                const float* f = (q < 2) ? f0 : f1;
                const int b = (q & 1) * 2;
                const float lx = f[b]     - __uint_as_float(ph[q] << 16);
                const float ly = f[b + 1] - __uint_as_float(ph[q] & 0xFFFF0000u);
                pl[q] = pack_bf16(lx, ly);
            }
#pragma unroll
            for (int v = 0; v < 5; v++) {
                uint32_t vh[4], vl[4];
                const uint32_t vd = sb + AV_HI + (t * 16 + v_row) * ARB +
                                    (v * 16 + v_cof) * 2;
                ldm_x4_t(vh, vd);
                ldm_x4_t(vl, vd + AKV_BYTES);
                mma16816(o[2 * v + 0], ph, &vh[0]);
                mma16816(o[2 * v + 1], ph, &vh[2]);
                mma16816(o[2 * v + 0], ph, &vl[0]);
                mma16816(o[2 * v + 1], ph, &vl[2]);
                mma16816(o[2 * v + 0], pl, &vh[0]);
                mma16816(o[2 * v + 1], pl, &vh[2]);
            }
        }
    }

    // ---- epilogue: o/l -> hi/lo bf16 -> g_ahi/g_alo ----
    const float li0 = 1.f / l0, li1 = 1.f / l1;
    const int r0 = t0 + wid * 16 + (lane >> 2);
    const size_t colb = h * HD + 2 * (lane & 3);
#pragma unroll
    for (int n = 0; n < 10; n++) {
        const float f00 = o[n][0] * li0, f01 = o[n][1] * li0;
        const float f10 = o[n][2] * li1, f11 = o[n][3] * li1;
        __nv_bfloat16 h00, l00, h01, l01, h10, l10, h11, l11;
        split_hilo(f00, h00, l00); split_hilo(f01, h01, l01);
        split_hilo(f10, h10, l10); split_hilo(f11, h11, l11);
        const size_t p0 = (size_t)r0 * HID + colb + n * 8;
        const size_t p1 = (size_t)(r0 + 8) * HID + colb + n * 8;
        *(__nv_bfloat162*)(g_ahi + p0) = __nv_bfloat162(h00, h01);
        *(__nv_bfloat162*)(g_alo + p0) = __nv_bfloat162(l00, l01);
        *(__nv_bfloat162*)(g_ahi + p1) = __nv_bfloat162(h10, h11);
        *(__nv_bfloat162*)(g_alo + p1) = __nv_bfloat162(l10, l11);
    }
}

// ---------------------------------------------------------------------------
extern "C" void kernel_launch(void* const* d_in, const int* in_sizes, int n_in,
                              void* d_out, int out_size)
{
    const float* x      = (const float*)d_in[0];
    const float* cosb   = (const float*)d_in[2];
    const float* sinb   = (const float*)d_in[3];
    const float* w_qkv  = (const float*)d_in[4];
    const float* b_qkv  = (const float*)d_in[5];
    const float* w_proj = (const float*)d_in[6];
    const float* b_proj = (const float*)d_in[7];
    float* out = (float*)d_out;

    float* qkv_p;
    __nv_bfloat16 *xhi, *xlo, *wqhi, *wqlo, *wphi, *wplo, *ahi, *alo;
    cudaGetSymbolAddress((void**)&qkv_p, g_qkv);
    cudaGetSymbolAddress((void**)&xhi, g_xhi);
    cudaGetSymbolAddress((void**)&xlo, g_xlo);
    cudaGetSymbolAddress((void**)&wqhi, g_wqhi);
    cudaGetSymbolAddress((void**)&wqlo, g_wqlo);
    cudaGetSymbolAddress((void**)&wphi, g_wphi);
    cudaGetSymbolAddress((void**)&wplo, g_wplo);
    cudaGetSymbolAddress((void**)&ahi, g_ahi);
    cudaGetSymbolAddress((void**)&alo, g_alo);

    cudaFuncSetAttribute(gemm_mma,
                         cudaFuncAttributeMaxDynamicSharedMemorySize, GEMM_SMEM);
    cudaFuncSetAttribute(attn_mma,
                         cudaFuncAttributeMaxDynamicSharedMemorySize, ATTN_SMEM);

    const int n_x = S_LEN * HID;
    const int n_wq = 3 * HID * HID;
    const int n_wp = HID * HID;

    cvt_hilo<<<(n_x / 4 + 255) / 256, 256>>>(x, xhi, xlo, n_x);
    cvt_hilo<<<(n_wq / 4 + 255) / 256, 256>>>(w_qkv, wqhi, wqlo, n_wq);
    cvt_hilo<<<(n_wp / 4 + 255) / 256, 256>>>(w_proj, wphi, wplo, n_wp);

    gemm_mma<<<dim3(3 * HID / GBN, S_LEN / GBM), 256, GEMM_SMEM>>>(
        xhi, xlo, wqhi, wqlo, b_qkv, qkv_p, S_LEN, 3 * HID, HID);

    rope_cvt<<<(S_LEN * NH * 40 + 255) / 256, 256>>>(cosb, sinb);

    attn_mma<<<dim3(8, NC * NH), 256, ATTN_SMEM>>>();

    gemm_mma<<<dim3(HID / GBN, S_LEN / GBM), 256, GEMM_SMEM>>>(
        ahi, alo, wphi, wplo, b_proj, out, S_LEN, HID, HID);
}

// round 6
// speedup vs baseline: 3.5145x; 1.0383x over previous
#include <cuda_runtime.h>
#include <cuda_bf16.h>
#include <cuda_fp16.h>
#include <cstdint>
#include <math.h>

#define S_LEN 16384
#define HID 1280
#define NH 16
#define HD 80
#define NC 16
#define CH 1024
#define QKV_STRIDE (3 * HID)   // 3840

// ---------------------------------------------------------------------------
// Scratch (no cudaMalloc allowed)
// ---------------------------------------------------------------------------
__device__ float g_qkv[(size_t)S_LEN * 3 * HID];   // [S, 3, NH, HD] fp32

__device__ __align__(256) __nv_bfloat16 g_xhi[(size_t)S_LEN * HID];
__device__ __align__(256) __nv_bfloat16 g_xlo[(size_t)S_LEN * HID];
__device__ __align__(256) __nv_bfloat16 g_wqhi[(size_t)3 * HID * HID];
__device__ __align__(256) __nv_bfloat16 g_wqlo[(size_t)3 * HID * HID];
__device__ __align__(256) __nv_bfloat16 g_wphi[(size_t)HID * HID];
__device__ __align__(256) __nv_bfloat16 g_wplo[(size_t)HID * HID];
// attention inputs: q/k bf16 hi/lo (q pre-scaled by 1/sqrt(80)*log2e),
// v fp16 hi/lo (PV runs in fp16, 2-term)
__device__ __align__(256) __nv_bfloat16 g_qhi[(size_t)S_LEN * HID];
__device__ __align__(256) __nv_bfloat16 g_qlo[(size_t)S_LEN * HID];
__device__ __align__(256) __nv_bfloat16 g_khi[(size_t)S_LEN * HID];
__device__ __align__(256) __nv_bfloat16 g_klo[(size_t)S_LEN * HID];
__device__ __align__(256) __half       g_vhi[(size_t)S_LEN * HID];
__device__ __align__(256) __half       g_vlo[(size_t)S_LEN * HID];
// attention output (= proj GEMM input), hi/lo
__device__ __align__(256) __nv_bfloat16 g_ahi[(size_t)S_LEN * HID];
__device__ __align__(256) __nv_bfloat16 g_alo[(size_t)S_LEN * HID];

// ---------------------------------------------------------------------------
// helpers (sm_80-era instructions only — harness compiles for plain sm_103)
// ---------------------------------------------------------------------------
__device__ __forceinline__ uint32_t smem_u32(const void* p) {
    uint32_t a;
    asm("{ .reg .u64 t; cvta.to.shared.u64 t, %1; cvt.u32.u64 %0, t; }"
        : "=r"(a) : "l"(p));
    return a;
}

__device__ __forceinline__ void cpa16(uint32_t dst, const void* src) {
    asm volatile("cp.async.cg.shared.global [%0], [%1], 16;\n"
                 :: "r"(dst), "l"(src));
}
__device__ __forceinline__ void cpa_commit() {
    asm volatile("cp.async.commit_group;\n" ::: "memory");
}
template <int N>
__device__ __forceinline__ void cpa_wait() {
    asm volatile("cp.async.wait_group %0;\n" :: "n"(N) : "memory");
}

__device__ __forceinline__ void ldm_x4(uint32_t* r, uint32_t addr) {
    asm volatile("ldmatrix.sync.aligned.m8n8.x4.shared.b16 {%0,%1,%2,%3}, [%4];"
                 : "=r"(r[0]), "=r"(r[1]), "=r"(r[2]), "=r"(r[3])
                 : "r"(addr));
}
__device__ __forceinline__ void ldm_x4_t(uint32_t* r, uint32_t addr) {
    asm volatile(
        "ldmatrix.sync.aligned.m8n8.x4.trans.shared.b16 {%0,%1,%2,%3}, [%4];"
        : "=r"(r[0]), "=r"(r[1]), "=r"(r[2]), "=r"(r[3])
        : "r"(addr));
}

// bf16 mma, fp32 accumulate
__device__ __forceinline__ void mma16816(float* d, const uint32_t* a,
                                         const uint32_t* b) {
    asm volatile(
        "mma.sync.aligned.m16n8k16.row.col.f32.bf16.bf16.f32 "
        "{%0,%1,%2,%3}, {%4,%5,%6,%7}, {%8,%9}, {%0,%1,%2,%3};"
        : "+f"(d[0]), "+f"(d[1]), "+f"(d[2]), "+f"(d[3])
        : "r"(a[0]), "r"(a[1]), "r"(a[2]), "r"(a[3]), "r"(b[0]), "r"(b[1]));
}
// fp16 mma, fp32 accumulate
__device__ __forceinline__ void mma16816h(float* d, const uint32_t* a,
                                          const uint32_t* b) {
    asm volatile(
        "mma.sync.aligned.m16n8k16.row.col.f32.f16.f16.f32 "
        "{%0,%1,%2,%3}, {%4,%5,%6,%7}, {%8,%9}, {%0,%1,%2,%3};"
        : "+f"(d[0]), "+f"(d[1]), "+f"(d[2]), "+f"(d[3])
        : "r"(a[0]), "r"(a[1]), "r"(a[2]), "r"(a[3]), "r"(b[0]), "r"(b[1]));
}

// pack two fp32 into bf16x2 / f16x2: low half = lo, high half = hi
__device__ __forceinline__ uint32_t pack_bf16(float lo, float hi) {
    uint32_t d;
    asm("cvt.rn.bf16x2.f32 %0, %1, %2;" : "=r"(d) : "f"(hi), "f"(lo));
    return d;
}
__device__ __forceinline__ uint32_t pack_f16(float lo, float hi) {
    uint32_t d;
    asm("cvt.rn.f16x2.f32 %0, %1, %2;" : "=r"(d) : "f"(hi), "f"(lo));
    return d;
}

__device__ __forceinline__ void split_hilo(float f, __nv_bfloat16& h,
                                           __nv_bfloat16& l) {
    h = __float2bfloat16(f);
    l = __float2bfloat16(f - __bfloat162float(h));
}
__device__ __forceinline__ void split_hilo_h(float f, __half& h, __half& l) {
    h = __float2half(f);
    l = __float2half(f - __half2float(h));
}

// ---------------------------------------------------------------------------
// fp32 -> (hi, lo) bf16 split conversion  (n must be a multiple of 4)
// ---------------------------------------------------------------------------
__global__ void cvt_hilo(const float* __restrict__ src,
                         __nv_bfloat16* __restrict__ hi,
                         __nv_bfloat16* __restrict__ lo, int n)
{
    int i = (blockIdx.x * blockDim.x + threadIdx.x) * 4;
    if (i >= n) return;
    float4 v = *(const float4*)(src + i);
    float f[4] = {v.x, v.y, v.z, v.w};
    __nv_bfloat16 h[4], l[4];
#pragma unroll
    for (int j = 0; j < 4; j++) split_hilo(f[j], h[j], l[j]);
    *(__nv_bfloat162*)(hi + i)     = __nv_bfloat162(h[0], h[1]);
    *(__nv_bfloat162*)(hi + i + 2) = __nv_bfloat162(h[2], h[3]);
    *(__nv_bfloat162*)(lo + i)     = __nv_bfloat162(l[0], l[1]);
    *(__nv_bfloat162*)(lo + i + 2) = __nv_bfloat162(l[2], l[3]);
}

// ---------------------------------------------------------------------------
// HMMA GEMM: C[M,N] = split(A)[M,K] @ split(B)[N,K]^T + bias[N]
// Block 128x128, K-chunk 32, 8 warps (4M x 2N), warp tile 32x64.
// Single __syncthreads per K-iter; prefetch issued post-barrier.
// ---------------------------------------------------------------------------
#define GBM 128
#define GBN 128
#define GBK 32
#define ROWB 80
#define MAT_BYTES (128 * ROWB)
#define SM_AHI 0
#define SM_ALO (1 * MAT_BYTES)
#define SM_BHI (2 * MAT_BYTES)
#define SM_BLO (3 * MAT_BYTES)
#define STG_BYTES (4 * MAT_BYTES)     // 40960
#define GEMM_SMEM (2 * STG_BYTES)     // 81920

__global__ __launch_bounds__(256, 2)
void gemm_mma(const __nv_bfloat16* __restrict__ Ahi,
              const __nv_bfloat16* __restrict__ Alo,
              const __nv_bfloat16* __restrict__ Bhi,
              const __nv_bfloat16* __restrict__ Blo,
              const float* __restrict__ bias, float* __restrict__ C,
              int M, int N, int K)
{
    extern __shared__ char dsm[];
    const uint32_t sbase = smem_u32(dsm);

    const int tid  = threadIdx.x;
    const int lane = tid & 31;
    const int wid  = tid >> 5;
    const int wm   = wid & 3;
    const int wn   = wid >> 2;
    const int bm   = blockIdx.y * GBM;
    const int bn   = blockIdx.x * GBN;
    const int NK   = K / GBK;

    float acc[2][8][4];
#pragma unroll
    for (int i = 0; i < 2; i++)
#pragma unroll
        for (int j = 0; j < 8; j++)
#pragma unroll
            for (int c = 0; c < 4; c++) acc[i][j][c] = 0.f;

    auto load_stage = [&](int k0, int s) {
        const uint32_t sb = sbase + s * STG_BYTES;
#pragma unroll
        for (int i = 0; i < 2; i++) {
            const int c   = tid + i * 256;
            const int row = c >> 2, j = c & 3;
            const uint32_t off = (uint32_t)(row * ROWB + j * 16);
            const size_t ga = (size_t)(bm + row) * K + k0 + j * 8;
            const size_t gb = (size_t)(bn + row) * K + k0 + j * 8;
            cpa16(sb + SM_AHI + off, Ahi + ga);
            cpa16(sb + SM_ALO + off, Alo + ga);
            cpa16(sb + SM_BHI + off, Bhi + gb);
            cpa16(sb + SM_BLO + off, Blo + gb);
        }
        cpa_commit();
    };

    load_stage(0, 0);

    const int a_row = (lane & 15);
    const int a_kof = (lane >> 4) << 3;
    const int b_nof = (lane & 7) + ((lane >> 4) << 3);
    const int b_kof = ((lane >> 3) & 1) << 3;

    for (int k = 0; k < NK; k++) {
        cpa_wait<0>();                          // stage k landed
        __syncthreads();                        // visibility + WAR barrier
        if (k + 1 < NK) load_stage((k + 1) * GBK, (k + 1) & 1);

        const uint32_t sb = sbase + (k & 1) * STG_BYTES;
#pragma unroll
        for (int kk = 0; kk < GBK; kk += 16) {
            uint32_t a_hi[2][4], a_lo[2][4];
#pragma unroll
            for (int mf = 0; mf < 2; mf++) {
                const uint32_t ad = sb + SM_AHI +
                    (wm * 32 + mf * 16 + a_row) * ROWB + (kk + a_kof) * 2;
                ldm_x4(a_hi[mf], ad);
                ldm_x4(a_lo[mf], ad + MAT_BYTES);
            }
#pragma unroll
            for (int j = 0; j < 4; j++) {
                uint32_t b_hi[4], b_lo[4];
                const uint32_t bd = sb + SM_BHI +
                    (wn * 64 + j * 16 + b_nof) * ROWB + (kk + b_kof) * 2;
                ldm_x4(b_hi, bd);
                ldm_x4(b_lo, bd + MAT_BYTES);
#pragma unroll
                for (int mf = 0; mf < 2; mf++) {
                    mma16816(acc[mf][2 * j + 0], a_hi[mf], &b_hi[0]);
                    mma16816(acc[mf][2 * j + 1], a_hi[mf], &b_hi[2]);
                    mma16816(acc[mf][2 * j + 0], a_hi[mf], &b_lo[0]);
                    mma16816(acc[mf][2 * j + 1], a_hi[mf], &b_lo[2]);
                    mma16816(acc[mf][2 * j + 0], a_lo[mf], &b_hi[0]);
                    mma16816(acc[mf][2 * j + 1], a_lo[mf], &b_hi[2]);
                }
            }
        }
    }

#pragma unroll
    for (int mf = 0; mf < 2; mf++) {
        const int r0 = bm + wm * 32 + mf * 16 + (lane >> 2);
#pragma unroll
        for (int nf = 0; nf < 8; nf++) {
            const int c0 = bn + wn * 64 + nf * 8 + (lane & 3) * 2;
            const float b0 = bias[c0], b1 = bias[c0 + 1];
            float2 v0 = {acc[mf][nf][0] + b0, acc[mf][nf][1] + b1};
            float2 v1 = {acc[mf][nf][2] + b0, acc[mf][nf][3] + b1};
            *(float2*)(C + (size_t)r0 * N + c0) = v0;
            *(float2*)(C + (size_t)(r0 + 8) * N + c0) = v1;
        }
    }
}

// ---------------------------------------------------------------------------
// RoPE + conversion: q,k -> bf16 hi/lo (q pre-scaled into log2 domain),
// v -> fp16 hi/lo.
// ---------------------------------------------------------------------------
#define QSCALE 0.16130856f   // 0.11180339887 * 1.44269504089

__global__ void rope_cvt(const float* __restrict__ cosb,
                         const float* __restrict__ sinb)
{
    int idx = blockIdx.x * blockDim.x + threadIdx.x;
    if (idx >= S_LEN * NH * 40) return;
    const int d = idx % 40;
    const int h = (idx / 40) % NH;
    const int t = idx / (40 * NH);

    const float c0 = cosb[t * HD + d];
    const float c1 = cosb[t * HD + d + 40];
    const float s0 = sinb[t * HD + d];
    const float s1 = sinb[t * HD + d + 40];

    const size_t base = (size_t)t * QKV_STRIDE + h * HD;
    const float q0 = g_qkv[base + d],            q1 = g_qkv[base + d + 40];
    const float k0 = g_qkv[base + HID + d],      k1 = g_qkv[base + HID + d + 40];
    const float v0 = g_qkv[base + 2 * HID + d],  v1 = g_qkv[base + 2 * HID + d + 40];

    const float qr0 = (q0 * c0 - q1 * s0) * QSCALE;
    const float qr1 = (q1 * c1 + q0 * s1) * QSCALE;
    const float kr0 = k0 * c0 - k1 * s0;
    const float kr1 = k1 * c1 + k0 * s1;

    const size_t o = (size_t)t * HID + h * HD + d;
    __nv_bfloat16 hh, ll;
    __half hf, lf;
    split_hilo(qr0, hh, ll); g_qhi[o] = hh;      g_qlo[o] = ll;
    split_hilo(qr1, hh, ll); g_qhi[o + 40] = hh; g_qlo[o + 40] = ll;
    split_hilo(kr0, hh, ll); g_khi[o] = hh;      g_klo[o] = ll;
    split_hilo(kr1, hh, ll); g_khi[o + 40] = hh; g_klo[o + 40] = ll;
    split_hilo_h(v0, hf, lf); g_vhi[o] = hf;      g_vlo[o] = lf;
    split_hilo_h(v1, hf, lf); g_vhi[o + 40] = hf; g_vlo[o + 40] = lf;
}

// ---------------------------------------------------------------------------
// HMMA flash attention. CTA = (chunk, head, 128 q rows); 8 warps x 16 rows.
// 3-stage cp.async KV pipeline, single sync per iter, S + state in regs.
// QK^T: bf16 3-term split.  PV: fp16, P rounded to fp16 (1 term) x V hi/lo
// fp16 (2 terms) -> 2 MMAs per tile instead of 3.
// ---------------------------------------------------------------------------
#define ARB 176                         // bytes per smem row
#define AQ_BYTES (128 * ARB)            // 22528
#define AKV_BYTES (64 * ARB)            // 11264
#define A_STG (4 * AKV_BYTES)           // 45056
#define ATTN_SMEM (2 * AQ_BYTES + 3 * A_STG)   // 180224
#define AK_HI 0
#define AK_LO (1 * AKV_BYTES)
#define AV_HI (2 * AKV_BYTES)
#define AV_LO (3 * AKV_BYTES)

__global__ __launch_bounds__(256, 1)
void attn_mma()
{
    extern __shared__ char dsm[];
    const uint32_t sbase = smem_u32(dsm);
    const uint32_t SQH = sbase;
    const uint32_t SQL = sbase + AQ_BYTES;
    const uint32_t SKV0 = sbase + 2 * AQ_BYTES;

    const int tid  = threadIdx.x;
    const int lane = tid & 31;
    const int wid  = tid >> 5;
    const int nc = blockIdx.y >> 4;
    const int h  = blockIdx.y & 15;
    const int t0 = nc * CH + blockIdx.x * 128;

    const int a_row = (lane & 15);
    const int a_kof = (lane >> 4) << 3;
    const int b_nof = (lane & 7) + ((lane >> 4) << 3);
    const int b_kof = ((lane >> 3) & 1) << 3;
    const int v_row = (lane & 15);
    const int v_cof = (lane >> 4) << 3;

    // Q loads (folded into group 0 with KV stage 0)
    for (int i = tid; i < 1280; i += 256) {
        const int r = i / 10, c = i % 10;
        const uint32_t off = (uint32_t)(r * ARB + c * 16);
        const size_t src = (size_t)(t0 + r) * HID + h * HD + c * 8;
        cpa16(SQH + off, g_qhi + src);
        cpa16(SQL + off, g_qlo + src);
    }
    auto load_kv = [&](int kb, int s) {
        const uint32_t sb = SKV0 + s * A_STG;
        for (int i = tid; i < 640; i += 256) {
            const int r = i / 10, c = i % 10;
            const uint32_t off = (uint32_t)(r * ARB + c * 16);
            const size_t src = (size_t)(nc * CH + kb * 64 + r) * HID + h * HD + c * 8;
            cpa16(sb + AK_HI + off, g_khi + src);
            cpa16(sb + AK_LO + off, g_klo + src);
            cpa16(sb + AV_HI + off, g_vhi + src);
            cpa16(sb + AV_LO + off, g_vlo + src);
        }
        cpa_commit();
    };
    load_kv(0, 0);       // group 0 (Q + KV0)
    load_kv(1, 1);       // group 1

    float o[10][4];
#pragma unroll
    for (int n = 0; n < 10; n++)
#pragma unroll
        for (int c = 0; c < 4; c++) o[n][c] = 0.f;
    float m0 = -1e30f, m1 = -1e30f, l0 = 0.f, l1 = 0.f;

    for (int kb = 0; kb < 16; kb++) {
        if (kb < 14) cpa_wait<1>(); else cpa_wait<0>();
        __syncthreads();
        if (kb + 2 < 16) load_kv(kb + 2, (kb + 2) % 3);

        const uint32_t sb = SKV0 + (kb % 3) * A_STG;

        // ---- S = Q K^T (3-term split), 64 cols, k=80; log2-domain logits ----
        float s[8][4];
#pragma unroll
        for (int j = 0; j < 8; j++)
#pragma unroll
            for (int c = 0; c < 4; c++) s[j][c] = 0.f;

#pragma unroll
        for (int kt = 0; kt < 5; kt++) {
            uint32_t ah[4], al[4];
            const uint32_t ad = SQH + (wid * 16 + a_row) * ARB +
                                (kt * 16 + a_kof) * 2;
            ldm_x4(ah, ad);
            ldm_x4(al, ad + (SQL - SQH));
#pragma unroll
            for (int g = 0; g < 4; g++) {
                uint32_t bh[4], bl[4];
                const uint32_t bd = sb + AK_HI + (g * 16 + b_nof) * ARB +
                                    (kt * 16 + b_kof) * 2;
                ldm_x4(bh, bd);
                ldm_x4(bl, bd + AKV_BYTES);
                mma16816(s[2 * g + 0], ah, &bh[0]);
                mma16816(s[2 * g + 1], ah, &bh[2]);
                mma16816(s[2 * g + 0], ah, &bl[0]);
                mma16816(s[2 * g + 1], ah, &bl[2]);
                mma16816(s[2 * g + 0], al, &bh[0]);
                mma16816(s[2 * g + 1], al, &bh[2]);
            }
        }

        // ---- online softmax (log2 domain) ----
        float mb0 = -1e30f, mb1 = -1e30f;
#pragma unroll
        for (int j = 0; j < 8; j++) {
            mb0 = fmaxf(mb0, fmaxf(s[j][0], s[j][1]));
            mb1 = fmaxf(mb1, fmaxf(s[j][2], s[j][3]));
        }
        mb0 = fmaxf(mb0, __shfl_xor_sync(0xffffffffu, mb0, 1));
        mb0 = fmaxf(mb0, __shfl_xor_sync(0xffffffffu, mb0, 2));
        mb1 = fmaxf(mb1, __shfl_xor_sync(0xffffffffu, mb1, 1));
        mb1 = fmaxf(mb1, __shfl_xor_sync(0xffffffffu, mb1, 2));

        const float mn0 = fmaxf(m0, mb0), mn1 = fmaxf(m1, mb1);
        const float alpha0 = exp2f(m0 - mn0);
        const float alpha1 = exp2f(m1 - mn1);
        m0 = mn0; m1 = mn1;

        float sum0 = 0.f, sum1 = 0.f;
#pragma unroll
        for (int j = 0; j < 8; j++) {
            s[j][0] = exp2f(s[j][0] - m0); sum0 += s[j][0];
            s[j][1] = exp2f(s[j][1] - m0); sum0 += s[j][1];
            s[j][2] = exp2f(s[j][2] - m1); sum1 += s[j][2];
            s[j][3] = exp2f(s[j][3] - m1); sum1 += s[j][3];
        }
        sum0 += __shfl_xor_sync(0xffffffffu, sum0, 1);
        sum0 += __shfl_xor_sync(0xffffffffu, sum0, 2);
        sum1 += __shfl_xor_sync(0xffffffffu, sum1, 1);
        sum1 += __shfl_xor_sync(0xffffffffu, sum1, 2);
        l0 = l0 * alpha0 + sum0;
        l1 = l1 * alpha1 + sum1;

#pragma unroll
        for (int n = 0; n < 10; n++) {
            o[n][0] *= alpha0; o[n][1] *= alpha0;
            o[n][2] *= alpha1; o[n][3] *= alpha1;
        }

        // ---- O += P V, fp16: P rounded (1 term) x V hi/lo (2 terms) ----
#pragma unroll
        for (int t = 0; t < 4; t++) {
            uint32_t ph[4];
            const float* f0 = s[2 * t];
            const float* f1 = s[2 * t + 1];
            ph[0] = pack_f16(f0[0], f0[1]);
            ph[1] = pack_f16(f0[2], f0[3]);
            ph[2] = pack_f16(f1[0], f1[1]);
            ph[3] = pack_f16(f1[2], f1[3]);
#pragma unroll
            for (int v = 0; v < 5; v++) {
                uint32_t vh[4], vl[4];
                const uint32_t vd = sb + AV_HI + (t * 16 + v_row) * ARB +
                                    (v * 16 + v_cof) * 2;
                ldm_x4_t(vh, vd);
                ldm_x4_t(vl, vd + AKV_BYTES);
                mma16816h(o[2 * v + 0], ph, &vh[0]);
                mma16816h(o[2 * v + 1], ph, &vh[2]);
                mma16816h(o[2 * v + 0], ph, &vl[0]);
                mma16816h(o[2 * v + 1], ph, &vl[2]);
            }
        }
    }

    // ---- epilogue: o/l -> hi/lo bf16 -> g_ahi/g_alo ----
    const float li0 = 1.f / l0, li1 = 1.f / l1;
    const int r0 = t0 + wid * 16 + (lane >> 2);
    const size_t colb = h * HD + 2 * (lane & 3);
#pragma unroll
    for (int n = 0; n < 10; n++) {
        const float f00 = o[n][0] * li0, f01 = o[n][1] * li0;
        const float f10 = o[n][2] * li1, f11 = o[n][3] * li1;
        __nv_bfloat16 h00, l00, h01, l01, h10, l10, h11, l11;
        split_hilo(f00, h00, l00); split_hilo(f01, h01, l01);
        split_hilo(f10, h10, l10); split_hilo(f11, h11, l11);
        const size_t p0 = (size_t)r0 * HID + colb + n * 8;
        const size_t p1 = (size_t)(r0 + 8) * HID + colb + n * 8;
        *(__nv_bfloat162*)(g_ahi + p0) = __nv_bfloat162(h00, h01);
        *(__nv_bfloat162*)(g_alo + p0) = __nv_bfloat162(l00, l01);
        *(__nv_bfloat162*)(g_ahi + p1) = __nv_bfloat162(h10, h11);
        *(__nv_bfloat162*)(g_alo + p1) = __nv_bfloat162(l10, l11);
    }
}

// ---------------------------------------------------------------------------
extern "C" void kernel_launch(void* const* d_in, const int* in_sizes, int n_in,
                              void* d_out, int out_size)
{
    const float* x      = (const float*)d_in[0];
    const float* cosb   = (const float*)d_in[2];
    const float* sinb   = (const float*)d_in[3];
    const float* w_qkv  = (const float*)d_in[4];
    const float* b_qkv  = (const float*)d_in[5];
    const float* w_proj = (const float*)d_in[6];
    const float* b_proj = (const float*)d_in[7];
    float* out = (float*)d_out;

    float* qkv_p;
    __nv_bfloat16 *xhi, *xlo, *wqhi, *wqlo, *wphi, *wplo, *ahi, *alo;
    cudaGetSymbolAddress((void**)&qkv_p, g_qkv);
    cudaGetSymbolAddress((void**)&xhi, g_xhi);
    cudaGetSymbolAddress((void**)&xlo, g_xlo);
    cudaGetSymbolAddress((void**)&wqhi, g_wqhi);
    cudaGetSymbolAddress((void**)&wqlo, g_wqlo);
    cudaGetSymbolAddress((void**)&wphi, g_wphi);
    cudaGetSymbolAddress((void**)&wplo, g_wplo);
    cudaGetSymbolAddress((void**)&ahi, g_ahi);
    cudaGetSymbolAddress((void**)&alo, g_alo);

    cudaFuncSetAttribute(gemm_mma,
                         cudaFuncAttributeMaxDynamicSharedMemorySize, GEMM_SMEM);
    cudaFuncSetAttribute(attn_mma,
                         cudaFuncAttributeMaxDynamicSharedMemorySize, ATTN_SMEM);

    const int n_x = S_LEN * HID;
    const int n_wq = 3 * HID * HID;
    const int n_wp = HID * HID;

    cvt_hilo<<<(n_x / 4 + 255) / 256, 256>>>(x, xhi, xlo, n_x);
    cvt_hilo<<<(n_wq / 4 + 255) / 256, 256>>>(w_qkv, wqhi, wqlo, n_wq);
    cvt_hilo<<<(n_wp / 4 + 255) / 256, 256>>>(w_proj, wphi, wplo, n_wp);

    gemm_mma<<<dim3(3 * HID / GBN, S_LEN / GBM), 256, GEMM_SMEM>>>(
        xhi, xlo, wqhi, wqlo, b_qkv, qkv_p, S_LEN, 3 * HID, HID);

    rope_cvt<<<(S_LEN * NH * 40 + 255) / 256, 256>>>(cosb, sinb);

    attn_mma<<<dim3(8, NC * NH), 256, ATTN_SMEM>>>();

    gemm_mma<<<dim3(HID / GBN, S_LEN / GBM), 256, GEMM_SMEM>>>(
        ahi, alo, wphi, wplo, b_proj, out, S_LEN, HID, HID);
}

// round 7
// speedup vs baseline: 4.4328x; 1.2613x over previous
#include <cuda_runtime.h>
#include <cuda_bf16.h>
#include <cuda_fp16.h>
#include <cstdint>
#include <math.h>

#define S_LEN 16384
#define HID 1280
#define NH 16
#define HD 80
#define NC 16
#define CH 1024
#define QKV_STRIDE (3 * HID)   // 3840

// ---------------------------------------------------------------------------
// Scratch (no cudaMalloc allowed)
// ---------------------------------------------------------------------------
__device__ float g_qkv[(size_t)S_LEN * 3 * HID];   // [S, 3, NH, HD] fp32

// GEMM operands: activations rounded fp16 (single), weights split fp16 hi/lo
__device__ __align__(256) __half g_xf[(size_t)S_LEN * HID];
__device__ __align__(256) __half g_wqh[(size_t)3 * HID * HID];
__device__ __align__(256) __half g_wql[(size_t)3 * HID * HID];
__device__ __align__(256) __half g_wph[(size_t)HID * HID];
__device__ __align__(256) __half g_wpl[(size_t)HID * HID];
// attention inputs: q/k bf16 hi/lo (q pre-scaled by 1/sqrt(80)*log2e),
// v fp16 hi/lo (PV runs in fp16, 2-term)
__device__ __align__(256) __nv_bfloat16 g_qhi[(size_t)S_LEN * HID];
__device__ __align__(256) __nv_bfloat16 g_qlo[(size_t)S_LEN * HID];
__device__ __align__(256) __nv_bfloat16 g_khi[(size_t)S_LEN * HID];
__device__ __align__(256) __nv_bfloat16 g_klo[(size_t)S_LEN * HID];
__device__ __align__(256) __half       g_vhi[(size_t)S_LEN * HID];
__device__ __align__(256) __half       g_vlo[(size_t)S_LEN * HID];
// attention output = proj GEMM activation (fp16, rounded)
__device__ __align__(256) __half g_af[(size_t)S_LEN * HID];

// ---------------------------------------------------------------------------
// helpers (sm_80-era instructions only — harness compiles for plain sm_103)
// ---------------------------------------------------------------------------
__device__ __forceinline__ uint32_t smem_u32(const void* p) {
    uint32_t a;
    asm("{ .reg .u64 t; cvta.to.shared.u64 t, %1; cvt.u32.u64 %0, t; }"
        : "=r"(a) : "l"(p));
    return a;
}

__device__ __forceinline__ void cpa16(uint32_t dst, const void* src) {
    asm volatile("cp.async.cg.shared.global [%0], [%1], 16;\n"
                 :: "r"(dst), "l"(src));
}
__device__ __forceinline__ void cpa_commit() {
    asm volatile("cp.async.commit_group;\n" ::: "memory");
}
template <int N>
__device__ __forceinline__ void cpa_wait() {
    asm volatile("cp.async.wait_group %0;\n" :: "n"(N) : "memory");
}

__device__ __forceinline__ void ldm_x4(uint32_t* r, uint32_t addr) {
    asm volatile("ldmatrix.sync.aligned.m8n8.x4.shared.b16 {%0,%1,%2,%3}, [%4];"
                 : "=r"(r[0]), "=r"(r[1]), "=r"(r[2]), "=r"(r[3])
                 : "r"(addr));
}
__device__ __forceinline__ void ldm_x4_t(uint32_t* r, uint32_t addr) {
    asm volatile(
        "ldmatrix.sync.aligned.m8n8.x4.trans.shared.b16 {%0,%1,%2,%3}, [%4];"
        : "=r"(r[0]), "=r"(r[1]), "=r"(r[2]), "=r"(r[3])
        : "r"(addr));
}

// bf16 mma, fp32 accumulate
__device__ __forceinline__ void mma16816(float* d, const uint32_t* a,
                                         const uint32_t* b) {
    asm volatile(
        "mma.sync.aligned.m16n8k16.row.col.f32.bf16.bf16.f32 "
        "{%0,%1,%2,%3}, {%4,%5,%6,%7}, {%8,%9}, {%0,%1,%2,%3};"
        : "+f"(d[0]), "+f"(d[1]), "+f"(d[2]), "+f"(d[3])
        : "r"(a[0]), "r"(a[1]), "r"(a[2]), "r"(a[3]), "r"(b[0]), "r"(b[1]));
}
// fp16 mma, fp32 accumulate
__device__ __forceinline__ void mma16816h(float* d, const uint32_t* a,
                                          const uint32_t* b) {
    asm volatile(
        "mma.sync.aligned.m16n8k16.row.col.f32.f16.f16.f32 "
        "{%0,%1,%2,%3}, {%4,%5,%6,%7}, {%8,%9}, {%0,%1,%2,%3};"
        : "+f"(d[0]), "+f"(d[1]), "+f"(d[2]), "+f"(d[3])
        : "r"(a[0]), "r"(a[1]), "r"(a[2]), "r"(a[3]), "r"(b[0]), "r"(b[1]));
}

__device__ __forceinline__ uint32_t pack_f16(float lo, float hi) {
    uint32_t d;
    asm("cvt.rn.f16x2.f32 %0, %1, %2;" : "=r"(d) : "f"(hi), "f"(lo));
    return d;
}

__device__ __forceinline__ void split_hilo(float f, __nv_bfloat16& h,
                                           __nv_bfloat16& l) {
    h = __float2bfloat16(f);
    l = __float2bfloat16(f - __bfloat162float(h));
}
__device__ __forceinline__ void split_hilo_h(float f, __half& h, __half& l) {
    h = __float2half(f);
    l = __float2half(f - __half2float(h));
}

// ---------------------------------------------------------------------------
// conversions
// ---------------------------------------------------------------------------
__global__ void cvt_f16(const float* __restrict__ src,
                        __half* __restrict__ dst, int n)
{
    int i = (blockIdx.x * blockDim.x + threadIdx.x) * 4;
    if (i >= n) return;
    float4 v = *(const float4*)(src + i);
    *(__half2*)(dst + i)     = __floats2half2_rn(v.x, v.y);
    *(__half2*)(dst + i + 2) = __floats2half2_rn(v.z, v.w);
}

__global__ void cvt_hilo_f16(const float* __restrict__ src,
                             __half* __restrict__ hi,
                             __half* __restrict__ lo, int n)
{
    int i = (blockIdx.x * blockDim.x + threadIdx.x) * 4;
    if (i >= n) return;
    float4 v = *(const float4*)(src + i);
    float f[4] = {v.x, v.y, v.z, v.w};
    __half h[4], l[4];
#pragma unroll
    for (int j = 0; j < 4; j++) split_hilo_h(f[j], h[j], l[j]);
    *(__half2*)(hi + i)     = __half2(h[0], h[1]);
    *(__half2*)(hi + i + 2) = __half2(h[2], h[3]);
    *(__half2*)(lo + i)     = __half2(l[0], l[1]);
    *(__half2*)(lo + i + 2) = __half2(l[2], l[3]);
}

// ---------------------------------------------------------------------------
// fp16 2-term GEMM: C[M,N] = Af[M,K] @ (Bh+Bl)[N,K]^T + bias[N]
// Block 128x128, K-chunk 32, 8 warps (4M x 2N), warp tile 32x64.
// Single __syncthreads per K-iter; prefetch issued post-barrier.
// ---------------------------------------------------------------------------
#define GBM 128
#define GBN 128
#define GBK 32
#define ROWB 80
#define MAT_BYTES (128 * ROWB)        // 10240
#define SM_AF 0
#define SM_BH (1 * MAT_BYTES)
#define SM_BL (2 * MAT_BYTES)
#define STG_BYTES (3 * MAT_BYTES)     // 30720
#define GEMM_SMEM (2 * STG_BYTES)     // 61440

__global__ __launch_bounds__(256, 2)
void gemm_mma(const __half* __restrict__ Af,
              const __half* __restrict__ Bh,
              const __half* __restrict__ Bl,
              const float* __restrict__ bias, float* __restrict__ C,
              int M, int N, int K)
{
    extern __shared__ char dsm[];
    const uint32_t sbase = smem_u32(dsm);

    const int tid  = threadIdx.x;
    const int lane = tid & 31;
    const int wid  = tid >> 5;
    const int wm   = wid & 3;
    const int wn   = wid >> 2;
    const int bm   = blockIdx.y * GBM;
    const int bn   = blockIdx.x * GBN;
    const int NK   = K / GBK;

    float acc[2][8][4];
#pragma unroll
    for (int i = 0; i < 2; i++)
#pragma unroll
        for (int j = 0; j < 8; j++)
#pragma unroll
            for (int c = 0; c < 4; c++) acc[i][j][c] = 0.f;

    auto load_stage = [&](int k0, int s) {
        const uint32_t sb = sbase + s * STG_BYTES;
#pragma unroll
        for (int i = 0; i < 2; i++) {
            const int c   = tid + i * 256;
            const int row = c >> 2, j = c & 3;
            const uint32_t off = (uint32_t)(row * ROWB + j * 16);
            const size_t ga = (size_t)(bm + row) * K + k0 + j * 8;
            const size_t gb = (size_t)(bn + row) * K + k0 + j * 8;
            cpa16(sb + SM_AF + off, Af + ga);
            cpa16(sb + SM_BH + off, Bh + gb);
            cpa16(sb + SM_BL + off, Bl + gb);
        }
        cpa_commit();
    };

    load_stage(0, 0);

    const int a_row = (lane & 15);
    const int a_kof = (lane >> 4) << 3;
    const int b_nof = (lane & 7) + ((lane >> 4) << 3);
    const int b_kof = ((lane >> 3) & 1) << 3;

    for (int k = 0; k < NK; k++) {
        cpa_wait<0>();                          // stage k landed
        __syncthreads();                        // visibility + WAR barrier
        if (k + 1 < NK) load_stage((k + 1) * GBK, (k + 1) & 1);

        const uint32_t sb = sbase + (k & 1) * STG_BYTES;
#pragma unroll
        for (int kk = 0; kk < GBK; kk += 16) {
            uint32_t af[2][4];
#pragma unroll
            for (int mf = 0; mf < 2; mf++) {
                const uint32_t ad = sb + SM_AF +
                    (wm * 32 + mf * 16 + a_row) * ROWB + (kk + a_kof) * 2;
                ldm_x4(af[mf], ad);
            }
#pragma unroll
            for (int j = 0; j < 4; j++) {
                uint32_t b_hi[4], b_lo[4];
                const uint32_t bd = sb + SM_BH +
                    (wn * 64 + j * 16 + b_nof) * ROWB + (kk + b_kof) * 2;
                ldm_x4(b_hi, bd);
                ldm_x4(b_lo, bd + MAT_BYTES);
#pragma unroll
                for (int mf = 0; mf < 2; mf++) {
                    mma16816h(acc[mf][2 * j + 0], af[mf], &b_hi[0]);
                    mma16816h(acc[mf][2 * j + 1], af[mf], &b_hi[2]);
                    mma16816h(acc[mf][2 * j + 0], af[mf], &b_lo[0]);
                    mma16816h(acc[mf][2 * j + 1], af[mf], &b_lo[2]);
                }
            }
        }
    }

#pragma unroll
    for (int mf = 0; mf < 2; mf++) {
        const int r0 = bm + wm * 32 + mf * 16 + (lane >> 2);
#pragma unroll
        for (int nf = 0; nf < 8; nf++) {
            const int c0 = bn + wn * 64 + nf * 8 + (lane & 3) * 2;
            const float b0 = bias[c0], b1 = bias[c0 + 1];
            float2 v0 = {acc[mf][nf][0] + b0, acc[mf][nf][1] + b1};
            float2 v1 = {acc[mf][nf][2] + b0, acc[mf][nf][3] + b1};
            *(float2*)(C + (size_t)r0 * N + c0) = v0;
            *(float2*)(C + (size_t)(r0 + 8) * N + c0) = v1;
        }
    }
}

// ---------------------------------------------------------------------------
// RoPE + conversion: q,k -> bf16 hi/lo (q pre-scaled into log2 domain),
// v -> fp16 hi/lo.
// ---------------------------------------------------------------------------
#define QSCALE 0.16130856f   // 0.11180339887 * 1.44269504089

__global__ void rope_cvt(const float* __restrict__ cosb,
                         const float* __restrict__ sinb)
{
    int idx = blockIdx.x * blockDim.x + threadIdx.x;
    if (idx >= S_LEN * NH * 40) return;
    const int d = idx % 40;
    const int h = (idx / 40) % NH;
    const int t = idx / (40 * NH);

    const float c0 = cosb[t * HD + d];
    const float c1 = cosb[t * HD + d + 40];
    const float s0 = sinb[t * HD + d];
    const float s1 = sinb[t * HD + d + 40];

    const size_t base = (size_t)t * QKV_STRIDE + h * HD;
    const float q0 = g_qkv[base + d],            q1 = g_qkv[base + d + 40];
    const float k0 = g_qkv[base + HID + d],      k1 = g_qkv[base + HID + d + 40];
    const float v0 = g_qkv[base + 2 * HID + d],  v1 = g_qkv[base + 2 * HID + d + 40];

    const float qr0 = (q0 * c0 - q1 * s0) * QSCALE;
    const float qr1 = (q1 * c1 + q0 * s1) * QSCALE;
    const float kr0 = k0 * c0 - k1 * s0;
    const float kr1 = k1 * c1 + k0 * s1;

    const size_t o = (size_t)t * HID + h * HD + d;
    __nv_bfloat16 hh, ll;
    __half hf, lf;
    split_hilo(qr0, hh, ll); g_qhi[o] = hh;      g_qlo[o] = ll;
    split_hilo(qr1, hh, ll); g_qhi[o + 40] = hh; g_qlo[o + 40] = ll;
    split_hilo(kr0, hh, ll); g_khi[o] = hh;      g_klo[o] = ll;
    split_hilo(kr1, hh, ll); g_khi[o + 40] = hh; g_klo[o + 40] = ll;
    split_hilo_h(v0, hf, lf); g_vhi[o] = hf;      g_vlo[o] = lf;
    split_hilo_h(v1, hf, lf); g_vhi[o + 40] = hf; g_vlo[o + 40] = lf;
}

// ---------------------------------------------------------------------------
// HMMA flash attention. CTA = (chunk, head, 128 q rows); 8 warps x 16 rows.
// 3-stage cp.async KV pipeline, single sync per iter, S + state in regs.
// QK^T: bf16 3-term split.  PV: fp16, P rounded (1 term) x V hi/lo (2 terms).
// Epilogue writes fp16 (rounded) proj-GEMM activation.
// ---------------------------------------------------------------------------
#define ARB 176                         // bytes per smem row
#define AQ_BYTES (128 * ARB)            // 22528
#define AKV_BYTES (64 * ARB)            // 11264
#define A_STG (4 * AKV_BYTES)           // 45056
#define ATTN_SMEM (2 * AQ_BYTES + 3 * A_STG)   // 180224
#define AK_HI 0
#define AK_LO (1 * AKV_BYTES)
#define AV_HI (2 * AKV_BYTES)
#define AV_LO (3 * AKV_BYTES)

__global__ __launch_bounds__(256, 1)
void attn_mma()
{
    extern __shared__ char dsm[];
    const uint32_t sbase = smem_u32(dsm);
    const uint32_t SQH = sbase;
    const uint32_t SQL = sbase + AQ_BYTES;
    const uint32_t SKV0 = sbase + 2 * AQ_BYTES;

    const int tid  = threadIdx.x;
    const int lane = tid & 31;
    const int wid  = tid >> 5;
    const int nc = blockIdx.y >> 4;
    const int h  = blockIdx.y & 15;
    const int t0 = nc * CH + blockIdx.x * 128;

    const int a_row = (lane & 15);
    const int a_kof = (lane >> 4) << 3;
    const int b_nof = (lane & 7) + ((lane >> 4) << 3);
    const int b_kof = ((lane >> 3) & 1) << 3;
    const int v_row = (lane & 15);
    const int v_cof = (lane >> 4) << 3;

    // Q loads (folded into group 0 with KV stage 0)
    for (int i = tid; i < 1280; i += 256) {
        const int r = i / 10, c = i % 10;
        const uint32_t off = (uint32_t)(r * ARB + c * 16);
        const size_t src = (size_t)(t0 + r) * HID + h * HD + c * 8;
        cpa16(SQH + off, g_qhi + src);
        cpa16(SQL + off, g_qlo + src);
    }
    auto load_kv = [&](int kb, int s) {
        const uint32_t sb = SKV0 + s * A_STG;
        for (int i = tid; i < 640; i += 256) {
            const int r = i / 10, c = i % 10;
            const uint32_t off = (uint32_t)(r * ARB + c * 16);
            const size_t src = (size_t)(nc * CH + kb * 64 + r) * HID + h * HD + c * 8;
            cpa16(sb + AK_HI + off, g_khi + src);
            cpa16(sb + AK_LO + off, g_klo + src);
            cpa16(sb + AV_HI + off, g_vhi + src);
            cpa16(sb + AV_LO + off, g_vlo + src);
        }
        cpa_commit();
    };
    load_kv(0, 0);       // group 0 (Q + KV0)
    load_kv(1, 1);       // group 1

    float o[10][4];
#pragma unroll
    for (int n = 0; n < 10; n++)
#pragma unroll
        for (int c = 0; c < 4; c++) o[n][c] = 0.f;
    float m0 = -1e30f, m1 = -1e30f, l0 = 0.f, l1 = 0.f;

    for (int kb = 0; kb < 16; kb++) {
        if (kb < 14) cpa_wait<1>(); else cpa_wait<0>();
        __syncthreads();
        if (kb + 2 < 16) load_kv(kb + 2, (kb + 2) % 3);

        const uint32_t sb = SKV0 + (kb % 3) * A_STG;

        // ---- S = Q K^T (3-term split), 64 cols, k=80; log2-domain logits ----
        float s[8][4];
#pragma unroll
        for (int j = 0; j < 8; j++)
#pragma unroll
            for (int c = 0; c < 4; c++) s[j][c] = 0.f;

#pragma unroll
        for (int kt = 0; kt < 5; kt++) {
            uint32_t ah[4], al[4];
            const uint32_t ad = SQH + (wid * 16 + a_row) * ARB +
                                (kt * 16 + a_kof) * 2;
            ldm_x4(ah, ad);
            ldm_x4(al, ad + (SQL - SQH));
#pragma unroll
            for (int g = 0; g < 4; g++) {
                uint32_t bh[4], bl[4];
                const uint32_t bd = sb + AK_HI + (g * 16 + b_nof) * ARB +
                                    (kt * 16 + b_kof) * 2;
                ldm_x4(bh, bd);
                ldm_x4(bl, bd + AKV_BYTES);
                mma16816(s[2 * g + 0], ah, &bh[0]);
                mma16816(s[2 * g + 1], ah, &bh[2]);
                mma16816(s[2 * g + 0], ah, &bl[0]);
                mma16816(s[2 * g + 1], ah, &bl[2]);
                mma16816(s[2 * g + 0], al, &bh[0]);
                mma16816(s[2 * g + 1], al, &bh[2]);
            }
        }

        // ---- online softmax (log2 domain) ----
        float mb0 = -1e30f, mb1 = -1e30f;
#pragma unroll
        for (int j = 0; j < 8; j++) {
            mb0 = fmaxf(mb0, fmaxf(s[j][0], s[j][1]));
            mb1 = fmaxf(mb1, fmaxf(s[j][2], s[j][3]));
        }
        mb0 = fmaxf(mb0, __shfl_xor_sync(0xffffffffu, mb0, 1));
        mb0 = fmaxf(mb0, __shfl_xor_sync(0xffffffffu, mb0, 2));
        mb1 = fmaxf(mb1, __shfl_xor_sync(0xffffffffu, mb1, 1));
        mb1 = fmaxf(mb1, __shfl_xor_sync(0xffffffffu, mb1, 2));

        const float mn0 = fmaxf(m0, mb0), mn1 = fmaxf(m1, mb1);
        const float alpha0 = exp2f(m0 - mn0);
        const float alpha1 = exp2f(m1 - mn1);
        m0 = mn0; m1 = mn1;

        float sum0 = 0.f, sum1 = 0.f;
#pragma unroll
        for (int j = 0; j < 8; j++) {
            s[j][0] = exp2f(s[j][0] - m0); sum0 += s[j][0];
            s[j][1] = exp2f(s[j][1] - m0); sum0 += s[j][1];
            s[j][2] = exp2f(s[j][2] - m1); sum1 += s[j][2];
            s[j][3] = exp2f(s[j][3] - m1); sum1 += s[j][3];
        }
        sum0 += __shfl_xor_sync(0xffffffffu, sum0, 1);
        sum0 += __shfl_xor_sync(0xffffffffu, sum0, 2);
        sum1 += __shfl_xor_sync(0xffffffffu, sum1, 1);
        sum1 += __shfl_xor_sync(0xffffffffu, sum1, 2);
        l0 = l0 * alpha0 + sum0;
        l1 = l1 * alpha1 + sum1;

#pragma unroll
        for (int n = 0; n < 10; n++) {
            o[n][0] *= alpha0; o[n][1] *= alpha0;
            o[n][2] *= alpha1; o[n][3] *= alpha1;
        }

        // ---- O += P V, fp16: P rounded (1 term) x V hi/lo (2 terms) ----
#pragma unroll
        for (int t = 0; t < 4; t++) {
            uint32_t ph[4];
            const float* f0 = s[2 * t];
            const float* f1 = s[2 * t + 1];
            ph[0] = pack_f16(f0[0], f0[1]);
            ph[1] = pack_f16(f0[2], f0[3]);
            ph[2] = pack_f16(f1[0], f1[1]);
            ph[3] = pack_f16(f1[2], f1[3]);
#pragma unroll
            for (int v = 0; v < 5; v++) {
                uint32_t vh[4], vl[4];
                const uint32_t vd = sb + AV_HI + (t * 16 + v_row) * ARB +
                                    (v * 16 + v_cof) * 2;
                ldm_x4_t(vh, vd);
                ldm_x4_t(vl, vd + AKV_BYTES);
                mma16816h(o[2 * v + 0], ph, &vh[0]);
                mma16816h(o[2 * v + 1], ph, &vh[2]);
                mma16816h(o[2 * v + 0], ph, &vl[0]);
                mma16816h(o[2 * v + 1], ph, &vl[2]);
            }
        }
    }

    // ---- epilogue: o/l -> fp16 -> g_af (proj activation) ----
    const float li0 = 1.f / l0, li1 = 1.f / l1;
    const int r0 = t0 + wid * 16 + (lane >> 2);
    const size_t colb = h * HD + 2 * (lane & 3);
#pragma unroll
    for (int n = 0; n < 10; n++) {
        const size_t p0 = (size_t)r0 * HID + colb + n * 8;
        const size_t p1 = (size_t)(r0 + 8) * HID + colb + n * 8;
        *(__half2*)(g_af + p0) = __floats2half2_rn(o[n][0] * li0, o[n][1] * li0);
        *(__half2*)(g_af + p1) = __floats2half2_rn(o[n][2] * li1, o[n][3] * li1);
    }
}

// ---------------------------------------------------------------------------
extern "C" void kernel_launch(void* const* d_in, const int* in_sizes, int n_in,
                              void* d_out, int out_size)
{
    const float* x      = (const float*)d_in[0];
    const float* cosb   = (const float*)d_in[2];
    const float* sinb   = (const float*)d_in[3];
    const float* w_qkv  = (const float*)d_in[4];
    const float* b_qkv  = (const float*)d_in[5];
    const float* w_proj = (const float*)d_in[6];
    const float* b_proj = (const float*)d_in[7];
    float* out = (float*)d_out;

    float* qkv_p;
    __half *xf, *wqh, *wql, *wph, *wpl, *af;
    cudaGetSymbolAddress((void**)&qkv_p, g_qkv);
    cudaGetSymbolAddress((void**)&xf, g_xf);
    cudaGetSymbolAddress((void**)&wqh, g_wqh);
    cudaGetSymbolAddress((void**)&wql, g_wql);
    cudaGetSymbolAddress((void**)&wph, g_wph);
    cudaGetSymbolAddress((void**)&wpl, g_wpl);
    cudaGetSymbolAddress((void**)&af, g_af);

    cudaFuncSetAttribute(gemm_mma,
                         cudaFuncAttributeMaxDynamicSharedMemorySize, GEMM_SMEM);
    cudaFuncSetAttribute(attn_mma,
                         cudaFuncAttributeMaxDynamicSharedMemorySize, ATTN_SMEM);

    const int n_x = S_LEN * HID;
    const int n_wq = 3 * HID * HID;
    const int n_wp = HID * HID;

    cvt_f16<<<(n_x / 4 + 255) / 256, 256>>>(x, xf, n_x);
    cvt_hilo_f16<<<(n_wq / 4 + 255) / 256, 256>>>(w_qkv, wqh, wql, n_wq);
    cvt_hilo_f16<<<(n_wp / 4 + 255) / 256, 256>>>(w_proj, wph, wpl, n_wp);

    gemm_mma<<<dim3(3 * HID / GBN, S_LEN / GBM), 256, GEMM_SMEM>>>(
        xf, wqh, wql, b_qkv, qkv_p, S_LEN, 3 * HID, HID);

    rope_cvt<<<(S_LEN * NH * 40 + 255) / 256, 256>>>(cosb, sinb);

    attn_mma<<<dim3(8, NC * NH), 256, ATTN_SMEM>>>();

    gemm_mma<<<dim3(HID / GBN, S_LEN / GBM), 256, GEMM_SMEM>>>(
        af, wph, wpl, b_proj, out, S_LEN, HID, HID);
}

// round 8
// speedup vs baseline: 4.6283x; 1.0441x over previous
#include <cuda_runtime.h>
#include <cuda_bf16.h>
#include <cuda_fp16.h>
#include <cstdint>
#include <math.h>

#define S_LEN 16384
#define HID 1280
#define NH 16
#define HD 80
#define NC 16
#define CH 1024
#define QKV_STRIDE (3 * HID)   // 3840

// ---------------------------------------------------------------------------
// Scratch (no cudaMalloc allowed)
// ---------------------------------------------------------------------------
__device__ float g_qkv[(size_t)S_LEN * 3 * HID];   // [S, 3, NH, HD] fp32

// GEMM operands: activations rounded fp16 (single), weights split fp16 hi/lo
__device__ __align__(256) __half g_xf[(size_t)S_LEN * HID];
__device__ __align__(256) __half g_wqh[(size_t)3 * HID * HID];
__device__ __align__(256) __half g_wql[(size_t)3 * HID * HID];
__device__ __align__(256) __half g_wph[(size_t)HID * HID];
__device__ __align__(256) __half g_wpl[(size_t)HID * HID];
// attention inputs (all fp16): q rounded single (pre-scaled by 1/sqrt(80)*log2e),
// k hi/lo, v hi/lo
__device__ __align__(256) __half g_qf[(size_t)S_LEN * HID];
__device__ __align__(256) __half g_khi[(size_t)S_LEN * HID];
__device__ __align__(256) __half g_klo[(size_t)S_LEN * HID];
__device__ __align__(256) __half g_vhi[(size_t)S_LEN * HID];
__device__ __align__(256) __half g_vlo[(size_t)S_LEN * HID];
// attention output = proj GEMM activation (fp16, rounded)
__device__ __align__(256) __half g_af[(size_t)S_LEN * HID];

// ---------------------------------------------------------------------------
// helpers (sm_80-era instructions only — harness compiles for plain sm_103)
// ---------------------------------------------------------------------------
__device__ __forceinline__ uint32_t smem_u32(const void* p) {
    uint32_t a;
    asm("{ .reg .u64 t; cvta.to.shared.u64 t, %1; cvt.u32.u64 %0, t; }"
        : "=r"(a) : "l"(p));
    return a;
}

__device__ __forceinline__ void cpa16(uint32_t dst, const void* src) {
    asm volatile("cp.async.cg.shared.global [%0], [%1], 16;\n"
                 :: "r"(dst), "l"(src));
}
__device__ __forceinline__ void cpa_commit() {
    asm volatile("cp.async.commit_group;\n" ::: "memory");
}
template <int N>
__device__ __forceinline__ void cpa_wait() {
    asm volatile("cp.async.wait_group %0;\n" :: "n"(N) : "memory");
}

__device__ __forceinline__ void ldm_x4(uint32_t* r, uint32_t addr) {
    asm volatile("ldmatrix.sync.aligned.m8n8.x4.shared.b16 {%0,%1,%2,%3}, [%4];"
                 : "=r"(r[0]), "=r"(r[1]), "=r"(r[2]), "=r"(r[3])
                 : "r"(addr));
}
__device__ __forceinline__ void ldm_x4_t(uint32_t* r, uint32_t addr) {
    asm volatile(
        "ldmatrix.sync.aligned.m8n8.x4.trans.shared.b16 {%0,%1,%2,%3}, [%4];"
        : "=r"(r[0]), "=r"(r[1]), "=r"(r[2]), "=r"(r[3])
        : "r"(addr));
}

// fp16 mma, fp32 accumulate
__device__ __forceinline__ void mma16816h(float* d, const uint32_t* a,
                                          const uint32_t* b) {
    asm volatile(
        "mma.sync.aligned.m16n8k16.row.col.f32.f16.f16.f32 "
        "{%0,%1,%2,%3}, {%4,%5,%6,%7}, {%8,%9}, {%0,%1,%2,%3};"
        : "+f"(d[0]), "+f"(d[1]), "+f"(d[2]), "+f"(d[3])
        : "r"(a[0]), "r"(a[1]), "r"(a[2]), "r"(a[3]), "r"(b[0]), "r"(b[1]));
}

__device__ __forceinline__ uint32_t pack_f16(float lo, float hi) {
    uint32_t d;
    asm("cvt.rn.f16x2.f32 %0, %1, %2;" : "=r"(d) : "f"(hi), "f"(lo));
    return d;
}

__device__ __forceinline__ void split_hilo_h(float f, __half& h, __half& l) {
    h = __float2half(f);
    l = __float2half(f - __half2float(h));
}

// ---------------------------------------------------------------------------
// conversions
// ---------------------------------------------------------------------------
__global__ void cvt_f16(const float* __restrict__ src,
                        __half* __restrict__ dst, int n)
{
    int i = (blockIdx.x * blockDim.x + threadIdx.x) * 4;
    if (i >= n) return;
    float4 v = *(const float4*)(src + i);
    *(__half2*)(dst + i)     = __floats2half2_rn(v.x, v.y);
    *(__half2*)(dst + i + 2) = __floats2half2_rn(v.z, v.w);
}

__global__ void cvt_hilo_f16(const float* __restrict__ src,
                             __half* __restrict__ hi,
                             __half* __restrict__ lo, int n)
{
    int i = (blockIdx.x * blockDim.x + threadIdx.x) * 4;
    if (i >= n) return;
    float4 v = *(const float4*)(src + i);
    float f[4] = {v.x, v.y, v.z, v.w};
    __half h[4], l[4];
#pragma unroll
    for (int j = 0; j < 4; j++) split_hilo_h(f[j], h[j], l[j]);
    *(__half2*)(hi + i)     = __half2(h[0], h[1]);
    *(__half2*)(hi + i + 2) = __half2(h[2], h[3]);
    *(__half2*)(lo + i)     = __half2(l[0], l[1]);
    *(__half2*)(lo + i + 2) = __half2(l[2], l[3]);
}

// ---------------------------------------------------------------------------
// fp16 2-term GEMM: C[M,N] = Af[M,K] @ (Bh+Bl)[N,K]^T + bias[N]
// Block 128x128, K-chunk 32, 8 warps (4M x 2N), warp tile 32x64.
// 3-stage cp.async pipeline, single __syncthreads per K-iter.
// ---------------------------------------------------------------------------
#define GBM 128
#define GBN 128
#define GBK 32
#define ROWB 80
#define MAT_BYTES (128 * ROWB)        // 10240
#define SM_AF 0
#define SM_BH (1 * MAT_BYTES)
#define SM_BL (2 * MAT_BYTES)
#define STG_BYTES (3 * MAT_BYTES)     // 30720
#define GEMM_SMEM (3 * STG_BYTES)     // 92160

__global__ __launch_bounds__(256, 2)
void gemm_mma(const __half* __restrict__ Af,
              const __half* __restrict__ Bh,
              const __half* __restrict__ Bl,
              const float* __restrict__ bias, float* __restrict__ C,
              int M, int N, int K)
{
    extern __shared__ char dsm[];
    const uint32_t sbase = smem_u32(dsm);

    const int tid  = threadIdx.x;
    const int lane = tid & 31;
    const int wid  = tid >> 5;
    const int wm   = wid & 3;
    const int wn   = wid >> 2;
    const int bm   = blockIdx.y * GBM;
    const int bn   = blockIdx.x * GBN;
    const int NK   = K / GBK;

    float acc[2][8][4];
#pragma unroll
    for (int i = 0; i < 2; i++)
#pragma unroll
        for (int j = 0; j < 8; j++)
#pragma unroll
            for (int c = 0; c < 4; c++) acc[i][j][c] = 0.f;

    auto load_stage = [&](int k0, int s) {
        const uint32_t sb = sbase + s * STG_BYTES;
#pragma unroll
        for (int i = 0; i < 2; i++) {
            const int c   = tid + i * 256;
            const int row = c >> 2, j = c & 3;
            const uint32_t off = (uint32_t)(row * ROWB + j * 16);
            const size_t ga = (size_t)(bm + row) * K + k0 + j * 8;
            const size_t gb = (size_t)(bn + row) * K + k0 + j * 8;
            cpa16(sb + SM_AF + off, Af + ga);
            cpa16(sb + SM_BH + off, Bh + gb);
            cpa16(sb + SM_BL + off, Bl + gb);
        }
        cpa_commit();
    };

    load_stage(0, 0);
    load_stage(GBK, 1);

    const int a_row = (lane & 15);
    const int a_kof = (lane >> 4) << 3;
    const int b_nof = (lane & 7) + ((lane >> 4) << 3);
    const int b_kof = ((lane >> 3) & 1) << 3;

    for (int k = 0; k < NK; k++) {
        if (k + 1 < NK) cpa_wait<1>(); else cpa_wait<0>();
        __syncthreads();                        // visibility + WAR barrier
        if (k + 2 < NK) load_stage((k + 2) * GBK, (k + 2) % 3);

        const uint32_t sb = sbase + (k % 3) * STG_BYTES;
#pragma unroll
        for (int kk = 0; kk < GBK; kk += 16) {
            uint32_t af[2][4];
#pragma unroll
            for (int mf = 0; mf < 2; mf++) {
                const uint32_t ad = sb + SM_AF +
                    (wm * 32 + mf * 16 + a_row) * ROWB + (kk + a_kof) * 2;
                ldm_x4(af[mf], ad);
            }
#pragma unroll
            for (int j = 0; j < 4; j++) {
                uint32_t b_hi[4], b_lo[4];
                const uint32_t bd = sb + SM_BH +
                    (wn * 64 + j * 16 + b_nof) * ROWB + (kk + b_kof) * 2;
                ldm_x4(b_hi, bd);
                ldm_x4(b_lo, bd + MAT_BYTES);
#pragma unroll
                for (int mf = 0; mf < 2; mf++) {
                    mma16816h(acc[mf][2 * j + 0], af[mf], &b_hi[0]);
                    mma16816h(acc[mf][2 * j + 1], af[mf], &b_hi[2]);
                    mma16816h(acc[mf][2 * j + 0], af[mf], &b_lo[0]);
                    mma16816h(acc[mf][2 * j + 1], af[mf], &b_lo[2]);
                }
            }
        }
    }

#pragma unroll
    for (int mf = 0; mf < 2; mf++) {
        const int r0 = bm + wm * 32 + mf * 16 + (lane >> 2);
#pragma unroll
        for (int nf = 0; nf < 8; nf++) {
            const int c0 = bn + wn * 64 + nf * 8 + (lane & 3) * 2;
            const float b0 = bias[c0], b1 = bias[c0 + 1];
            float2 v0 = {acc[mf][nf][0] + b0, acc[mf][nf][1] + b1};
            float2 v1 = {acc[mf][nf][2] + b0, acc[mf][nf][3] + b1};
            *(float2*)(C + (size_t)r0 * N + c0) = v0;
            *(float2*)(C + (size_t)(r0 + 8) * N + c0) = v1;
        }
    }
}

// ---------------------------------------------------------------------------
// RoPE + conversion: q -> fp16 single (pre-scaled into log2 domain),
// k -> fp16 hi/lo, v -> fp16 hi/lo.
// ---------------------------------------------------------------------------
#define QSCALE 0.16130856f   // 0.11180339887 * 1.44269504089

__global__ void rope_cvt(const float* __restrict__ cosb,
                         const float* __restrict__ sinb)
{
    int idx = blockIdx.x * blockDim.x + threadIdx.x;
    if (idx >= S_LEN * NH * 40) return;
    const int d = idx % 40;
    const int h = (idx / 40) % NH;
    const int t = idx / (40 * NH);

    const float c0 = cosb[t * HD + d];
    const float c1 = cosb[t * HD + d + 40];
    const float s0 = sinb[t * HD + d];
    const float s1 = sinb[t * HD + d + 40];

    const size_t base = (size_t)t * QKV_STRIDE + h * HD;
    const float q0 = g_qkv[base + d],            q1 = g_qkv[base + d + 40];
    const float k0 = g_qkv[base + HID + d],      k1 = g_qkv[base + HID + d + 40];
    const float v0 = g_qkv[base + 2 * HID + d],  v1 = g_qkv[base + 2 * HID + d + 40];

    const float qr0 = (q0 * c0 - q1 * s0) * QSCALE;
    const float qr1 = (q1 * c1 + q0 * s1) * QSCALE;
    const float kr0 = k0 * c0 - k1 * s0;
    const float kr1 = k1 * c1 + k0 * s1;

    const size_t o = (size_t)t * HID + h * HD + d;
    __half hf, lf;
    g_qf[o]      = __float2half(qr0);
    g_qf[o + 40] = __float2half(qr1);
    split_hilo_h(kr0, hf, lf); g_khi[o] = hf;      g_klo[o] = lf;
    split_hilo_h(kr1, hf, lf); g_khi[o + 40] = hf; g_klo[o + 40] = lf;
    split_hilo_h(v0, hf, lf);  g_vhi[o] = hf;      g_vlo[o] = lf;
    split_hilo_h(v1, hf, lf);  g_vhi[o + 40] = hf; g_vlo[o + 40] = lf;
}

// ---------------------------------------------------------------------------
// HMMA flash attention. CTA = (chunk, head, 128 q rows); 8 warps x 16 rows.
// 3-stage cp.async KV pipeline, single sync per iter, S + state in regs.
// QK^T: fp16 2-term (Q rounded x K hi/lo).  PV: fp16 2-term (P rounded x
// V hi/lo).  Epilogue writes fp16 (rounded) proj-GEMM activation.
// ---------------------------------------------------------------------------
#define ARB 176                         // bytes per smem row
#define AQ_BYTES (128 * ARB)            // 22528 (Q fp16, single)
#define AKV_BYTES (64 * ARB)            // 11264
#define A_STG (4 * AKV_BYTES)           // 45056
#define ATTN_SMEM (AQ_BYTES + 3 * A_STG)   // 157696
#define AK_HI 0
#define AK_LO (1 * AKV_BYTES)
#define AV_HI (2 * AKV_BYTES)
#define AV_LO (3 * AKV_BYTES)

__global__ __launch_bounds__(256, 1)
void attn_mma()
{
    extern __shared__ char dsm[];
    const uint32_t sbase = smem_u32(dsm);
    const uint32_t SQ = sbase;
    const uint32_t SKV0 = sbase + AQ_BYTES;

    const int tid  = threadIdx.x;
    const int lane = tid & 31;
    const int wid  = tid >> 5;
    const int nc = blockIdx.y >> 4;
    const int h  = blockIdx.y & 15;
    const int t0 = nc * CH + blockIdx.x * 128;

    const int a_row = (lane & 15);
    const int a_kof = (lane >> 4) << 3;
    const int b_nof = (lane & 7) + ((lane >> 4) << 3);
    const int b_kof = ((lane >> 3) & 1) << 3;
    const int v_row = (lane & 15);
    const int v_cof = (lane >> 4) << 3;

    // Q loads (folded into group 0 with KV stage 0)
    for (int i = tid; i < 1280; i += 256) {
        const int r = i / 10, c = i % 10;
        const uint32_t off = (uint32_t)(r * ARB + c * 16);
        const size_t src = (size_t)(t0 + r) * HID + h * HD + c * 8;
        cpa16(SQ + off, g_qf + src);
    }
    auto load_kv = [&](int kb, int s) {
        const uint32_t sb = SKV0 + s * A_STG;
        for (int i = tid; i < 640; i += 256) {
            const int r = i / 10, c = i % 10;
            const uint32_t off = (uint32_t)(r * ARB + c * 16);
            const size_t src = (size_t)(nc * CH + kb * 64 + r) * HID + h * HD + c * 8;
            cpa16(sb + AK_HI + off, g_khi + src);
            cpa16(sb + AK_LO + off, g_klo + src);
            cpa16(sb + AV_HI + off, g_vhi + src);
            cpa16(sb + AV_LO + off, g_vlo + src);
        }
        cpa_commit();
    };
    load_kv(0, 0);       // group 0 (Q + KV0)
    load_kv(1, 1);       // group 1

    float o[10][4];
#pragma unroll
    for (int n = 0; n < 10; n++)
#pragma unroll
        for (int c = 0; c < 4; c++) o[n][c] = 0.f;
    float m0 = -1e30f, m1 = -1e30f, l0 = 0.f, l1 = 0.f;

    for (int kb = 0; kb < 16; kb++) {
        if (kb < 14) cpa_wait<1>(); else cpa_wait<0>();
        __syncthreads();
        if (kb + 2 < 16) load_kv(kb + 2, (kb + 2) % 3);

        const uint32_t sb = SKV0 + (kb % 3) * A_STG;

        // ---- S = Q K^T (fp16 2-term), 64 cols, k=80; log2-domain logits ----
        float s[8][4];
#pragma unroll
        for (int j = 0; j < 8; j++)
#pragma unroll
            for (int c = 0; c < 4; c++) s[j][c] = 0.f;

#pragma unroll
        for (int kt = 0; kt < 5; kt++) {
            uint32_t af[4];
            const uint32_t ad = SQ + (wid * 16 + a_row) * ARB +
                                (kt * 16 + a_kof) * 2;
            ldm_x4(af, ad);
#pragma unroll
            for (int g = 0; g < 4; g++) {
                uint32_t bh[4], bl[4];
                const uint32_t bd = sb + AK_HI + (g * 16 + b_nof) * ARB +
                                    (kt * 16 + b_kof) * 2;
                ldm_x4(bh, bd);
                ldm_x4(bl, bd + AKV_BYTES);
                mma16816h(s[2 * g + 0], af, &bh[0]);
                mma16816h(s[2 * g + 1], af, &bh[2]);
                mma16816h(s[2 * g + 0], af, &bl[0]);
                mma16816h(s[2 * g + 1], af, &bl[2]);
            }
        }

        // ---- online softmax (log2 domain) ----
        float mb0 = -1e30f, mb1 = -1e30f;
#pragma unroll
        for (int j = 0; j < 8; j++) {
            mb0 = fmaxf(mb0, fmaxf(s[j][0], s[j][1]));
            mb1 = fmaxf(mb1, fmaxf(s[j][2], s[j][3]));
        }
        mb0 = fmaxf(mb0, __shfl_xor_sync(0xffffffffu, mb0, 1));
        mb0 = fmaxf(mb0, __shfl_xor_sync(0xffffffffu, mb0, 2));
        mb1 = fmaxf(mb1, __shfl_xor_sync(0xffffffffu, mb1, 1));
        mb1 = fmaxf(mb1, __shfl_xor_sync(0xffffffffu, mb1, 2));

        const float mn0 = fmaxf(m0, mb0), mn1 = fmaxf(m1, mb1);
        const float alpha0 = exp2f(m0 - mn0);
        const float alpha1 = exp2f(m1 - mn1);
        m0 = mn0; m1 = mn1;

        float sum0 = 0.f, sum1 = 0.f;
#pragma unroll
        for (int j = 0; j < 8; j++) {
            s[j][0] = exp2f(s[j][0] - m0); sum0 += s[j][0];
            s[j][1] = exp2f(s[j][1] - m0); sum0 += s[j][1];
            s[j][2] = exp2f(s[j][2] - m1); sum1 += s[j][2];
            s[j][3] = exp2f(s[j][3] - m1); sum1 += s[j][3];
        }
        sum0 += __shfl_xor_sync(0xffffffffu, sum0, 1);
        sum0 += __shfl_xor_sync(0xffffffffu, sum0, 2);
        sum1 += __shfl_xor_sync(0xffffffffu, sum1, 1);
        sum1 += __shfl_xor_sync(0xffffffffu, sum1, 2);
        l0 = l0 * alpha0 + sum0;
        l1 = l1 * alpha1 + sum1;

#pragma unroll
        for (int n = 0; n < 10; n++) {
            o[n][0] *= alpha0; o[n][1] *= alpha0;
            o[n][2] *= alpha1; o[n][3] *= alpha1;
        }

        // ---- O += P V, fp16: P rounded (1 term) x V hi/lo (2 terms) ----
#pragma unroll
        for (int t = 0; t < 4; t++) {
            uint32_t ph[4];
            const float* f0 = s[2 * t];
            const float* f1 = s[2 * t + 1];
            ph[0] = pack_f16(f0[0], f0[1]);
            ph[1] = pack_f16(f0[2], f0[3]);
            ph[2] = pack_f16(f1[0], f1[1]);
            ph[3] = pack_f16(f1[2], f1[3]);
#pragma unroll
            for (int v = 0; v < 5; v++) {
                uint32_t vh[4], vl[4];
                const uint32_t vd = sb + AV_HI + (t * 16 + v_row) * ARB +
                                    (v * 16 + v_cof) * 2;
                ldm_x4_t(vh, vd);
                ldm_x4_t(vl, vd + AKV_BYTES);
                mma16816h(o[2 * v + 0], ph, &vh[0]);
                mma16816h(o[2 * v + 1], ph, &vh[2]);
                mma16816h(o[2 * v + 0], ph, &vl[0]);
                mma16816h(o[2 * v + 1], ph, &vl[2]);
            }
        }
    }

    // ---- epilogue: o/l -> fp16 -> g_af (proj activation) ----
    const float li0 = 1.f / l0, li1 = 1.f / l1;
    const int r0 = t0 + wid * 16 + (lane >> 2);
    const size_t colb = h * HD + 2 * (lane & 3);
#pragma unroll
    for (int n = 0; n < 10; n++) {
        const size_t p0 = (size_t)r0 * HID + colb + n * 8;
        const size_t p1 = (size_t)(r0 + 8) * HID + colb + n * 8;
        *(__half2*)(g_af + p0) = __floats2half2_rn(o[n][0] * li0, o[n][1] * li0);
        *(__half2*)(g_af + p1) = __floats2half2_rn(o[n][2] * li1, o[n][3] * li1);
    }
}

// ---------------------------------------------------------------------------
extern "C" void kernel_launch(void* const* d_in, const int* in_sizes, int n_in,
                              void* d_out, int out_size)
{
    const float* x      = (const float*)d_in[0];
    const float* cosb   = (const float*)d_in[2];
    const float* sinb   = (const float*)d_in[3];
    const float* w_qkv  = (const float*)d_in[4];
    const float* b_qkv  = (const float*)d_in[5];
    const float* w_proj = (const float*)d_in[6];
    const float* b_proj = (const float*)d_in[7];
    float* out = (float*)d_out;

    float* qkv_p;
    __half *xf, *wqh, *wql, *wph, *wpl, *af;
    cudaGetSymbolAddress((void**)&qkv_p, g_qkv);
    cudaGetSymbolAddress((void**)&xf, g_xf);
    cudaGetSymbolAddress((void**)&wqh, g_wqh);
    cudaGetSymbolAddress((void**)&wql, g_wql);
    cudaGetSymbolAddress((void**)&wph, g_wph);
    cudaGetSymbolAddress((void**)&wpl, g_wpl);
    cudaGetSymbolAddress((void**)&af, g_af);

    cudaFuncSetAttribute(gemm_mma,
                         cudaFuncAttributeMaxDynamicSharedMemorySize, GEMM_SMEM);
    cudaFuncSetAttribute(attn_mma,
                         cudaFuncAttributeMaxDynamicSharedMemorySize, ATTN_SMEM);

    const int n_x = S_LEN * HID;
    const int n_wq = 3 * HID * HID;
    const int n_wp = HID * HID;

    cvt_f16<<<(n_x / 4 + 255) / 256, 256>>>(x, xf, n_x);
    cvt_hilo_f16<<<(n_wq / 4 + 255) / 256, 256>>>(w_qkv, wqh, wql, n_wq);
    cvt_hilo_f16<<<(n_wp / 4 + 255) / 256, 256>>>(w_proj, wph, wpl, n_wp);

    gemm_mma<<<dim3(3 * HID / GBN, S_LEN / GBM), 256, GEMM_SMEM>>>(
        xf, wqh, wql, b_qkv, qkv_p, S_LEN, 3 * HID, HID);

    rope_cvt<<<(S_LEN * NH * 40 + 255) / 256, 256>>>(cosb, sinb);

    attn_mma<<<dim3(8, NC * NH), 256, ATTN_SMEM>>>();

    gemm_mma<<<dim3(HID / GBN, S_LEN / GBM), 256, GEMM_SMEM>>>(
        af, wph, wpl, b_proj, out, S_LEN, HID, HID);
}

// round 9
// speedup vs baseline: 6.4065x; 1.3842x over previous
#include <cuda_runtime.h>
#include <cuda_bf16.h>
#include <cuda_fp16.h>
#include <cstdint>
#include <math.h>

#define S_LEN 16384
#define HID 1280
#define NH 16
#define HD 80
#define NC 16
#define CH 1024
#define QKV_STRIDE (3 * HID)   // 3840

// ---------------------------------------------------------------------------
// Scratch (no cudaMalloc allowed)
// ---------------------------------------------------------------------------
__device__ float g_qkv[(size_t)S_LEN * 3 * HID];   // [S, 3, NH, HD] fp32

// GEMM operands: plain fp16 (both sides rounded)
__device__ __align__(256) __half g_xf[(size_t)S_LEN * HID];
__device__ __align__(256) __half g_wq[(size_t)3 * HID * HID];
__device__ __align__(256) __half g_wp[(size_t)HID * HID];
// attention inputs (all fp16): q rounded single (pre-scaled by 1/sqrt(80)*log2e),
// k hi/lo, v hi/lo
__device__ __align__(256) __half g_qf[(size_t)S_LEN * HID];
__device__ __align__(256) __half g_khi[(size_t)S_LEN * HID];
__device__ __align__(256) __half g_klo[(size_t)S_LEN * HID];
__device__ __align__(256) __half g_vhi[(size_t)S_LEN * HID];
__device__ __align__(256) __half g_vlo[(size_t)S_LEN * HID];
// attention output = proj GEMM activation (fp16, rounded)
__device__ __align__(256) __half g_af[(size_t)S_LEN * HID];

// ---------------------------------------------------------------------------
// helpers (sm_80-era instructions only — harness compiles for plain sm_103)
// ---------------------------------------------------------------------------
__device__ __forceinline__ uint32_t smem_u32(const void* p) {
    uint32_t a;
    asm("{ .reg .u64 t; cvta.to.shared.u64 t, %1; cvt.u32.u64 %0, t; }"
        : "=r"(a) : "l"(p));
    return a;
}

__device__ __forceinline__ void cpa16(uint32_t dst, const void* src) {
    asm volatile("cp.async.cg.shared.global [%0], [%1], 16;\n"
                 :: "r"(dst), "l"(src));
}
__device__ __forceinline__ void cpa_commit() {
    asm volatile("cp.async.commit_group;\n" ::: "memory");
}
template <int N>
__device__ __forceinline__ void cpa_wait() {
    asm volatile("cp.async.wait_group %0;\n" :: "n"(N) : "memory");
}

__device__ __forceinline__ void ldm_x4(uint32_t* r, uint32_t addr) {
    asm volatile("ldmatrix.sync.aligned.m8n8.x4.shared.b16 {%0,%1,%2,%3}, [%4];"
                 : "=r"(r[0]), "=r"(r[1]), "=r"(r[2]), "=r"(r[3])
                 : "r"(addr));
}
__device__ __forceinline__ void ldm_x4_t(uint32_t* r, uint32_t addr) {
    asm volatile(
        "ldmatrix.sync.aligned.m8n8.x4.trans.shared.b16 {%0,%1,%2,%3}, [%4];"
        : "=r"(r[0]), "=r"(r[1]), "=r"(r[2]), "=r"(r[3])
        : "r"(addr));
}

// fp16 mma, fp32 accumulate
__device__ __forceinline__ void mma16816h(float* d, const uint32_t* a,
                                          const uint32_t* b) {
    asm volatile(
        "mma.sync.aligned.m16n8k16.row.col.f32.f16.f16.f32 "
        "{%0,%1,%2,%3}, {%4,%5,%6,%7}, {%8,%9}, {%0,%1,%2,%3};"
        : "+f"(d[0]), "+f"(d[1]), "+f"(d[2]), "+f"(d[3])
        : "r"(a[0]), "r"(a[1]), "r"(a[2]), "r"(a[3]), "r"(b[0]), "r"(b[1]));
}

__device__ __forceinline__ uint32_t pack_f16(float lo, float hi) {
    uint32_t d;
    asm("cvt.rn.f16x2.f32 %0, %1, %2;" : "=r"(d) : "f"(hi), "f"(lo));
    return d;
}

__device__ __forceinline__ void split_hilo_h(float f, __half& h, __half& l) {
    h = __float2half(f);
    l = __float2half(f - __half2float(h));
}

// ---------------------------------------------------------------------------
// conversions
// ---------------------------------------------------------------------------
__global__ void cvt_f16(const float* __restrict__ src,
                        __half* __restrict__ dst, int n)
{
    int i = (blockIdx.x * blockDim.x + threadIdx.x) * 4;
    if (i >= n) return;
    float4 v = *(const float4*)(src + i);
    *(__half2*)(dst + i)     = __floats2half2_rn(v.x, v.y);
    *(__half2*)(dst + i + 2) = __floats2half2_rn(v.z, v.w);
}

// ---------------------------------------------------------------------------
// fp16 GEMM: C[M,N] = Af[M,K] @ Bf[N,K]^T + bias[N]
// Block 128x128, K-chunk 32, 8 warps (4M x 2N), warp tile 32x64.
// 3-stage cp.async pipeline, single __syncthreads per K-iter.
// ---------------------------------------------------------------------------
#define GBM 128
#define GBN 128
#define GBK 32
#define ROWB 80
#define MAT_BYTES (128 * ROWB)        // 10240
#define SM_AF 0
#define SM_BF (1 * MAT_BYTES)
#define STG_BYTES (2 * MAT_BYTES)     // 20480
#define GEMM_SMEM (3 * STG_BYTES)     // 61440

__global__ __launch_bounds__(256, 2)
void gemm_mma(const __half* __restrict__ Af,
              const __half* __restrict__ Bf,
              const float* __restrict__ bias, float* __restrict__ C,
              int M, int N, int K)
{
    extern __shared__ char dsm[];
    const uint32_t sbase = smem_u32(dsm);

    const int tid  = threadIdx.x;
    const int lane = tid & 31;
    const int wid  = tid >> 5;
    const int wm   = wid & 3;
    const int wn   = wid >> 2;
    const int bm   = blockIdx.y * GBM;
    const int bn   = blockIdx.x * GBN;
    const int NK   = K / GBK;

    float acc[2][8][4];
#pragma unroll
    for (int i = 0; i < 2; i++)
#pragma unroll
        for (int j = 0; j < 8; j++)
#pragma unroll
            for (int c = 0; c < 4; c++) acc[i][j][c] = 0.f;

    auto load_stage = [&](int k0, int s) {
        const uint32_t sb = sbase + s * STG_BYTES;
#pragma unroll
        for (int i = 0; i < 2; i++) {
            const int c   = tid + i * 256;
            const int row = c >> 2, j = c & 3;
            const uint32_t off = (uint32_t)(row * ROWB + j * 16);
            const size_t ga = (size_t)(bm + row) * K + k0 + j * 8;
            const size_t gb = (size_t)(bn + row) * K + k0 + j * 8;
            cpa16(sb + SM_AF + off, Af + ga);
            cpa16(sb + SM_BF + off, Bf + gb);
        }
        cpa_commit();
    };

    load_stage(0, 0);
    load_stage(GBK, 1);

    const int a_row = (lane & 15);
    const int a_kof = (lane >> 4) << 3;
    const int b_nof = (lane & 7) + ((lane >> 4) << 3);
    const int b_kof = ((lane >> 3) & 1) << 3;

    for (int k = 0; k < NK; k++) {
        if (k + 1 < NK) cpa_wait<1>(); else cpa_wait<0>();
        __syncthreads();                        // visibility + WAR barrier
        if (k + 2 < NK) load_stage((k + 2) * GBK, (k + 2) % 3);

        const uint32_t sb = sbase + (k % 3) * STG_BYTES;
#pragma unroll
        for (int kk = 0; kk < GBK; kk += 16) {
            uint32_t af[2][4];
#pragma unroll
            for (int mf = 0; mf < 2; mf++) {
                const uint32_t ad = sb + SM_AF +
                    (wm * 32 + mf * 16 + a_row) * ROWB + (kk + a_kof) * 2;
                ldm_x4(af[mf], ad);
            }
#pragma unroll
            for (int j = 0; j < 4; j++) {
                uint32_t bf[4];
                const uint32_t bd = sb + SM_BF +
                    (wn * 64 + j * 16 + b_nof) * ROWB + (kk + b_kof) * 2;
                ldm_x4(bf, bd);
#pragma unroll
                for (int mf = 0; mf < 2; mf++) {
                    mma16816h(acc[mf][2 * j + 0], af[mf], &bf[0]);
                    mma16816h(acc[mf][2 * j + 1], af[mf], &bf[2]);
                }
            }
        }
    }

#pragma unroll
    for (int mf = 0; mf < 2; mf++) {
        const int r0 = bm + wm * 32 + mf * 16 + (lane >> 2);
#pragma unroll
        for (int nf = 0; nf < 8; nf++) {
            const int c0 = bn + wn * 64 + nf * 8 + (lane & 3) * 2;
            const float b0 = bias[c0], b1 = bias[c0 + 1];
            float2 v0 = {acc[mf][nf][0] + b0, acc[mf][nf][1] + b1};
            float2 v1 = {acc[mf][nf][2] + b0, acc[mf][nf][3] + b1};
            *(float2*)(C + (size_t)r0 * N + c0) = v0;
            *(float2*)(C + (size_t)(r0 + 8) * N + c0) = v1;
        }
    }
}

// ---------------------------------------------------------------------------
// RoPE + conversion: q -> fp16 single (pre-scaled into log2 domain),
// k -> fp16 hi/lo, v -> fp16 hi/lo.
// ---------------------------------------------------------------------------
#define QSCALE 0.16130856f   // 0.11180339887 * 1.44269504089

__global__ void rope_cvt(const float* __restrict__ cosb,
                         const float* __restrict__ sinb)
{
    int idx = blockIdx.x * blockDim.x + threadIdx.x;
    if (idx >= S_LEN * NH * 40) return;
    const int d = idx % 40;
    const int h = (idx / 40) % NH;
    const int t = idx / (40 * NH);

    const float c0 = cosb[t * HD + d];
    const float c1 = cosb[t * HD + d + 40];
    const float s0 = sinb[t * HD + d];
    const float s1 = sinb[t * HD + d + 40];

    const size_t base = (size_t)t * QKV_STRIDE + h * HD;
    const float q0 = g_qkv[base + d],            q1 = g_qkv[base + d + 40];
    const float k0 = g_qkv[base + HID + d],      k1 = g_qkv[base + HID + d + 40];
    const float v0 = g_qkv[base + 2 * HID + d],  v1 = g_qkv[base + 2 * HID + d + 40];

    const float qr0 = (q0 * c0 - q1 * s0) * QSCALE;
    const float qr1 = (q1 * c1 + q0 * s1) * QSCALE;
    const float kr0 = k0 * c0 - k1 * s0;
    const float kr1 = k1 * c1 + k0 * s1;

    const size_t o = (size_t)t * HID + h * HD + d;
    __half hf, lf;
    g_qf[o]      = __float2half(qr0);
    g_qf[o + 40] = __float2half(qr1);
    split_hilo_h(kr0, hf, lf); g_khi[o] = hf;      g_klo[o] = lf;
    split_hilo_h(kr1, hf, lf); g_khi[o + 40] = hf; g_klo[o + 40] = lf;
    split_hilo_h(v0, hf, lf);  g_vhi[o] = hf;      g_vlo[o] = lf;
    split_hilo_h(v1, hf, lf);  g_vhi[o + 40] = hf; g_vlo[o + 40] = lf;
}

// ---------------------------------------------------------------------------
// HMMA flash attention. CTA = (chunk, head, 128 q rows); 8 warps x 16 rows.
// 3-stage cp.async KV pipeline, single sync per iter, S + state in regs.
// QK^T: fp16 2-term (Q rounded x K hi/lo).  PV: fp16 2-term (P rounded x
// V hi/lo).  Epilogue writes fp16 (rounded) proj-GEMM activation.
// ---------------------------------------------------------------------------
#define ARB 176                         // bytes per smem row
#define AQ_BYTES (128 * ARB)            // 22528 (Q fp16, single)
#define AKV_BYTES (64 * ARB)            // 11264
#define A_STG (4 * AKV_BYTES)           // 45056
#define ATTN_SMEM (AQ_BYTES + 3 * A_STG)   // 157696
#define AK_HI 0
#define AK_LO (1 * AKV_BYTES)
#define AV_HI (2 * AKV_BYTES)
#define AV_LO (3 * AKV_BYTES)

__global__ __launch_bounds__(256, 1)
void attn_mma()
{
    extern __shared__ char dsm[];
    const uint32_t sbase = smem_u32(dsm);
    const uint32_t SQ = sbase;
    const uint32_t SKV0 = sbase + AQ_BYTES;

    const int tid  = threadIdx.x;
    const int lane = tid & 31;
    const int wid  = tid >> 5;
    const int nc = blockIdx.y >> 4;
    const int h  = blockIdx.y & 15;
    const int t0 = nc * CH + blockIdx.x * 128;

    const int a_row = (lane & 15);
    const int a_kof = (lane >> 4) << 3;
    const int b_nof = (lane & 7) + ((lane >> 4) << 3);
    const int b_kof = ((lane >> 3) & 1) << 3;
    const int v_row = (lane & 15);
    const int v_cof = (lane >> 4) << 3;

    // Q loads (folded into group 0 with KV stage 0)
    for (int i = tid; i < 1280; i += 256) {
        const int r = i / 10, c = i % 10;
        const uint32_t off = (uint32_t)(r * ARB + c * 16);
        const size_t src = (size_t)(t0 + r) * HID + h * HD + c * 8;
        cpa16(SQ + off, g_qf + src);
    }
    auto load_kv = [&](int kb, int s) {
        const uint32_t sb = SKV0 + s * A_STG;
        for (int i = tid; i < 640; i += 256) {
            const int r = i / 10, c = i % 10;
            const uint32_t off = (uint32_t)(r * ARB + c * 16);
            const size_t src = (size_t)(nc * CH + kb * 64 + r) * HID + h * HD + c * 8;
            cpa16(sb + AK_HI + off, g_khi + src);
            cpa16(sb + AK_LO + off, g_klo + src);
            cpa16(sb + AV_HI + off, g_vhi + src);
            cpa16(sb + AV_LO + off, g_vlo + src);
        }
        cpa_commit();
    };
    load_kv(0, 0);       // group 0 (Q + KV0)
    load_kv(1, 1);       // group 1

    float o[10][4];
#pragma unroll
    for (int n = 0; n < 10; n++)
#pragma unroll
        for (int c = 0; c < 4; c++) o[n][c] = 0.f;
    float m0 = -1e30f, m1 = -1e30f, l0 = 0.f, l1 = 0.f;

    for (int kb = 0; kb < 16; kb++) {
        if (kb < 14) cpa_wait<1>(); else cpa_wait<0>();
        __syncthreads();
        if (kb + 2 < 16) load_kv(kb + 2, (kb + 2) % 3);

        const uint32_t sb = SKV0 + (kb % 3) * A_STG;

        // ---- S = Q K^T (fp16 2-term), 64 cols, k=80; log2-domain logits ----
        float s[8][4];
#pragma unroll
        for (int j = 0; j < 8; j++)
#pragma unroll
            for (int c = 0; c < 4; c++) s[j][c] = 0.f;

#pragma unroll
        for (int kt = 0; kt < 5; kt++) {
            uint32_t af[4];
            const uint32_t ad = SQ + (wid * 16 + a_row) * ARB +
                                (kt * 16 + a_kof) * 2;
            ldm_x4(af, ad);
#pragma unroll
            for (int g = 0; g < 4; g++) {
                uint32_t bh[4], bl[4];
                const uint32_t bd = sb + AK_HI + (g * 16 + b_nof) * ARB +
                                    (kt * 16 + b_kof) * 2;
                ldm_x4(bh, bd);
                ldm_x4(bl, bd + AKV_BYTES);
                mma16816h(s[2 * g + 0], af, &bh[0]);
                mma16816h(s[2 * g + 1], af, &bh[2]);
                mma16816h(s[2 * g + 0], af, &bl[0]);
                mma16816h(s[2 * g + 1], af, &bl[2]);
            }
        }

        // ---- online softmax (log2 domain) ----
        float mb0 = -1e30f, mb1 = -1e30f;
#pragma unroll
        for (int j = 0; j < 8; j++) {
            mb0 = fmaxf(mb0, fmaxf(s[j][0], s[j][1]));
            mb1 = fmaxf(mb1, fmaxf(s[j][2], s[j][3]));
        }
        mb0 = fmaxf(mb0, __shfl_xor_sync(0xffffffffu, mb0, 1));
        mb0 = fmaxf(mb0, __shfl_xor_sync(0xffffffffu, mb0, 2));
        mb1 = fmaxf(mb1, __shfl_xor_sync(0xffffffffu, mb1, 1));
        mb1 = fmaxf(mb1, __shfl_xor_sync(0xffffffffu, mb1, 2));

        const float mn0 = fmaxf(m0, mb0), mn1 = fmaxf(m1, mb1);
        const float alpha0 = exp2f(m0 - mn0);
        const float alpha1 = exp2f(m1 - mn1);
        m0 = mn0; m1 = mn1;

        float sum0 = 0.f, sum1 = 0.f;
#pragma unroll
        for (int j = 0; j < 8; j++) {
            s[j][0] = exp2f(s[j][0] - m0); sum0 += s[j][0];
            s[j][1] = exp2f(s[j][1] - m0); sum0 += s[j][1];
            s[j][2] = exp2f(s[j][2] - m1); sum1 += s[j][2];
            s[j][3] = exp2f(s[j][3] - m1); sum1 += s[j][3];
        }
        sum0 += __shfl_xor_sync(0xffffffffu, sum0, 1);
        sum0 += __shfl_xor_sync(0xffffffffu, sum0, 2);
        sum1 += __shfl_xor_sync(0xffffffffu, sum1, 1);
        sum1 += __shfl_xor_sync(0xffffffffu, sum1, 2);
        l0 = l0 * alpha0 + sum0;
        l1 = l1 * alpha1 + sum1;

#pragma unroll
        for (int n = 0; n < 10; n++) {
            o[n][0] *= alpha0; o[n][1] *= alpha0;
            o[n][2] *= alpha1; o[n][3] *= alpha1;
        }

        // ---- O += P V, fp16: P rounded (1 term) x V hi/lo (2 terms) ----
#pragma unroll
        for (int t = 0; t < 4; t++) {
            uint32_t ph[4];
            const float* f0 = s[2 * t];
            const float* f1 = s[2 * t + 1];
            ph[0] = pack_f16(f0[0], f0[1]);
            ph[1] = pack_f16(f0[2], f0[3]);
            ph[2] = pack_f16(f1[0], f1[1]);
            ph[3] = pack_f16(f1[2], f1[3]);
#pragma unroll
            for (int v = 0; v < 5; v++) {
                uint32_t vh[4], vl[4];
                const uint32_t vd = sb + AV_HI + (t * 16 + v_row) * ARB +
                                    (v * 16 + v_cof) * 2;
                ldm_x4_t(vh, vd);
                ldm_x4_t(vl, vd + AKV_BYTES);
                mma16816h(o[2 * v + 0], ph, &vh[0]);
                mma16816h(o[2 * v + 1], ph, &vh[2]);
                mma16816h(o[2 * v + 0], ph, &vl[0]);
                mma16816h(o[2 * v + 1], ph, &vl[2]);
            }
        }
    }

    // ---- epilogue: o/l -> fp16 -> g_af (proj activation) ----
    const float li0 = 1.f / l0, li1 = 1.f / l1;
    const int r0 = t0 + wid * 16 + (lane >> 2);
    const size_t colb = h * HD + 2 * (lane & 3);
#pragma unroll
    for (int n = 0; n < 10; n++) {
        const size_t p0 = (size_t)r0 * HID + colb + n * 8;
        const size_t p1 = (size_t)(r0 + 8) * HID + colb + n * 8;
        *(__half2*)(g_af + p0) = __floats2half2_rn(o[n][0] * li0, o[n][1] * li0);
        *(__half2*)(g_af + p1) = __floats2half2_rn(o[n][2] * li1, o[n][3] * li1);
    }
}

// ---------------------------------------------------------------------------
extern "C" void kernel_launch(void* const* d_in, const int* in_sizes, int n_in,
                              void* d_out, int out_size)
{
    const float* x      = (const float*)d_in[0];
    const float* cosb   = (const float*)d_in[2];
    const float* sinb   = (const float*)d_in[3];
    const float* w_qkv  = (const float*)d_in[4];
    const float* b_qkv  = (const float*)d_in[5];
    const float* w_proj = (const float*)d_in[6];
    const float* b_proj = (const float*)d_in[7];
    float* out = (float*)d_out;

    float* qkv_p;
    __half *xf, *wq, *wp, *af;
    cudaGetSymbolAddress((void**)&qkv_p, g_qkv);
    cudaGetSymbolAddress((void**)&xf, g_xf);
    cudaGetSymbolAddress((void**)&wq, g_wq);
    cudaGetSymbolAddress((void**)&wp, g_wp);
    cudaGetSymbolAddress((void**)&af, g_af);

    cudaFuncSetAttribute(gemm_mma,
                         cudaFuncAttributeMaxDynamicSharedMemorySize, GEMM_SMEM);
    cudaFuncSetAttribute(attn_mma,
                         cudaFuncAttributeMaxDynamicSharedMemorySize, ATTN_SMEM);

    const int n_x = S_LEN * HID;
    const int n_wq = 3 * HID * HID;
    const int n_wp = HID * HID;

    cvt_f16<<<(n_x / 4 + 255) / 256, 256>>>(x, xf, n_x);
    cvt_f16<<<(n_wq / 4 + 255) / 256, 256>>>(w_qkv, wq, n_wq);
    cvt_f16<<<(n_wp / 4 + 255) / 256, 256>>>(w_proj, wp, n_wp);

    gemm_mma<<<dim3(3 * HID / GBN, S_LEN / GBM), 256, GEMM_SMEM>>>(
        xf, wq, b_qkv, qkv_p, S_LEN, 3 * HID, HID);

    rope_cvt<<<(S_LEN * NH * 40 + 255) / 256, 256>>>(cosb, sinb);

    attn_mma<<<dim3(8, NC * NH), 256, ATTN_SMEM>>>();

    gemm_mma<<<dim3(HID / GBN, S_LEN / GBM), 256, GEMM_SMEM>>>(
        af, wp, b_proj, out, S_LEN, HID, HID);
}

// round 10
// speedup vs baseline: 8.1394x; 1.2705x over previous
#include <cuda_runtime.h>
#include <cuda_bf16.h>
#include <cuda_fp16.h>
#include <cstdint>
#include <math.h>

#define S_LEN 16384
#define HID 1280
#define NH 16
#define HD 80
#define NC 16
#define CH 1024
#define QKV_STRIDE (3 * HID)   // 3840

// ---------------------------------------------------------------------------
// Scratch (no cudaMalloc allowed)
// ---------------------------------------------------------------------------
__device__ float g_qkv[(size_t)S_LEN * 3 * HID];   // [S, 3, NH, HD] fp32

// GEMM operands: plain fp16 (both sides rounded)
__device__ __align__(256) __half g_xf[(size_t)S_LEN * HID];
__device__ __align__(256) __half g_wq[(size_t)3 * HID * HID];
__device__ __align__(256) __half g_wp[(size_t)HID * HID];
// attention inputs: plain fp16 (q pre-scaled by 1/sqrt(80)*log2e)
__device__ __align__(256) __half g_qf[(size_t)S_LEN * HID];
__device__ __align__(256) __half g_kf[(size_t)S_LEN * HID];
__device__ __align__(256) __half g_vf[(size_t)S_LEN * HID];
// attention output = proj GEMM activation (fp16, rounded)
__device__ __align__(256) __half g_af[(size_t)S_LEN * HID];

// ---------------------------------------------------------------------------
// helpers (sm_80-era instructions only — harness compiles for plain sm_103)
// ---------------------------------------------------------------------------
__device__ __forceinline__ uint32_t smem_u32(const void* p) {
    uint32_t a;
    asm("{ .reg .u64 t; cvta.to.shared.u64 t, %1; cvt.u32.u64 %0, t; }"
        : "=r"(a) : "l"(p));
    return a;
}

__device__ __forceinline__ void cpa16(uint32_t dst, const void* src) {
    asm volatile("cp.async.cg.shared.global [%0], [%1], 16;\n"
                 :: "r"(dst), "l"(src));
}
__device__ __forceinline__ void cpa_commit() {
    asm volatile("cp.async.commit_group;\n" ::: "memory");
}
template <int N>
__device__ __forceinline__ void cpa_wait() {
    asm volatile("cp.async.wait_group %0;\n" :: "n"(N) : "memory");
}

__device__ __forceinline__ void ldm_x4(uint32_t* r, uint32_t addr) {
    asm volatile("ldmatrix.sync.aligned.m8n8.x4.shared.b16 {%0,%1,%2,%3}, [%4];"
                 : "=r"(r[0]), "=r"(r[1]), "=r"(r[2]), "=r"(r[3])
                 : "r"(addr));
}
__device__ __forceinline__ void ldm_x4_t(uint32_t* r, uint32_t addr) {
    asm volatile(
        "ldmatrix.sync.aligned.m8n8.x4.trans.shared.b16 {%0,%1,%2,%3}, [%4];"
        : "=r"(r[0]), "=r"(r[1]), "=r"(r[2]), "=r"(r[3])
        : "r"(addr));
}

// fp16 mma, fp32 accumulate
__device__ __forceinline__ void mma16816h(float* d, const uint32_t* a,
                                          const uint32_t* b) {
    asm volatile(
        "mma.sync.aligned.m16n8k16.row.col.f32.f16.f16.f32 "
        "{%0,%1,%2,%3}, {%4,%5,%6,%7}, {%8,%9}, {%0,%1,%2,%3};"
        : "+f"(d[0]), "+f"(d[1]), "+f"(d[2]), "+f"(d[3])
        : "r"(a[0]), "r"(a[1]), "r"(a[2]), "r"(a[3]), "r"(b[0]), "r"(b[1]));
}

__device__ __forceinline__ uint32_t pack_f16(float lo, float hi) {
    uint32_t d;
    asm("cvt.rn.f16x2.f32 %0, %1, %2;" : "=r"(d) : "f"(hi), "f"(lo));
    return d;
}

// ---------------------------------------------------------------------------
// conversions
// ---------------------------------------------------------------------------
__global__ void cvt_f16(const float* __restrict__ src,
                        __half* __restrict__ dst, int n)
{
    int i = (blockIdx.x * blockDim.x + threadIdx.x) * 4;
    if (i >= n) return;
    float4 v = *(const float4*)(src + i);
    *(__half2*)(dst + i)     = __floats2half2_rn(v.x, v.y);
    *(__half2*)(dst + i + 2) = __floats2half2_rn(v.z, v.w);
}

// ---------------------------------------------------------------------------
// fp16 GEMM: C[M,N] = Af[M,K] @ Bf[N,K]^T + bias[N]
// Block 128x128, K-chunk 32, 8 warps (4M x 2N), warp tile 32x64.
// 3-stage cp.async pipeline, single __syncthreads per K-iter.
// ---------------------------------------------------------------------------
#define GBM 128
#define GBN 128
#define GBK 32
#define ROWB 80
#define MAT_BYTES (128 * ROWB)        // 10240
#define SM_AF 0
#define SM_BF (1 * MAT_BYTES)
#define STG_BYTES (2 * MAT_BYTES)     // 20480
#define GEMM_SMEM (3 * STG_BYTES)     // 61440

__global__ __launch_bounds__(256, 2)
void gemm_mma(const __half* __restrict__ Af,
              const __half* __restrict__ Bf,
              const float* __restrict__ bias, float* __restrict__ C,
              int M, int N, int K)
{
    extern __shared__ char dsm[];
    const uint32_t sbase = smem_u32(dsm);

    const int tid  = threadIdx.x;
    const int lane = tid & 31;
    const int wid  = tid >> 5;
    const int wm   = wid & 3;
    const int wn   = wid >> 2;
    const int bm   = blockIdx.y * GBM;
    const int bn   = blockIdx.x * GBN;
    const int NK   = K / GBK;

    float acc[2][8][4];
#pragma unroll
    for (int i = 0; i < 2; i++)
#pragma unroll
        for (int j = 0; j < 8; j++)
#pragma unroll
            for (int c = 0; c < 4; c++) acc[i][j][c] = 0.f;

    auto load_stage = [&](int k0, int s) {
        const uint32_t sb = sbase + s * STG_BYTES;
#pragma unroll
        for (int i = 0; i < 2; i++) {
            const int c   = tid + i * 256;
            const int row = c >> 2, j = c & 3;
            const uint32_t off = (uint32_t)(row * ROWB + j * 16);
            const size_t ga = (size_t)(bm + row) * K + k0 + j * 8;
            const size_t gb = (size_t)(bn + row) * K + k0 + j * 8;
            cpa16(sb + SM_AF + off, Af + ga);
            cpa16(sb + SM_BF + off, Bf + gb);
        }
        cpa_commit();
    };

    load_stage(0, 0);
    load_stage(GBK, 1);

    const int a_row = (lane & 15);
    const int a_kof = (lane >> 4) << 3;
    const int b_nof = (lane & 7) + ((lane >> 4) << 3);
    const int b_kof = ((lane >> 3) & 1) << 3;

    for (int k = 0; k < NK; k++) {
        if (k + 1 < NK) cpa_wait<1>(); else cpa_wait<0>();
        __syncthreads();                        // visibility + WAR barrier
        if (k + 2 < NK) load_stage((k + 2) * GBK, (k + 2) % 3);

        const uint32_t sb = sbase + (k % 3) * STG_BYTES;
#pragma unroll
        for (int kk = 0; kk < GBK; kk += 16) {
            uint32_t af[2][4];
#pragma unroll
            for (int mf = 0; mf < 2; mf++) {
                const uint32_t ad = sb + SM_AF +
                    (wm * 32 + mf * 16 + a_row) * ROWB + (kk + a_kof) * 2;
                ldm_x4(af[mf], ad);
            }
#pragma unroll
            for (int j = 0; j < 4; j++) {
                uint32_t bf[4];
                const uint32_t bd = sb + SM_BF +
                    (wn * 64 + j * 16 + b_nof) * ROWB + (kk + b_kof) * 2;
                ldm_x4(bf, bd);
#pragma unroll
                for (int mf = 0; mf < 2; mf++) {
                    mma16816h(acc[mf][2 * j + 0], af[mf], &bf[0]);
                    mma16816h(acc[mf][2 * j + 1], af[mf], &bf[2]);
                }
            }
        }
    }

#pragma unroll
    for (int mf = 0; mf < 2; mf++) {
        const int r0 = bm + wm * 32 + mf * 16 + (lane >> 2);
#pragma unroll
        for (int nf = 0; nf < 8; nf++) {
            const int c0 = bn + wn * 64 + nf * 8 + (lane & 3) * 2;
            const float b0 = bias[c0], b1 = bias[c0 + 1];
            float2 v0 = {acc[mf][nf][0] + b0, acc[mf][nf][1] + b1};
            float2 v1 = {acc[mf][nf][2] + b0, acc[mf][nf][3] + b1};
            *(float2*)(C + (size_t)r0 * N + c0) = v0;
            *(float2*)(C + (size_t)(r0 + 8) * N + c0) = v1;
        }
    }
}

// ---------------------------------------------------------------------------
// RoPE + conversion: q (pre-scaled into log2 domain), k, v -> plain fp16
// ---------------------------------------------------------------------------
#define QSCALE 0.16130856f   // 0.11180339887 * 1.44269504089

__global__ void rope_cvt(const float* __restrict__ cosb,
                         const float* __restrict__ sinb)
{
    int idx = blockIdx.x * blockDim.x + threadIdx.x;
    if (idx >= S_LEN * NH * 40) return;
    const int d = idx % 40;
    const int h = (idx / 40) % NH;
    const int t = idx / (40 * NH);

    const float c0 = cosb[t * HD + d];
    const float c1 = cosb[t * HD + d + 40];
    const float s0 = sinb[t * HD + d];
    const float s1 = sinb[t * HD + d + 40];

    const size_t base = (size_t)t * QKV_STRIDE + h * HD;
    const float q0 = g_qkv[base + d],            q1 = g_qkv[base + d + 40];
    const float k0 = g_qkv[base + HID + d],      k1 = g_qkv[base + HID + d + 40];
    const float v0 = g_qkv[base + 2 * HID + d],  v1 = g_qkv[base + 2 * HID + d + 40];

    const float qr0 = (q0 * c0 - q1 * s0) * QSCALE;
    const float qr1 = (q1 * c1 + q0 * s1) * QSCALE;
    const float kr0 = k0 * c0 - k1 * s0;
    const float kr1 = k1 * c1 + k0 * s1;

    const size_t o = (size_t)t * HID + h * HD + d;
    g_qf[o]      = __float2half(qr0);
    g_qf[o + 40] = __float2half(qr1);
    g_kf[o]      = __float2half(kr0);
    g_kf[o + 40] = __float2half(kr1);
    g_vf[o]      = __float2half(v0);
    g_vf[o + 40] = __float2half(v1);
}

// ---------------------------------------------------------------------------
// HMMA flash attention, plain fp16 operands (fp32 accumulate).
// CTA = (chunk, head, 128 q rows); 8 warps x 16 rows.
// 3-stage cp.async KV pipeline, single sync per iter, S + state in regs.
// Small smem (90 KB) -> 2 CTAs/SM.
// ---------------------------------------------------------------------------
#define ARB 176                         // bytes per smem row
#define AQ_BYTES (128 * ARB)            // 22528 (Q fp16)
#define AKV_BYTES (64 * ARB)            // 11264
#define A_STG (2 * AKV_BYTES)           // 22528 (K + V)
#define ATTN_SMEM (AQ_BYTES + 3 * A_STG)   // 90112
#define AK_OFF 0
#define AV_OFF AKV_BYTES

__global__ __launch_bounds__(256, 2)
void attn_mma()
{
    extern __shared__ char dsm[];
    const uint32_t sbase = smem_u32(dsm);
    const uint32_t SQ = sbase;
    const uint32_t SKV0 = sbase + AQ_BYTES;

    const int tid  = threadIdx.x;
    const int lane = tid & 31;
    const int wid  = tid >> 5;
    const int nc = blockIdx.y >> 4;
    const int h  = blockIdx.y & 15;
    const int t0 = nc * CH + blockIdx.x * 128;

    const int a_row = (lane & 15);
    const int a_kof = (lane >> 4) << 3;
    const int b_nof = (lane & 7) + ((lane >> 4) << 3);
    const int b_kof = ((lane >> 3) & 1) << 3;
    const int v_row = (lane & 15);
    const int v_cof = (lane >> 4) << 3;

    // Q loads (folded into group 0 with KV stage 0)
    for (int i = tid; i < 1280; i += 256) {
        const int r = i / 10, c = i % 10;
        const uint32_t off = (uint32_t)(r * ARB + c * 16);
        const size_t src = (size_t)(t0 + r) * HID + h * HD + c * 8;
        cpa16(SQ + off, g_qf + src);
    }
    auto load_kv = [&](int kb, int s) {
        const uint32_t sb = SKV0 + s * A_STG;
        for (int i = tid; i < 640; i += 256) {
            const int r = i / 10, c = i % 10;
            const uint32_t off = (uint32_t)(r * ARB + c * 16);
            const size_t src = (size_t)(nc * CH + kb * 64 + r) * HID + h * HD + c * 8;
            cpa16(sb + AK_OFF + off, g_kf + src);
            cpa16(sb + AV_OFF + off, g_vf + src);
        }
        cpa_commit();
    };
    load_kv(0, 0);       // group 0 (Q + KV0)
    load_kv(1, 1);       // group 1

    float o[10][4];
#pragma unroll
    for (int n = 0; n < 10; n++)
#pragma unroll
        for (int c = 0; c < 4; c++) o[n][c] = 0.f;
    float m0 = -1e30f, m1 = -1e30f, l0 = 0.f, l1 = 0.f;

    for (int kb = 0; kb < 16; kb++) {
        if (kb < 14) cpa_wait<1>(); else cpa_wait<0>();
        __syncthreads();
        if (kb + 2 < 16) load_kv(kb + 2, (kb + 2) % 3);

        const uint32_t sb = SKV0 + (kb % 3) * A_STG;

        // ---- S = Q K^T (fp16), 64 cols, k=80; log2-domain logits ----
        float s[8][4];
#pragma unroll
        for (int j = 0; j < 8; j++)
#pragma unroll
            for (int c = 0; c < 4; c++) s[j][c] = 0.f;

#pragma unroll
        for (int kt = 0; kt < 5; kt++) {
            uint32_t af[4];
            const uint32_t ad = SQ + (wid * 16 + a_row) * ARB +
                                (kt * 16 + a_kof) * 2;
            ldm_x4(af, ad);
#pragma unroll
            for (int g = 0; g < 4; g++) {
                uint32_t bf[4];
                const uint32_t bd = sb + AK_OFF + (g * 16 + b_nof) * ARB +
                                    (kt * 16 + b_kof) * 2;
                ldm_x4(bf, bd);
                mma16816h(s[2 * g + 0], af, &bf[0]);
                mma16816h(s[2 * g + 1], af, &bf[2]);
            }
        }

        // ---- online softmax (log2 domain) ----
        float mb0 = -1e30f, mb1 = -1e30f;
#pragma unroll
        for (int j = 0; j < 8; j++) {
            mb0 = fmaxf(mb0, fmaxf(s[j][0], s[j][1]));
            mb1 = fmaxf(mb1, fmaxf(s[j][2], s[j][3]));
        }
        mb0 = fmaxf(mb0, __shfl_xor_sync(0xffffffffu, mb0, 1));
        mb0 = fmaxf(mb0, __shfl_xor_sync(0xffffffffu, mb0, 2));
        mb1 = fmaxf(mb1, __shfl_xor_sync(0xffffffffu, mb1, 1));
        mb1 = fmaxf(mb1, __shfl_xor_sync(0xffffffffu, mb1, 2));

        const float mn0 = fmaxf(m0, mb0), mn1 = fmaxf(m1, mb1);
        const float alpha0 = exp2f(m0 - mn0);
        const float alpha1 = exp2f(m1 - mn1);
        m0 = mn0; m1 = mn1;

        float sum0 = 0.f, sum1 = 0.f;
#pragma unroll
        for (int j = 0; j < 8; j++) {
            s[j][0] = exp2f(s[j][0] - m0); sum0 += s[j][0];
            s[j][1] = exp2f(s[j][1] - m0); sum0 += s[j][1];
            s[j][2] = exp2f(s[j][2] - m1); sum1 += s[j][2];
            s[j][3] = exp2f(s[j][3] - m1); sum1 += s[j][3];
        }
        sum0 += __shfl_xor_sync(0xffffffffu, sum0, 1);
        sum0 += __shfl_xor_sync(0xffffffffu, sum0, 2);
        sum1 += __shfl_xor_sync(0xffffffffu, sum1, 1);
        sum1 += __shfl_xor_sync(0xffffffffu, sum1, 2);
        l0 = l0 * alpha0 + sum0;
        l1 = l1 * alpha1 + sum1;

#pragma unroll
        for (int n = 0; n < 10; n++) {
            o[n][0] *= alpha0; o[n][1] *= alpha0;
            o[n][2] *= alpha1; o[n][3] *= alpha1;
        }

        // ---- O += P V (fp16, P rounded) ----
#pragma unroll
        for (int t = 0; t < 4; t++) {
            uint32_t ph[4];
            const float* f0 = s[2 * t];
            const float* f1 = s[2 * t + 1];
            ph[0] = pack_f16(f0[0], f0[1]);
            ph[1] = pack_f16(f0[2], f0[3]);
            ph[2] = pack_f16(f1[0], f1[1]);
            ph[3] = pack_f16(f1[2], f1[3]);
#pragma unroll
            for (int v = 0; v < 5; v++) {
                uint32_t vf[4];
                const uint32_t vd = sb + AV_OFF + (t * 16 + v_row) * ARB +
                                    (v * 16 + v_cof) * 2;
                ldm_x4_t(vf, vd);
                mma16816h(o[2 * v + 0], ph, &vf[0]);
                mma16816h(o[2 * v + 1], ph, &vf[2]);
            }
        }
    }

    // ---- epilogue: o/l -> fp16 -> g_af (proj activation) ----
    const float li0 = 1.f / l0, li1 = 1.f / l1;
    const int r0 = t0 + wid * 16 + (lane >> 2);
    const size_t colb = h * HD + 2 * (lane & 3);
#pragma unroll
    for (int n = 0; n < 10; n++) {
        const size_t p0 = (size_t)r0 * HID + colb + n * 8;
        const size_t p1 = (size_t)(r0 + 8) * HID + colb + n * 8;
        *(__half2*)(g_af + p0) = __floats2half2_rn(o[n][0] * li0, o[n][1] * li0);
        *(__half2*)(g_af + p1) = __floats2half2_rn(o[n][2] * li1, o[n][3] * li1);
    }
}

// ---------------------------------------------------------------------------
extern "C" void kernel_launch(void* const* d_in, const int* in_sizes, int n_in,
                              void* d_out, int out_size)
{
    const float* x      = (const float*)d_in[0];
    const float* cosb   = (const float*)d_in[2];
    const float* sinb   = (const float*)d_in[3];
    const float* w_qkv  = (const float*)d_in[4];
    const float* b_qkv  = (const float*)d_in[5];
    const float* w_proj = (const float*)d_in[6];
    const float* b_proj = (const float*)d_in[7];
    float* out = (float*)d_out;

    float* qkv_p;
    __half *xf, *wq, *wp, *af;
    cudaGetSymbolAddress((void**)&qkv_p, g_qkv);
    cudaGetSymbolAddress((void**)&xf, g_xf);
    cudaGetSymbolAddress((void**)&wq, g_wq);
    cudaGetSymbolAddress((void**)&wp, g_wp);
    cudaGetSymbolAddress((void**)&af, g_af);

    cudaFuncSetAttribute(gemm_mma,
                         cudaFuncAttributeMaxDynamicSharedMemorySize, GEMM_SMEM);
    cudaFuncSetAttribute(attn_mma,
                         cudaFuncAttributeMaxDynamicSharedMemorySize, ATTN_SMEM);

    const int n_x = S_LEN * HID;
    const int n_wq = 3 * HID * HID;
    const int n_wp = HID * HID;

    cvt_f16<<<(n_x / 4 + 255) / 256, 256>>>(x, xf, n_x);
    cvt_f16<<<(n_wq / 4 + 255) / 256, 256>>>(w_qkv, wq, n_wq);
    cvt_f16<<<(n_wp / 4 + 255) / 256, 256>>>(w_proj, wp, n_wp);

    gemm_mma<<<dim3(3 * HID / GBN, S_LEN / GBM), 256, GEMM_SMEM>>>(
        xf, wq, b_qkv, qkv_p, S_LEN, 3 * HID, HID);

    rope_cvt<<<(S_LEN * NH * 40 + 255) / 256, 256>>>(cosb, sinb);

    attn_mma<<<dim3(8, NC * NH), 256, ATTN_SMEM>>>();

    gemm_mma<<<dim3(HID / GBN, S_LEN / GBM), 256, GEMM_SMEM>>>(
        af, wp, b_proj, out, S_LEN, HID, HID);
}

// round 11
// speedup vs baseline: 8.1556x; 1.0020x over previous
#include <cuda_runtime.h>
#include <cuda_bf16.h>
#include <cuda_fp16.h>
#include <cstdint>
#include <math.h>

#define S_LEN 16384
#define HID 1280
#define NH 16
#define HD 80
#define NC 16
#define CH 1024

// ---------------------------------------------------------------------------
// Scratch (no cudaMalloc allowed)
// ---------------------------------------------------------------------------
// GEMM operands: plain fp16 (both sides rounded)
__device__ __align__(256) __half g_xf[(size_t)S_LEN * HID];
__device__ __align__(256) __half g_wq[(size_t)3 * HID * HID];  // q/k rows PERMUTED
__device__ __align__(256) float  g_bq[3 * HID];                // permuted bias
__device__ __align__(256) __half g_wp[(size_t)HID * HID];
// attention inputs: plain fp16. q,k stored in rope-permuted d-layout
// (pairs (d, d+40) interleaved as (2i, 2i+1)); q pre-scaled by 1/sqrt(80)*log2e.
__device__ __align__(256) __half g_qf[(size_t)S_LEN * HID];
__device__ __align__(256) __half g_kf[(size_t)S_LEN * HID];
__device__ __align__(256) __half g_vf[(size_t)S_LEN * HID];
// attention output = proj GEMM activation (fp16, rounded)
__device__ __align__(256) __half g_af[(size_t)S_LEN * HID];

#define QSCALE 0.16130856f   // 0.11180339887 * 1.44269504089

// ---------------------------------------------------------------------------
// helpers (sm_80-era instructions only — harness compiles for plain sm_103)
// ---------------------------------------------------------------------------
__device__ __forceinline__ uint32_t smem_u32(const void* p) {
    uint32_t a;
    asm("{ .reg .u64 t; cvta.to.shared.u64 t, %1; cvt.u32.u64 %0, t; }"
        : "=r"(a) : "l"(p));
    return a;
}

__device__ __forceinline__ void cpa16(uint32_t dst, const void* src) {
    asm volatile("cp.async.cg.shared.global [%0], [%1], 16;\n"
                 :: "r"(dst), "l"(src));
}
__device__ __forceinline__ void cpa_commit() {
    asm volatile("cp.async.commit_group;\n" ::: "memory");
}
template <int N>
__device__ __forceinline__ void cpa_wait() {
    asm volatile("cp.async.wait_group %0;\n" :: "n"(N) : "memory");
}

__device__ __forceinline__ void ldm_x4(uint32_t* r, uint32_t addr) {
    asm volatile("ldmatrix.sync.aligned.m8n8.x4.shared.b16 {%0,%1,%2,%3}, [%4];"
                 : "=r"(r[0]), "=r"(r[1]), "=r"(r[2]), "=r"(r[3])
                 : "r"(addr));
}
__device__ __forceinline__ void ldm_x4_t(uint32_t* r, uint32_t addr) {
    asm volatile(
        "ldmatrix.sync.aligned.m8n8.x4.trans.shared.b16 {%0,%1,%2,%3}, [%4];"
        : "=r"(r[0]), "=r"(r[1]), "=r"(r[2]), "=r"(r[3])
        : "r"(addr));
}

// fp16 mma, fp32 accumulate
__device__ __forceinline__ void mma16816h(float* d, const uint32_t* a,
                                          const uint32_t* b) {
    asm volatile(
        "mma.sync.aligned.m16n8k16.row.col.f32.f16.f16.f32 "
        "{%0,%1,%2,%3}, {%4,%5,%6,%7}, {%8,%9}, {%0,%1,%2,%3};"
        : "+f"(d[0]), "+f"(d[1]), "+f"(d[2]), "+f"(d[3])
        : "r"(a[0]), "r"(a[1]), "r"(a[2]), "r"(a[3]), "r"(b[0]), "r"(b[1]));
}

__device__ __forceinline__ uint32_t pack_f16(float lo, float hi) {
    uint32_t d;
    asm("cvt.rn.f16x2.f32 %0, %1, %2;" : "=r"(d) : "f"(hi), "f"(lo));
    return d;
}

// ---------------------------------------------------------------------------
// conversions
// ---------------------------------------------------------------------------
__global__ void cvt_f16(const float* __restrict__ src,
                        __half* __restrict__ dst, int n)
{
    int i = (blockIdx.x * blockDim.x + threadIdx.x) * 4;
    if (i >= n) return;
    float4 v = *(const float4*)(src + i);
    *(__half2*)(dst + i)     = __floats2half2_rn(v.x, v.y);
    *(__half2*)(dst + i + 2) = __floats2half2_rn(v.z, v.w);
}

// w_qkv conversion with rope-pair permutation of q/k output channels.
// Permuted row p holds original channel n(p):
//   which = p/1280; for which<2: h = (p%1280)/80, j = (p%1280)%80,
//   d = (j&1) ? (j>>1)+40 : (j>>1);  n = which*1280 + h*80 + d.
//   which==2 (v): identity.
// Also writes permuted bias.
__global__ void cvt_wq_perm(const float* __restrict__ w,
                            const float* __restrict__ b)
{
    int i = (blockIdx.x * blockDim.x + threadIdx.x) * 4;
    if (i >= 3 * HID * HID) return;
    const int p  = i / HID;
    const int kk = i % HID;
    const int which = p / HID;
    int n = p;
    if (which < 2) {
        const int pl = p % HID;
        const int h = pl / 80, j = pl % 80;
        const int d = (j & 1) ? (j >> 1) + 40 : (j >> 1);
        n = which * HID + h * 80 + d;
    }
    float4 v = *(const float4*)(w + (size_t)n * HID + kk);
    *(__half2*)(g_wq + (size_t)p * HID + kk)     = __floats2half2_rn(v.x, v.y);
    *(__half2*)(g_wq + (size_t)p * HID + kk + 2) = __floats2half2_rn(v.z, v.w);
    if (kk == 0) g_bq[p] = b[n];
}

// ---------------------------------------------------------------------------
// fp16 GEMM mainloop (shared by both kernels via macro).
// Block 128x128, K-chunk 32, 8 warps (4M x 2N), warp tile 32x64.
// 3-stage cp.async pipeline, single __syncthreads per K-iter.
// ---------------------------------------------------------------------------
#define GBM 128
#define GBN 128
#define GBK 32
#define ROWB 80
#define MAT_BYTES (128 * ROWB)        // 10240
#define SM_AF 0
#define SM_BF (1 * MAT_BYTES)
#define STG_BYTES (2 * MAT_BYTES)     // 20480
#define GEMM_SMEM (3 * STG_BYTES)     // 61440

#define GEMM_MAINLOOP(Af, Bf, K)                                              \
    extern __shared__ char dsm[];                                             \
    const uint32_t sbase = smem_u32(dsm);                                     \
    const int tid  = threadIdx.x;                                             \
    const int lane = tid & 31;                                                \
    const int wid  = tid >> 5;                                                \
    const int wm   = wid & 3;                                                 \
    const int wn   = wid >> 2;                                                \
    const int bm   = blockIdx.y * GBM;                                        \
    const int bn   = blockIdx.x * GBN;                                        \
    const int NK   = (K) / GBK;                                               \
    float acc[2][8][4];                                                       \
    _Pragma("unroll")                                                         \
    for (int i = 0; i < 2; i++)                                               \
        _Pragma("unroll")                                                     \
        for (int j = 0; j < 8; j++)                                           \
            _Pragma("unroll")                                                 \
            for (int c = 0; c < 4; c++) acc[i][j][c] = 0.f;                   \
    auto load_stage = [&](int k0, int s) {                                    \
        const uint32_t sb = sbase + s * STG_BYTES;                            \
        _Pragma("unroll")                                                     \
        for (int i = 0; i < 2; i++) {                                         \
            const int c   = tid + i * 256;                                    \
            const int row = c >> 2, j = c & 3;                                \
            const uint32_t off = (uint32_t)(row * ROWB + j * 16);             \
            const size_t ga = (size_t)(bm + row) * (K) + k0 + j * 8;          \
            const size_t gb = (size_t)(bn + row) * (K) + k0 + j * 8;          \
            cpa16(sb + SM_AF + off, (Af) + ga);                               \
            cpa16(sb + SM_BF + off, (Bf) + gb);                               \
        }                                                                     \
        cpa_commit();                                                         \
    };                                                                        \
    load_stage(0, 0);                                                         \
    load_stage(GBK, 1);                                                       \
    const int a_row = (lane & 15);                                            \
    const int a_kof = (lane >> 4) << 3;                                       \
    const int b_nof = (lane & 7) + ((lane >> 4) << 3);                        \
    const int b_kof = ((lane >> 3) & 1) << 3;                                 \
    for (int k = 0; k < NK; k++) {                                            \
        if (k + 1 < NK) cpa_wait<1>(); else cpa_wait<0>();                    \
        __syncthreads();                                                      \
        if (k + 2 < NK) load_stage((k + 2) * GBK, (k + 2) % 3);               \
        const uint32_t sb = sbase + (k % 3) * STG_BYTES;                      \
        _Pragma("unroll")                                                     \
        for (int kk = 0; kk < GBK; kk += 16) {                                \
            uint32_t af[2][4];                                                \
            _Pragma("unroll")                                                 \
            for (int mf = 0; mf < 2; mf++) {                                  \
                const uint32_t ad = sb + SM_AF +                              \
                    (wm * 32 + mf * 16 + a_row) * ROWB + (kk + a_kof) * 2;    \
                ldm_x4(af[mf], ad);                                           \
            }                                                                 \
            _Pragma("unroll")                                                 \
            for (int j = 0; j < 4; j++) {                                     \
                uint32_t bf[4];                                               \
                const uint32_t bd = sb + SM_BF +                              \
                    (wn * 64 + j * 16 + b_nof) * ROWB + (kk + b_kof) * 2;     \
                ldm_x4(bf, bd);                                               \
                _Pragma("unroll")                                             \
                for (int mf = 0; mf < 2; mf++) {                              \
                    mma16816h(acc[mf][2 * j + 0], af[mf], &bf[0]);            \
                    mma16816h(acc[mf][2 * j + 1], af[mf], &bf[2]);            \
                }                                                             \
            }                                                                 \
        }                                                                     \
    }

// ---------------------------------------------------------------------------
// QKV GEMM with fused bias + RoPE + fp16 store into g_qf/g_kf/g_vf.
// Weight rows pre-permuted so rope partners are adjacent columns (2i, 2i+1).
// grid = (30, 128): blockIdx.x section is CTA-uniform (1280 % 128 == 0).
// ---------------------------------------------------------------------------
__global__ __launch_bounds__(256, 2)
void gemm_qkv(const __half* __restrict__ Af,
              const __half* __restrict__ Bf,
              const float* __restrict__ cosb,
              const float* __restrict__ sinb)
{
    GEMM_MAINLOOP(Af, Bf, HID)

    const int which = bn / HID;              // 0=q, 1=k, 2=v (CTA-uniform)
    __half* dst = (which == 0) ? g_qf : (which == 1) ? g_kf : g_vf;

#pragma unroll
    for (int mf = 0; mf < 2; mf++) {
        const int r0 = bm + wm * 32 + mf * 16 + (lane >> 2);
#pragma unroll
        for (int nf = 0; nf < 8; nf++) {
            const int c0 = bn + wn * 64 + nf * 8 + (lane & 3) * 2;  // even
            const float b0 = g_bq[c0], b1 = g_bq[c0 + 1];
            const int local = c0 - which * HID;
            float x00 = acc[mf][nf][0] + b0, x01 = acc[mf][nf][1] + b1;
            float x10 = acc[mf][nf][2] + b0, x11 = acc[mf][nf][3] + b1;
            if (which == 2) {
                *(__half2*)(dst + (size_t)r0 * HID + local) =
                    __floats2half2_rn(x00, x01);
                *(__half2*)(dst + (size_t)(r0 + 8) * HID + local) =
                    __floats2half2_rn(x10, x11);
            } else {
                const int i = (local % 80) >> 1;     // rope pair index
                // row r0
                const float* cr0 = cosb + (size_t)r0 * HD;
                const float* sr0 = sinb + (size_t)r0 * HD;
                float o00 = x00 * cr0[i]      - x01 * sr0[i];
                float o01 = x01 * cr0[i + 40] + x00 * sr0[i + 40];
                // row r0 + 8
                const float* cr1 = cr0 + 8 * HD;
                const float* sr1 = sr0 + 8 * HD;
                float o10 = x10 * cr1[i]      - x11 * sr1[i];
                float o11 = x11 * cr1[i + 40] + x10 * sr1[i + 40];
                if (which == 0) {
                    o00 *= QSCALE; o01 *= QSCALE;
                    o10 *= QSCALE; o11 *= QSCALE;
                }
                *(__half2*)(dst + (size_t)r0 * HID + local) =
                    __floats2half2_rn(o00, o01);
                *(__half2*)(dst + (size_t)(r0 + 8) * HID + local) =
                    __floats2half2_rn(o10, o11);
            }
        }
    }
}

// ---------------------------------------------------------------------------
// Proj GEMM: fp32 output + bias (final result)
// ---------------------------------------------------------------------------
__global__ __launch_bounds__(256, 2)
void gemm_proj(const __half* __restrict__ Af,
               const __half* __restrict__ Bf,
               const float* __restrict__ bias, float* __restrict__ C)
{
    GEMM_MAINLOOP(Af, Bf, HID)

    const int N = HID;
#pragma unroll
    for (int mf = 0; mf < 2; mf++) {
        const int r0 = bm + wm * 32 + mf * 16 + (lane >> 2);
#pragma unroll
        for (int nf = 0; nf < 8; nf++) {
            const int c0 = bn + wn * 64 + nf * 8 + (lane & 3) * 2;
            const float b0 = bias[c0], b1 = bias[c0 + 1];
            float2 v0 = {acc[mf][nf][0] + b0, acc[mf][nf][1] + b1};
            float2 v1 = {acc[mf][nf][2] + b0, acc[mf][nf][3] + b1};
            *(float2*)(C + (size_t)r0 * N + c0) = v0;
            *(float2*)(C + (size_t)(r0 + 8) * N + c0) = v1;
        }
    }
}

// ---------------------------------------------------------------------------
// HMMA flash attention, plain fp16 operands (fp32 accumulate).
// CTA = (chunk, head, 128 q rows); 8 warps x 16 rows.
// 3-stage cp.async KV pipeline, single sync per iter, S + state in regs.
// Small smem (90 KB) -> 2 CTAs/SM.  q/k in permuted d-layout (QK^T invariant).
// ---------------------------------------------------------------------------
#define ARB 176                         // bytes per smem row
#define AQ_BYTES (128 * ARB)            // 22528 (Q fp16)
#define AKV_BYTES (64 * ARB)            // 11264
#define A_STG (2 * AKV_BYTES)           // 22528 (K + V)
#define ATTN_SMEM (AQ_BYTES + 3 * A_STG)   // 90112
#define AK_OFF 0
#define AV_OFF AKV_BYTES

__global__ __launch_bounds__(256, 2)
void attn_mma()
{
    extern __shared__ char dsm[];
    const uint32_t sbase = smem_u32(dsm);
    const uint32_t SQ = sbase;
    const uint32_t SKV0 = sbase + AQ_BYTES;

    const int tid  = threadIdx.x;
    const int lane = tid & 31;
    const int wid  = tid >> 5;
    const int nc = blockIdx.y >> 4;
    const int h  = blockIdx.y & 15;
    const int t0 = nc * CH + blockIdx.x * 128;

    const int a_row = (lane & 15);
    const int a_kof = (lane >> 4) << 3;
    const int b_nof = (lane & 7) + ((lane >> 4) << 3);
    const int b_kof = ((lane >> 3) & 1) << 3;
    const int v_row = (lane & 15);
    const int v_cof = (lane >> 4) << 3;

    // Q loads (folded into group 0 with KV stage 0)
    for (int i = tid; i < 1280; i += 256) {
        const int r = i / 10, c = i % 10;
        const uint32_t off = (uint32_t)(r * ARB + c * 16);
        const size_t src = (size_t)(t0 + r) * HID + h * HD + c * 8;
        cpa16(SQ + off, g_qf + src);
    }
    auto load_kv = [&](int kb, int s) {
        const uint32_t sb = SKV0 + s * A_STG;
        for (int i = tid; i < 640; i += 256) {
            const int r = i / 10, c = i % 10;
            const uint32_t off = (uint32_t)(r * ARB + c * 16);
            const size_t src = (size_t)(nc * CH + kb * 64 + r) * HID + h * HD + c * 8;
            cpa16(sb + AK_OFF + off, g_kf + src);
            cpa16(sb + AV_OFF + off, g_vf + src);
        }
        cpa_commit();
    };
    load_kv(0, 0);       // group 0 (Q + KV0)
    load_kv(1, 1);       // group 1

    float o[10][4];
#pragma unroll
    for (int n = 0; n < 10; n++)
#pragma unroll
        for (int c = 0; c < 4; c++) o[n][c] = 0.f;
    float m0 = -1e30f, m1 = -1e30f, l0 = 0.f, l1 = 0.f;

    for (int kb = 0; kb < 16; kb++) {
        if (kb < 14) cpa_wait<1>(); else cpa_wait<0>();
        __syncthreads();
        if (kb + 2 < 16) load_kv(kb + 2, (kb + 2) % 3);

        const uint32_t sb = SKV0 + (kb % 3) * A_STG;

        // ---- S = Q K^T (fp16), 64 cols, k=80; log2-domain logits ----
        float s[8][4];
#pragma unroll
        for (int j = 0; j < 8; j++)
#pragma unroll
            for (int c = 0; c < 4; c++) s[j][c] = 0.f;

#pragma unroll
        for (int kt = 0; kt < 5; kt++) {
            uint32_t af[4];
            const uint32_t ad = SQ + (wid * 16 + a_row) * ARB +
                                (kt * 16 + a_kof) * 2;
            ldm_x4(af, ad);
#pragma unroll
            for (int g = 0; g < 4; g++) {
                uint32_t bf[4];
                const uint32_t bd = sb + AK_OFF + (g * 16 + b_nof) * ARB +
                                    (kt * 16 + b_kof) * 2;
                ldm_x4(bf, bd);
                mma16816h(s[2 * g + 0], af, &bf[0]);
                mma16816h(s[2 * g + 1], af, &bf[2]);
            }
        }

        // ---- online softmax (log2 domain) ----
        float mb0 = -1e30f, mb1 = -1e30f;
#pragma unroll
        for (int j = 0; j < 8; j++) {
            mb0 = fmaxf(mb0, fmaxf(s[j][0], s[j][1]));
            mb1 = fmaxf(mb1, fmaxf(s[j][2], s[j][3]));
        }
        mb0 = fmaxf(mb0, __shfl_xor_sync(0xffffffffu, mb0, 1));
        mb0 = fmaxf(mb0, __shfl_xor_sync(0xffffffffu, mb0, 2));
        mb1 = fmaxf(mb1, __shfl_xor_sync(0xffffffffu, mb1, 1));
        mb1 = fmaxf(mb1, __shfl_xor_sync(0xffffffffu, mb1, 2));

        const float mn0 = fmaxf(m0, mb0), mn1 = fmaxf(m1, mb1);
        const float alpha0 = exp2f(m0 - mn0);
        const float alpha1 = exp2f(m1 - mn1);
        m0 = mn0; m1 = mn1;

        float sum0 = 0.f, sum1 = 0.f;
#pragma unroll
        for (int j = 0; j < 8; j++) {
            s[j][0] = exp2f(s[j][0] - m0); sum0 += s[j][0];
            s[j][1] = exp2f(s[j][1] - m0); sum0 += s[j][1];
            s[j][2] = exp2f(s[j][2] - m1); sum1 += s[j][2];
            s[j][3] = exp2f(s[j][3] - m1); sum1 += s[j][3];
        }
        sum0 += __shfl_xor_sync(0xffffffffu, sum0, 1);
        sum0 += __shfl_xor_sync(0xffffffffu, sum0, 2);
        sum1 += __shfl_xor_sync(0xffffffffu, sum1, 1);
        sum1 += __shfl_xor_sync(0xffffffffu, sum1, 2);
        l0 = l0 * alpha0 + sum0;
        l1 = l1 * alpha1 + sum1;

#pragma unroll
        for (int n = 0; n < 10; n++) {
            o[n][0] *= alpha0; o[n][1] *= alpha0;
            o[n][2] *= alpha1; o[n][3] *= alpha1;
        }

        // ---- O += P V (fp16, P rounded) ----
#pragma unroll
        for (int t = 0; t < 4; t++) {
            uint32_t ph[4];
            const float* f0 = s[2 * t];
            const float* f1 = s[2 * t + 1];
            ph[0] = pack_f16(f0[0], f0[1]);
            ph[1] = pack_f16(f0[2], f0[3]);
            ph[2] = pack_f16(f1[0], f1[1]);
            ph[3] = pack_f16(f1[2], f1[3]);
#pragma unroll
            for (int v = 0; v < 5; v++) {
                uint32_t vf[4];
                const uint32_t vd = sb + AV_OFF + (t * 16 + v_row) * ARB +
                                    (v * 16 + v_cof) * 2;
                ldm_x4_t(vf, vd);
                mma16816h(o[2 * v + 0], ph, &vf[0]);
                mma16816h(o[2 * v + 1], ph, &vf[2]);
            }
        }
    }

    // ---- epilogue: o/l -> fp16 -> g_af (proj activation) ----
    const float li0 = 1.f / l0, li1 = 1.f / l1;
    const int r0 = t0 + wid * 16 + (lane >> 2);
    const size_t colb = h * HD + 2 * (lane & 3);
#pragma unroll
    for (int n = 0; n < 10; n++) {
        const size_t p0 = (size_t)r0 * HID + colb + n * 8;
        const size_t p1 = (size_t)(r0 + 8) * HID + colb + n * 8;
        *(__half2*)(g_af + p0) = __floats2half2_rn(o[n][0] * li0, o[n][1] * li0);
        *(__half2*)(g_af + p1) = __floats2half2_rn(o[n][2] * li1, o[n][3] * li1);
    }
}

// ---------------------------------------------------------------------------
extern "C" void kernel_launch(void* const* d_in, const int* in_sizes, int n_in,
                              void* d_out, int out_size)
{
    const float* x      = (const float*)d_in[0];
    const float* cosb   = (const float*)d_in[2];
    const float* sinb   = (const float*)d_in[3];
    const float* w_qkv  = (const float*)d_in[4];
    const float* b_qkv  = (const float*)d_in[5];
    const float* w_proj = (const float*)d_in[6];
    const float* b_proj = (const float*)d_in[7];
    float* out = (float*)d_out;

    __half *xf, *wq, *wp, *af;
    cudaGetSymbolAddress((void**)&xf, g_xf);
    cudaGetSymbolAddress((void**)&wq, g_wq);
    cudaGetSymbolAddress((void**)&wp, g_wp);
    cudaGetSymbolAddress((void**)&af, g_af);

    cudaFuncSetAttribute(gemm_qkv,
                         cudaFuncAttributeMaxDynamicSharedMemorySize, GEMM_SMEM);
    cudaFuncSetAttribute(gemm_proj,
                         cudaFuncAttributeMaxDynamicSharedMemorySize, GEMM_SMEM);
    cudaFuncSetAttribute(attn_mma,
                         cudaFuncAttributeMaxDynamicSharedMemorySize, ATTN_SMEM);

    const int n_x = S_LEN * HID;
    const int n_wq = 3 * HID * HID;
    const int n_wp = HID * HID;

    cvt_f16<<<(n_x / 4 + 255) / 256, 256>>>(x, xf, n_x);
    cvt_wq_perm<<<(n_wq / 4 + 255) / 256, 256>>>(w_qkv, b_qkv);
    cvt_f16<<<(n_wp / 4 + 255) / 256, 256>>>(w_proj, wp, n_wp);

    // QKV GEMM with fused bias + rope + fp16 q/k/v stores
    gemm_qkv<<<dim3(3 * HID / GBN, S_LEN / GBM), 256, GEMM_SMEM>>>(
        xf, wq, cosb, sinb);

    attn_mma<<<dim3(8, NC * NH), 256, ATTN_SMEM>>>();

    gemm_proj<<<dim3(HID / GBN, S_LEN / GBM), 256, GEMM_SMEM>>>(
        af, wp, b_proj, out);
}

// round 12
// speedup vs baseline: 8.3337x; 1.0218x over previous
#include <cuda_runtime.h>
#include <cuda_bf16.h>
#include <cuda_fp16.h>
#include <cstdint>
#include <math.h>

#define S_LEN 16384
#define HID 1280
#define NH 16
#define HD 80
#define NC 16
#define CH 1024

// ---------------------------------------------------------------------------
// Scratch (no cudaMalloc allowed)
// ---------------------------------------------------------------------------
__device__ __align__(256) __half g_xf[(size_t)S_LEN * HID];
__device__ __align__(256) __half g_wq[(size_t)3 * HID * HID];  // q/k rows PERMUTED
__device__ __align__(256) float  g_bq[3 * HID];                // permuted bias
__device__ __align__(256) __half g_wp[(size_t)HID * HID];
// rope table: (cos_i, cos_{i+40}, sin_i, sin_{i+40}) per (t, pair i)
__device__ __align__(256) float4 g_rope[(size_t)S_LEN * 40];
// attention inputs: plain fp16, q/k in rope-permuted d-layout,
// q pre-scaled by 1/sqrt(80)*log2e
__device__ __align__(256) __half g_qf[(size_t)S_LEN * HID];
__device__ __align__(256) __half g_kf[(size_t)S_LEN * HID];
__device__ __align__(256) __half g_vf[(size_t)S_LEN * HID];
// attention output = proj GEMM activation (fp16)
__device__ __align__(256) __half g_af[(size_t)S_LEN * HID];

#define QSCALE 0.16130856f   // 0.11180339887 * 1.44269504089

// ---------------------------------------------------------------------------
// helpers (sm_80-era instructions only — harness compiles for plain sm_103)
// ---------------------------------------------------------------------------
__device__ __forceinline__ uint32_t smem_u32(const void* p) {
    uint32_t a;
    asm("{ .reg .u64 t; cvta.to.shared.u64 t, %1; cvt.u32.u64 %0, t; }"
        : "=r"(a) : "l"(p));
    return a;
}

__device__ __forceinline__ void cpa16(uint32_t dst, const void* src) {
    asm volatile("cp.async.cg.shared.global [%0], [%1], 16;\n"
                 :: "r"(dst), "l"(src));
}
__device__ __forceinline__ void cpa_commit() {
    asm volatile("cp.async.commit_group;\n" ::: "memory");
}
template <int N>
__device__ __forceinline__ void cpa_wait() {
    asm volatile("cp.async.wait_group %0;\n" :: "n"(N) : "memory");
}

__device__ __forceinline__ void ldm_x4(uint32_t* r, uint32_t addr) {
    asm volatile("ldmatrix.sync.aligned.m8n8.x4.shared.b16 {%0,%1,%2,%3}, [%4];"
                 : "=r"(r[0]), "=r"(r[1]), "=r"(r[2]), "=r"(r[3])
                 : "r"(addr));
}
__device__ __forceinline__ void ldm_x4_t(uint32_t* r, uint32_t addr) {
    asm volatile(
        "ldmatrix.sync.aligned.m8n8.x4.trans.shared.b16 {%0,%1,%2,%3}, [%4];"
        : "=r"(r[0]), "=r"(r[1]), "=r"(r[2]), "=r"(r[3])
        : "r"(addr));
}

__device__ __forceinline__ void mma16816h(float* d, const uint32_t* a,
                                          const uint32_t* b) {
    asm volatile(
        "mma.sync.aligned.m16n8k16.row.col.f32.f16.f16.f32 "
        "{%0,%1,%2,%3}, {%4,%5,%6,%7}, {%8,%9}, {%0,%1,%2,%3};"
        : "+f"(d[0]), "+f"(d[1]), "+f"(d[2]), "+f"(d[3])
        : "r"(a[0]), "r"(a[1]), "r"(a[2]), "r"(a[3]), "r"(b[0]), "r"(b[1]));
}

__device__ __forceinline__ uint32_t pack_f16(float lo, float hi) {
    uint32_t d;
    asm("cvt.rn.f16x2.f32 %0, %1, %2;" : "=r"(d) : "f"(hi), "f"(lo));
    return d;
}

// ---------------------------------------------------------------------------
// Fused prep: x cvt | wq perm cvt (+bias) | wp cvt | rope table
// Segmented flat index space, 1 unit = 4 elements (or 1 rope pair entry).
// ---------------------------------------------------------------------------
#define N_X   (S_LEN * HID)            // 20971520
#define N_WQ  (3 * HID * HID)          // 4915200
#define N_WP  (HID * HID)              // 1638400
#define SEG0  (N_X / 4)                // x chunks
#define SEG1  (SEG0 + N_WQ / 4)
#define SEG2  (SEG1 + N_WP / 4)
#define SEG3  (SEG2 + S_LEN * 40)      // rope entries
// total threads = SEG3

__global__ void prep_all(const float* __restrict__ x,
                         const float* __restrict__ w_qkv,
                         const float* __restrict__ b_qkv,
                         const float* __restrict__ w_proj,
                         const float* __restrict__ cosb,
                         const float* __restrict__ sinb)
{
    int u = blockIdx.x * blockDim.x + threadIdx.x;
    if (u < SEG0) {
        const int i = u * 4;
        float4 v = *(const float4*)(x + i);
        *(__half2*)(g_xf + i)     = __floats2half2_rn(v.x, v.y);
        *(__half2*)(g_xf + i + 2) = __floats2half2_rn(v.z, v.w);
    } else if (u < SEG1) {
        const int i = (u - SEG0) * 4;
        const int p  = i / HID;
        const int kk = i % HID;
        const int which = p / HID;
        int n = p;
        if (which < 2) {
            const int pl = p % HID;
            const int h = pl / 80, j = pl % 80;
            const int d = (j & 1) ? (j >> 1) + 40 : (j >> 1);
            n = which * HID + h * 80 + d;
        }
        float4 v = *(const float4*)(w_qkv + (size_t)n * HID + kk);
        *(__half2*)(g_wq + (size_t)p * HID + kk)     = __floats2half2_rn(v.x, v.y);
        *(__half2*)(g_wq + (size_t)p * HID + kk + 2) = __floats2half2_rn(v.z, v.w);
        if (kk == 0) g_bq[p] = b_qkv[n];
    } else if (u < SEG2) {
        const int i = (u - SEG1) * 4;
        float4 v = *(const float4*)(w_proj + i);
        *(__half2*)(g_wp + i)     = __floats2half2_rn(v.x, v.y);
        *(__half2*)(g_wp + i + 2) = __floats2half2_rn(v.z, v.w);
    } else if (u < SEG3) {
        const int e = u - SEG2;
        const int t = e / 40, i = e % 40;
        float4 r;
        r.x = cosb[t * HD + i];
        r.y = cosb[t * HD + i + 40];
        r.z = sinb[t * HD + i];
        r.w = sinb[t * HD + i + 40];
        g_rope[e] = r;
    }
}

// ---------------------------------------------------------------------------
// fp16 GEMM mainloop (shared via macro).
// Block 128x128, K-chunk 32, 8 warps (4M x 2N), warp tile 32x64.
// 3-stage cp.async pipeline, single __syncthreads per K-iter.
// ---------------------------------------------------------------------------
#define GBM 128
#define GBN 128
#define GBK 32
#define ROWB 80
#define MAT_BYTES (128 * ROWB)        // 10240
#define SM_AF 0
#define SM_BF (1 * MAT_BYTES)
#define STG_BYTES (2 * MAT_BYTES)     // 20480
#define GEMM_SMEM (3 * STG_BYTES)     // 61440

#define GEMM_MAINLOOP(Af, Bf, K)                                              \
    extern __shared__ char dsm[];                                             \
    const uint32_t sbase = smem_u32(dsm);                                     \
    const int tid  = threadIdx.x;                                             \
    const int lane = tid & 31;                                                \
    const int wid  = tid >> 5;                                                \
    const int wm   = wid & 3;                                                 \
    const int wn   = wid >> 2;                                                \
    const int bm   = blockIdx.y * GBM;                                        \
    const int bn   = blockIdx.x * GBN;                                        \
    const int NK   = (K) / GBK;                                               \
    float acc[2][8][4];                                                       \
    _Pragma("unroll")                                                         \
    for (int i = 0; i < 2; i++)                                               \
        _Pragma("unroll")                                                     \
        for (int j = 0; j < 8; j++)                                           \
            _Pragma("unroll")                                                 \
            for (int c = 0; c < 4; c++) acc[i][j][c] = 0.f;                   \
    auto load_stage = [&](int k0, int s) {                                    \
        const uint32_t sb = sbase + s * STG_BYTES;                            \
        _Pragma("unroll")                                                     \
        for (int i = 0; i < 2; i++) {                                         \
            const int c   = tid + i * 256;                                    \
            const int row = c >> 2, j = c & 3;                                \
            const uint32_t off = (uint32_t)(row * ROWB + j * 16);             \
            const size_t ga = (size_t)(bm + row) * (K) + k0 + j * 8;          \
            const size_t gb = (size_t)(bn + row) * (K) + k0 + j * 8;          \
            cpa16(sb + SM_AF + off, (Af) + ga);                               \
            cpa16(sb + SM_BF + off, (Bf) + gb);                               \
        }                                                                     \
        cpa_commit();                                                         \
    };                                                                        \
    load_stage(0, 0);                                                         \
    load_stage(GBK, 1);                                                       \
    const int a_row = (lane & 15);                                            \
    const int a_kof = (lane >> 4) << 3;                                       \
    const int b_nof = (lane & 7) + ((lane >> 4) << 3);                        \
    const int b_kof = ((lane >> 3) & 1) << 3;                                 \
    for (int k = 0; k < NK; k++) {                                            \
        if (k + 1 < NK) cpa_wait<1>(); else cpa_wait<0>();                    \
        __syncthreads();                                                      \
        if (k + 2 < NK) load_stage((k + 2) * GBK, (k + 2) % 3);               \
        const uint32_t sb = sbase + (k % 3) * STG_BYTES;                      \
        _Pragma("unroll")                                                     \
        for (int kk = 0; kk < GBK; kk += 16) {                                \
            uint32_t af[2][4];                                                \
            _Pragma("unroll")                                                 \
            for (int mf = 0; mf < 2; mf++) {                                  \
                const uint32_t ad = sb + SM_AF +                              \
                    (wm * 32 + mf * 16 + a_row) * ROWB + (kk + a_kof) * 2;    \
                ldm_x4(af[mf], ad);                                           \
            }                                                                 \
            _Pragma("unroll")                                                 \
            for (int j = 0; j < 4; j++) {                                     \
                uint32_t bf[4];                                               \
                const uint32_t bd = sb + SM_BF +                              \
                    (wn * 64 + j * 16 + b_nof) * ROWB + (kk + b_kof) * 2;     \
                ldm_x4(bf, bd);                                               \
                _Pragma("unroll")                                             \
                for (int mf = 0; mf < 2; mf++) {                              \
                    mma16816h(acc[mf][2 * j + 0], af[mf], &bf[0]);            \
                    mma16816h(acc[mf][2 * j + 1], af[mf], &bf[2]);            \
                }                                                             \
            }                                                                 \
        }                                                                     \
    }

// ---------------------------------------------------------------------------
// QKV GEMM with fused bias + RoPE (table) + fp16 store into g_qf/g_kf/g_vf.
// ---------------------------------------------------------------------------
__global__ __launch_bounds__(256, 2)
void gemm_qkv(const __half* __restrict__ Af,
              const __half* __restrict__ Bf)
{
    GEMM_MAINLOOP(Af, Bf, HID)

    const int which = bn / HID;              // 0=q, 1=k, 2=v (CTA-uniform)
    __half* dst = (which == 0) ? g_qf : (which == 1) ? g_kf : g_vf;

#pragma unroll
    for (int mf = 0; mf < 2; mf++) {
        const int r0 = bm + wm * 32 + mf * 16 + (lane >> 2);
#pragma unroll
        for (int nf = 0; nf < 8; nf++) {
            const int c0 = bn + wn * 64 + nf * 8 + (lane & 3) * 2;  // even
            const float b0 = g_bq[c0], b1 = g_bq[c0 + 1];
            const int local = c0 - which * HID;
            float x00 = acc[mf][nf][0] + b0, x01 = acc[mf][nf][1] + b1;
            float x10 = acc[mf][nf][2] + b0, x11 = acc[mf][nf][3] + b1;
            if (which == 2) {
                *(__half2*)(dst + (size_t)r0 * HID + local) =
                    __floats2half2_rn(x00, x01);
                *(__half2*)(dst + (size_t)(r0 + 8) * HID + local) =
                    __floats2half2_rn(x10, x11);
            } else {
                const int i = (local % 80) >> 1;     // rope pair index
                const float4 ra = g_rope[(size_t)r0 * 40 + i];
                const float4 rb = g_rope[(size_t)(r0 + 8) * 40 + i];
                float o00 = x00 * ra.x - x01 * ra.z;
                float o01 = x01 * ra.y + x00 * ra.w;
                float o10 = x10 * rb.x - x11 * rb.z;
                float o11 = x11 * rb.y + x10 * rb.w;
                if (which == 0) {
                    o00 *= QSCALE; o01 *= QSCALE;
                    o10 *= QSCALE; o11 *= QSCALE;
                }
                *(__half2*)(dst + (size_t)r0 * HID + local) =
                    __floats2half2_rn(o00, o01);
                *(__half2*)(dst + (size_t)(r0 + 8) * HID + local) =
                    __floats2half2_rn(o10, o11);
            }
        }
    }
}

// ---------------------------------------------------------------------------
// Proj GEMM: fp32 output + bias (final result)
// ---------------------------------------------------------------------------
__global__ __launch_bounds__(256, 2)
void gemm_proj(const __half* __restrict__ Af,
               const __half* __restrict__ Bf,
               const float* __restrict__ bias, float* __restrict__ C)
{
    GEMM_MAINLOOP(Af, Bf, HID)

    const int N = HID;
#pragma unroll
    for (int mf = 0; mf < 2; mf++) {
        const int r0 = bm + wm * 32 + mf * 16 + (lane >> 2);
#pragma unroll
        for (int nf = 0; nf < 8; nf++) {
            const int c0 = bn + wn * 64 + nf * 8 + (lane & 3) * 2;
            const float b0 = bias[c0], b1 = bias[c0 + 1];
            float2 v0 = {acc[mf][nf][0] + b0, acc[mf][nf][1] + b1};
            float2 v1 = {acc[mf][nf][2] + b0, acc[mf][nf][3] + b1};
            *(float2*)(C + (size_t)r0 * N + c0) = v0;
            *(float2*)(C + (size_t)(r0 + 8) * N + c0) = v1;
        }
    }
}

// ---------------------------------------------------------------------------
// HMMA flash attention, plain fp16 operands (fp32 accumulate).
// CTA = (chunk, head, 128 q rows); 8 warps x 16 rows.
// 3-stage cp.async KV pipeline, single sync per iter, 2 CTAs/SM.
// ---------------------------------------------------------------------------
#define ARB 176
#define AQ_BYTES (128 * ARB)
#define AKV_BYTES (64 * ARB)
#define A_STG (2 * AKV_BYTES)
#define ATTN_SMEM (AQ_BYTES + 3 * A_STG)   // 90112
#define AK_OFF 0
#define AV_OFF AKV_BYTES

__global__ __launch_bounds__(256, 2)
void attn_mma()
{
    extern __shared__ char dsm[];
    const uint32_t sbase = smem_u32(dsm);
    const uint32_t SQ = sbase;
    const uint32_t SKV0 = sbase + AQ_BYTES;

    const int tid  = threadIdx.x;
    const int lane = tid & 31;
    const int wid  = tid >> 5;
    const int nc = blockIdx.y >> 4;
    const int h  = blockIdx.y & 15;
    const int t0 = nc * CH + blockIdx.x * 128;

    const int a_row = (lane & 15);
    const int a_kof = (lane >> 4) << 3;
    const int b_nof = (lane & 7) + ((lane >> 4) << 3);
    const int b_kof = ((lane >> 3) & 1) << 3;
    const int v_row = (lane & 15);
    const int v_cof = (lane >> 4) << 3;

    for (int i = tid; i < 1280; i += 256) {
        const int r = i / 10, c = i % 10;
        const uint32_t off = (uint32_t)(r * ARB + c * 16);
        const size_t src = (size_t)(t0 + r) * HID + h * HD + c * 8;
        cpa16(SQ + off, g_qf + src);
    }
    auto load_kv = [&](int kb, int s) {
        const uint32_t sb = SKV0 + s * A_STG;
        for (int i = tid; i < 640; i += 256) {
            const int r = i / 10, c = i % 10;
            const uint32_t off = (uint32_t)(r * ARB + c * 16);
            const size_t src = (size_t)(nc * CH + kb * 64 + r) * HID + h * HD + c * 8;
            cpa16(sb + AK_OFF + off, g_kf + src);
            cpa16(sb + AV_OFF + off, g_vf + src);
        }
        cpa_commit();
    };
    load_kv(0, 0);
    load_kv(1, 1);

    float o[10][4];
#pragma unroll
    for (int n = 0; n < 10; n++)
#pragma unroll
        for (int c = 0; c < 4; c++) o[n][c] = 0.f;
    float m0 = -1e30f, m1 = -1e30f, l0 = 0.f, l1 = 0.f;

    for (int kb = 0; kb < 16; kb++) {
        if (kb < 14) cpa_wait<1>(); else cpa_wait<0>();
        __syncthreads();
        if (kb + 2 < 16) load_kv(kb + 2, (kb + 2) % 3);

        const uint32_t sb = SKV0 + (kb % 3) * A_STG;

        float s[8][4];
#pragma unroll
        for (int j = 0; j < 8; j++)
#pragma unroll
            for (int c = 0; c < 4; c++) s[j][c] = 0.f;

#pragma unroll
        for (int kt = 0; kt < 5; kt++) {
            uint32_t af[4];
            const uint32_t ad = SQ + (wid * 16 + a_row) * ARB +
                                (kt * 16 + a_kof) * 2;
            ldm_x4(af, ad);
#pragma unroll
            for (int g = 0; g < 4; g++) {
                uint32_t bf[4];
                const uint32_t bd = sb + AK_OFF + (g * 16 + b_nof) * ARB +
                                    (kt * 16 + b_kof) * 2;
                ldm_x4(bf, bd);
                mma16816h(s[2 * g + 0], af, &bf[0]);
                mma16816h(s[2 * g + 1], af, &bf[2]);
            }
        }

        float mb0 = -1e30f, mb1 = -1e30f;
#pragma unroll
        for (int j = 0; j < 8; j++) {
            mb0 = fmaxf(mb0, fmaxf(s[j][0], s[j][1]));
            mb1 = fmaxf(mb1, fmaxf(s[j][2], s[j][3]));
        }
        mb0 = fmaxf(mb0, __shfl_xor_sync(0xffffffffu, mb0, 1));
        mb0 = fmaxf(mb0, __shfl_xor_sync(0xffffffffu, mb0, 2));
        mb1 = fmaxf(mb1, __shfl_xor_sync(0xffffffffu, mb1, 1));
        mb1 = fmaxf(mb1, __shfl_xor_sync(0xffffffffu, mb1, 2));

        const float mn0 = fmaxf(m0, mb0), mn1 = fmaxf(m1, mb1);
        const float alpha0 = exp2f(m0 - mn0);
        const float alpha1 = exp2f(m1 - mn1);
        m0 = mn0; m1 = mn1;

        float sum0 = 0.f, sum1 = 0.f;
#pragma unroll
        for (int j = 0; j < 8; j++) {
            s[j][0] = exp2f(s[j][0] - m0); sum0 += s[j][0];
            s[j][1] = exp2f(s[j][1] - m0); sum0 += s[j][1];
            s[j][2] = exp2f(s[j][2] - m1); sum1 += s[j][2];
            s[j][3] = exp2f(s[j][3] - m1); sum1 += s[j][3];
        }
        sum0 += __shfl_xor_sync(0xffffffffu, sum0, 1);
        sum0 += __shfl_xor_sync(0xffffffffu, sum0, 2);
        sum1 += __shfl_xor_sync(0xffffffffu, sum1, 1);
        sum1 += __shfl_xor_sync(0xffffffffu, sum1, 2);
        l0 = l0 * alpha0 + sum0;
        l1 = l1 * alpha1 + sum1;

#pragma unroll
        for (int n = 0; n < 10; n++) {
            o[n][0] *= alpha0; o[n][1] *= alpha0;
            o[n][2] *= alpha1; o[n][3] *= alpha1;
        }

#pragma unroll
        for (int t = 0; t < 4; t++) {
            uint32_t ph[4];
            const float* f0 = s[2 * t];
            const float* f1 = s[2 * t + 1];
            ph[0] = pack_f16(f0[0], f0[1]);
            ph[1] = pack_f16(f0[2], f0[3]);
            ph[2] = pack_f16(f1[0], f1[1]);
            ph[3] = pack_f16(f1[2], f1[3]);
#pragma unroll
            for (int v = 0; v < 5; v++) {
                uint32_t vf[4];
                const uint32_t vd = sb + AV_OFF + (t * 16 + v_row) * ARB +
                                    (v * 16 + v_cof) * 2;
                ldm_x4_t(vf, vd);
                mma16816h(o[2 * v + 0], ph, &vf[0]);
                mma16816h(o[2 * v + 1], ph, &vf[2]);
            }
        }
    }

    const float li0 = 1.f / l0, li1 = 1.f / l1;
    const int r0 = t0 + wid * 16 + (lane >> 2);
    const size_t colb = h * HD + 2 * (lane & 3);
#pragma unroll
    for (int n = 0; n < 10; n++) {
        const size_t p0 = (size_t)r0 * HID + colb + n * 8;
        const size_t p1 = (size_t)(r0 + 8) * HID + colb + n * 8;
        *(__half2*)(g_af + p0) = __floats2half2_rn(o[n][0] * li0, o[n][1] * li0);
        *(__half2*)(g_af + p1) = __floats2half2_rn(o[n][2] * li1, o[n][3] * li1);
    }
}

// ---------------------------------------------------------------------------
extern "C" void kernel_launch(void* const* d_in, const int* in_sizes, int n_in,
                              void* d_out, int out_size)
{
    const float* x      = (const float*)d_in[0];
    const float* cosb   = (const float*)d_in[2];
    const float* sinb   = (const float*)d_in[3];
    const float* w_qkv  = (const float*)d_in[4];
    const float* b_qkv  = (const float*)d_in[5];
    const float* w_proj = (const float*)d_in[6];
    const float* b_proj = (const float*)d_in[7];
    float* out = (float*)d_out;

    __half *xf, *wq, *wp, *af;
    cudaGetSymbolAddress((void**)&xf, g_xf);
    cudaGetSymbolAddress((void**)&wq, g_wq);
    cudaGetSymbolAddress((void**)&wp, g_wp);
    cudaGetSymbolAddress((void**)&af, g_af);

    cudaFuncSetAttribute(gemm_qkv,
                         cudaFuncAttributeMaxDynamicSharedMemorySize, GEMM_SMEM);
    cudaFuncSetAttribute(gemm_proj,
                         cudaFuncAttributeMaxDynamicSharedMemorySize, GEMM_SMEM);
    cudaFuncSetAttribute(attn_mma,
                         cudaFuncAttributeMaxDynamicSharedMemorySize, ATTN_SMEM);

    // fused prep: x/wq/wp conversion + rope table (one launch)
    prep_all<<<(SEG3 + 255) / 256, 256>>>(x, w_qkv, b_qkv, w_proj, cosb, sinb);

    gemm_qkv<<<dim3(3 * HID / GBN, S_LEN / GBM), 256, GEMM_SMEM>>>(xf, wq);

    attn_mma<<<dim3(8, NC * NH), 256, ATTN_SMEM>>>();

    gemm_proj<<<dim3(HID / GBN, S_LEN / GBM), 256, GEMM_SMEM>>>(
        af, wp, b_proj, out);
}